// round 1
// baseline (speedup 1.0000x reference)
#include <cuda_runtime.h>
#include <math.h>

#define BATCH 16384
#define DIMS  64
#define LAYERS 63
#define HID   64
#define OD    23
#define BTAIL 3.0f
#define XSTR  68   // smem row stride in floats (padded, float4-aligned)

// deterministic per-(dim, batch) logdet partials
__device__ float g_ld[DIMS * BATCH];

static const int SMEM_BYTES = (128 * XSTR + 64 * XSTR) * 4;  // 52224

// ---------------------------------------------------------------------------
// math helpers
// ---------------------------------------------------------------------------
__device__ __forceinline__ float softplus_(float x) {
    return (x > 15.f) ? x : log1pf(__expf(x));
}

__device__ __forceinline__ float tanh_(float v) {
    v = fminf(fmaxf(v, -15.f), 15.f);
    float e = __expf(2.f * v);
    return __fdividef(e - 1.f, e + 1.f);
}

__device__ __forceinline__ void softmax8(const float* in, float* out, float scale) {
    float m = in[0];
#pragma unroll
    for (int i = 1; i < 8; i++) m = fmaxf(m, in[i]);
    float e[8], s = 0.f;
#pragma unroll
    for (int i = 0; i < 8; i++) { e[i] = __expf(in[i] - m); s += e[i]; }
    float inv = scale / s;
#pragma unroll
    for (int i = 0; i < 8; i++) out[i] = e[i] * inv;
}

// rational-quadratic spline for one scalar, params p[0..22]
__device__ void rqs23(float xval, const float* __restrict__ p, float* zo, float* ldo) {
    float W[8], H[8], wi[8], he[8];
    softmax8(p,     W, 2.f * BTAIL);   // W = 2B * softmax(p[:8])
    softmax8(p + 8, H, 2.f * BTAIL);
    softmax8(W, wi, 1.f);              // second softmax (per reference)
    softmax8(H, he, 1.f);

    float cw[9], ch[9];
    cw[0] = -BTAIL; ch[0] = -BTAIL;
    float aw = 0.f, ah = 0.f;
#pragma unroll
    for (int i = 0; i < 8; i++) {
        float wv = 1e-3f + (1.f - 8e-3f) * wi[i];
        float hv = 1e-3f + (1.f - 8e-3f) * he[i];
        aw += wv; ah += hv;
        cw[i + 1] = 2.f * BTAIL * aw - BTAIL;
        ch[i + 1] = 2.f * BTAIL * ah - BTAIL;
    }
    cw[8] = BTAIL; ch[8] = BTAIL;

    float der[9];
    const float UDC = logf(expf(1.0f - 1e-3f) - 1.0f);  // pad constant
    float edge = 1e-3f + softplus_(UDC);
    der[0] = edge; der[8] = edge;
#pragma unroll
    for (int i = 0; i < 7; i++) der[i + 1] = 1e-3f + softplus_(softplus_(p[16 + i]));

    bool inside = (xval >= -BTAIL) && (xval <= BTAIL);
    float x = fminf(fmaxf(xval, -BTAIL), BTAIL);

    // bin = sum_{i=1..7} (x >= cw[i]); edge 0 always true, edge 8(+eps) always false
    int bin = 0;
#pragma unroll
    for (int i = 1; i < 8; i++) bin += (x >= cw[i]) ? 1 : 0;

    float icw = 0.f, iw = 1.f, ich = 0.f, ih = 1.f, dk = 1.f, dk1 = 1.f;
#pragma unroll
    for (int i = 0; i < 8; i++) {
        if (bin == i) {
            icw = cw[i];  iw = cw[i + 1] - cw[i];
            ich = ch[i];  ih = ch[i + 1] - ch[i];
            dk = der[i];  dk1 = der[i + 1];
        }
    }

    float delta = ih / iw;
    float th  = (x - icw) / iw;
    float t1  = th * (1.f - th);
    float numer = ih * (delta * th * th + dk * t1);
    float denom = delta + (dk + dk1 - 2.f * delta) * t1;
    float out = ich + numer / denom;
    float om = 1.f - th;
    float dnum = delta * delta * (dk1 * th * th + 2.f * delta * t1 + dk * om * om);
    float ld = logf(dnum) - 2.f * logf(denom);

    *zo  = inside ? out : xval;
    *ldo = inside ? ld  : 0.f;
}

// ---------------------------------------------------------------------------
// GEMM tile: out[r][c] = sum_k A[r][k] * Wt[c][k]; 128 rows x 64 cols,
// thread (lane, warp) owns rows {lane, lane+32, lane+64, lane+96}, cols warp*8..+7
// ---------------------------------------------------------------------------
__device__ __forceinline__ void gemm_tile(const float* __restrict__ A,
                                          const float* __restrict__ Wt,
                                          float acc[4][8], int lane, int warp) {
#pragma unroll
    for (int i = 0; i < 4; i++)
#pragma unroll
        for (int j = 0; j < 8; j++) acc[i][j] = 0.f;

#pragma unroll 2
    for (int k = 0; k < 64; k += 4) {
        float4 a[4];
#pragma unroll
        for (int i = 0; i < 4; i++)
            a[i] = *reinterpret_cast<const float4*>(&A[(lane + 32 * i) * XSTR + k]);
        float4 w[8];
#pragma unroll
        for (int j = 0; j < 8; j++)
            w[j] = *reinterpret_cast<const float4*>(&Wt[(warp * 8 + j) * XSTR + k]);
#pragma unroll
        for (int i = 0; i < 4; i++)
#pragma unroll
            for (int j = 0; j < 8; j++) {
                acc[i][j] = fmaf(a[i].x, w[j].x, acc[i][j]);
                acc[i][j] = fmaf(a[i].y, w[j].y, acc[i][j]);
                acc[i][j] = fmaf(a[i].z, w[j].z, acc[i][j]);
                acc[i][j] = fmaf(a[i].w, w[j].w, acc[i][j]);
            }
    }
}

__device__ __forceinline__ void store_act(float acc[4][8], const float* __restrict__ bias,
                                          float* __restrict__ dst, int lane, int warp) {
    float bb[8];
#pragma unroll
    for (int j = 0; j < 8; j++) bb[j] = bias[warp * 8 + j];
#pragma unroll
    for (int i = 0; i < 4; i++) {
        int r = lane + 32 * i;
        float t[8];
#pragma unroll
        for (int j = 0; j < 8; j++) t[j] = tanh_(acc[i][j] + bb[j]);
        *reinterpret_cast<float4*>(&dst[r * XSTR + warp * 8])     = make_float4(t[0], t[1], t[2], t[3]);
        *reinterpret_cast<float4*>(&dst[r * XSTR + warp * 8 + 4]) = make_float4(t[4], t[5], t[6], t[7]);
    }
}

// ---------------------------------------------------------------------------
// main fused kernel: one (layer l, 128-row tile) per block
// ---------------------------------------------------------------------------
__global__ void __launch_bounds__(256) nsf_main(
    const float* __restrict__ x,
    const float* __restrict__ W1, const float* __restrict__ b1,
    const float* __restrict__ W2, const float* __restrict__ b2,
    const float* __restrict__ W3, const float* __restrict__ b3,
    float* __restrict__ z)
{
    extern __shared__ float sm[];
    float* xs = sm;                   // [128][XSTR]  (x tile, later h1, later h2)
    float* ws = sm + 128 * XSTR;      // [64][XSTR]   (current weight matrix)

    const int l   = blockIdx.y;
    const int m0  = blockIdx.x * 128;
    const int tid = threadIdx.x;
    const int lane = tid & 31, warp = tid >> 5;

    // load masked x tile (keep cols 0..l)
    const float4* xg = reinterpret_cast<const float4*>(x + (size_t)m0 * DIMS);
    for (int idx = tid; idx < 128 * 16; idx += 256) {
        int r = idx >> 4, c4 = idx & 15;
        float4 v = xg[idx];
        int c = c4 << 2;
        if (c + 0 > l) v.x = 0.f;
        if (c + 1 > l) v.y = 0.f;
        if (c + 2 > l) v.z = 0.f;
        if (c + 3 > l) v.w = 0.f;
        *reinterpret_cast<float4*>(&xs[r * XSTR + c]) = v;
    }
    // load W1[l]
    {
        const float4* wg = reinterpret_cast<const float4*>(W1 + (size_t)l * HID * DIMS);
        for (int idx = tid; idx < 64 * 16; idx += 256) {
            int r = idx >> 4, c4 = idx & 15;
            *reinterpret_cast<float4*>(&ws[r * XSTR + (c4 << 2)]) = wg[idx];
        }
    }
    __syncthreads();

    float acc[4][8];

    // layer 1
    gemm_tile(xs, ws, acc, lane, warp);
    __syncthreads();
    store_act(acc, b1 + l * HID, xs, lane, warp);
    {
        const float4* wg = reinterpret_cast<const float4*>(W2 + (size_t)l * HID * HID);
        for (int idx = tid; idx < 64 * 16; idx += 256) {
            int r = idx >> 4, c4 = idx & 15;
            *reinterpret_cast<float4*>(&ws[r * XSTR + (c4 << 2)]) = wg[idx];
        }
    }
    __syncthreads();

    // layer 2
    gemm_tile(xs, ws, acc, lane, warp);
    __syncthreads();
    store_act(acc, b2 + l * HID, xs, lane, warp);
    {
        const float4* wg = reinterpret_cast<const float4*>(W3 + (size_t)l * OD * HID);
        for (int idx = tid; idx < OD * 16; idx += 256) {
            int r = idx >> 4, c4 = idx & 15;
            *reinterpret_cast<float4*>(&ws[r * XSTR + (c4 << 2)]) = wg[idx];
        }
    }
    __syncthreads();

    // layer 3 (only 23 output cols -> warps 0..2)
    if (warp < 3) gemm_tile(xs, ws, acc, lane, warp);
    __syncthreads();   // all reads of xs done before ps overwrite

    // params into smem (stride 24), reusing xs region
    if (warp < 3) {
        const float* b3l = b3 + (size_t)l * OD;
#pragma unroll
        for (int i = 0; i < 4; i++) {
            int r = lane + 32 * i;
#pragma unroll
            for (int j = 0; j < 8; j++) {
                int c = warp * 8 + j;
                if (c < OD) sm[r * 24 + c] = acc[i][j] + b3l[c];
            }
        }
    }
    __syncthreads();

    // spline for dimension d = l+1, one thread per row
    if (tid < 128) {
        int b = m0 + tid;
        float xv = x[(size_t)b * DIMS + (l + 1)];
        float zo, ldo;
        rqs23(xv, &sm[tid * 24], &zo, &ldo);
        z[(size_t)b * DIMS + (l + 1)] = zo;
        g_ld[(size_t)(l + 1) * BATCH + b] = ldo;
    }
}

// dimension 0: spline with init_param for every batch row
__global__ void __launch_bounds__(256) nsf_dim0(const float* __restrict__ x,
                                                const float* __restrict__ ip,
                                                float* __restrict__ z)
{
    int b = blockIdx.x * blockDim.x + threadIdx.x;
    float p[23];
#pragma unroll
    for (int i = 0; i < 23; i++) p[i] = ip[i];
    float zo, ldo;
    rqs23(x[(size_t)b * DIMS], p, &zo, &ldo);
    z[(size_t)b * DIMS] = zo;
    g_ld[b] = ldo;
}

// sum logdet partials over the 64 dims
__global__ void __launch_bounds__(256) nsf_reduce(float* __restrict__ ldo)
{
    int b = blockIdx.x * blockDim.x + threadIdx.x;
    float s = 0.f;
#pragma unroll
    for (int d = 0; d < DIMS; d++) s += g_ld[(size_t)d * BATCH + b];
    ldo[b] = s;
}

// ---------------------------------------------------------------------------
extern "C" void kernel_launch(void* const* d_in, const int* in_sizes, int n_in,
                              void* d_out, int out_size)
{
    const float* x  = (const float*)d_in[0];
    const float* ip = (const float*)d_in[1];
    const float* W1 = (const float*)d_in[2];
    const float* b1 = (const float*)d_in[3];
    const float* W2 = (const float*)d_in[4];
    const float* b2 = (const float*)d_in[5];
    const float* W3 = (const float*)d_in[6];
    const float* b3 = (const float*)d_in[7];

    float* z   = (float*)d_out;                    // [BATCH, DIMS]
    float* ldo = z + (size_t)BATCH * DIMS;         // [BATCH]

    cudaFuncSetAttribute(nsf_main, cudaFuncAttributeMaxDynamicSharedMemorySize, SMEM_BYTES);

    nsf_dim0<<<BATCH / 256, 256>>>(x, ip, z);
    nsf_main<<<dim3(128, LAYERS), 256, SMEM_BYTES>>>(x, W1, b1, W2, b2, W3, b3, z);
    nsf_reduce<<<BATCH / 256, 256>>>(ldo);
}

// round 6
// speedup vs baseline: 1.7947x; 1.7947x over previous
#include <cuda_runtime.h>
#include <cuda_bf16.h>
#include <math.h>
#include <stdint.h>

#define BATCH 16384
#define DIMS  64
#define LAYERS 63
#define HID   64
#define OD    23
#define BTAIL 3.0f
#define XSTR  68            // xs row stride in floats

// per-(dim,batch) logdet partials (deterministic reduce)
__device__ float g_ld[DIMS * BATCH];
// pre-split bf16 weight planes per layer:
// [W1hi 8K][W1lo 8K][W2hi 8K][W2lo 8K][W3hi 4K][W3lo 4K] = 40960 B
__device__ __align__(16) unsigned char g_w[(size_t)LAYERS * 40960];

// dynamic smem layout (bytes)
#define XS_OFF   0            // 128 x 68 floats = 34816 (reused as psm [128][24])
#define WB0_OFF  34816        // hi plane +0, lo plane +9216 (rows padded to 144B)
#define WB1_OFF  53248
#define BIAS_OFF 71680        // b1[64] b2[64] b3[23]
#define SMEM_BYTES 72320
#define WROWB 144             // 72 bf16 per weight row

// ---------------------------------------------------------------------------
// mma.sync m16n8k16 bf16 (baseline PTX, works on plain sm_103)
// ---------------------------------------------------------------------------
__device__ __forceinline__ void mma16816(float* c, const uint32_t* a, const uint32_t* b) {
    asm volatile(
        "mma.sync.aligned.m16n8k16.row.col.f32.bf16.bf16.f32 "
        "{%0,%1,%2,%3}, {%4,%5,%6,%7}, {%8,%9}, {%0,%1,%2,%3};"
        : "+f"(c[0]), "+f"(c[1]), "+f"(c[2]), "+f"(c[3])
        : "r"(a[0]), "r"(a[1]), "r"(a[2]), "r"(a[3]), "r"(b[0]), "r"(b[1]));
}

// split pair of floats into bf16 hi plane + bf16 lo (residual) plane, packed
__device__ __forceinline__ uint2 split2(float f0, float f1) {
    __nv_bfloat162 h = __floats2bfloat162_rn(f0, f1);
    float r0 = f0 - __bfloat162float(h.x);
    float r1 = f1 - __bfloat162float(h.y);
    __nv_bfloat162 l = __floats2bfloat162_rn(r0, r1);
    uint2 o;
    o.x = *(uint32_t*)&h;
    o.y = *(uint32_t*)&l;
    return o;
}

// ---------------------------------------------------------------------------
// math helpers (identical numerics to round-1 passing kernel)
// ---------------------------------------------------------------------------
__device__ __forceinline__ float softplus_(float x) {
    return (x > 15.f) ? x : log1pf(__expf(x));
}
__device__ __forceinline__ float tanh_(float v) {
    v = fminf(fmaxf(v, -15.f), 15.f);
    float e = __expf(2.f * v);
    return __fdividef(e - 1.f, e + 1.f);
}
__device__ __forceinline__ void softmax8(const float* in, float* out, float scale) {
    float m = in[0];
#pragma unroll
    for (int i = 1; i < 8; i++) m = fmaxf(m, in[i]);
    float e[8], s = 0.f;
#pragma unroll
    for (int i = 0; i < 8; i++) { e[i] = __expf(in[i] - m); s += e[i]; }
    float inv = scale / s;
#pragma unroll
    for (int i = 0; i < 8; i++) out[i] = e[i] * inv;
}

__device__ __forceinline__ void rqs23(float xval, const float* __restrict__ p,
                                      float* zo, float* ldo) {
    float W[8], H[8], wi[8], he[8];
    softmax8(p,     W, 2.f * BTAIL);
    softmax8(p + 8, H, 2.f * BTAIL);
    softmax8(W, wi, 1.f);
    softmax8(H, he, 1.f);

    float cw[9], ch[9];
    cw[0] = -BTAIL; ch[0] = -BTAIL;
    float aw = 0.f, ah = 0.f;
#pragma unroll
    for (int i = 0; i < 8; i++) {
        float wv = 1e-3f + (1.f - 8e-3f) * wi[i];
        float hv = 1e-3f + (1.f - 8e-3f) * he[i];
        aw += wv; ah += hv;
        cw[i + 1] = 2.f * BTAIL * aw - BTAIL;
        ch[i + 1] = 2.f * BTAIL * ah - BTAIL;
    }
    cw[8] = BTAIL; ch[8] = BTAIL;

    float der[9];
    const float UDC = logf(expf(1.0f - 1e-3f) - 1.0f);
    float edge = 1e-3f + softplus_(UDC);
    der[0] = edge; der[8] = edge;
#pragma unroll
    for (int i = 0; i < 7; i++) der[i + 1] = 1e-3f + softplus_(softplus_(p[16 + i]));

    bool inside = (xval >= -BTAIL) && (xval <= BTAIL);
    float x = fminf(fmaxf(xval, -BTAIL), BTAIL);

    int bin = 0;
#pragma unroll
    for (int i = 1; i < 8; i++) bin += (x >= cw[i]) ? 1 : 0;

    float icw = 0.f, iw = 1.f, ich = 0.f, ih = 1.f, dk = 1.f, dk1 = 1.f;
#pragma unroll
    for (int i = 0; i < 8; i++) {
        if (bin == i) {
            icw = cw[i];  iw = cw[i + 1] - cw[i];
            ich = ch[i];  ih = ch[i + 1] - ch[i];
            dk = der[i];  dk1 = der[i + 1];
        }
    }

    float delta = ih / iw;
    float th  = (x - icw) / iw;
    float t1  = th * (1.f - th);
    float numer = ih * (delta * th * th + dk * t1);
    float denom = delta + (dk + dk1 - 2.f * delta) * t1;
    float out = ich + numer / denom;
    float om = 1.f - th;
    float dnum = delta * delta * (dk1 * th * th + 2.f * delta * t1 + dk * om * om);
    float ld = logf(dnum) - 2.f * logf(denom);

    *zo  = inside ? out : xval;
    *ldo = inside ? ld  : 0.f;
}

// ---------------------------------------------------------------------------
// prep: split fp32 weights into bf16 hi/lo planes ([n][k] row-major, no pad)
// ---------------------------------------------------------------------------
__global__ void __launch_bounds__(256) nsf_prep(const float* __restrict__ W1,
                                                const float* __restrict__ W2,
                                                const float* __restrict__ W3) {
    int l = blockIdx.x, tid = threadIdx.x;
    unsigned char* dst = g_w + (size_t)l * 40960;
    for (int idx = tid; idx < 4096; idx += 256) {
        float v = W1[(size_t)l * 4096 + idx];
        __nv_bfloat16 h = __float2bfloat16(v);
        __nv_bfloat16 lo = __float2bfloat16(v - __bfloat162float(h));
        ((__nv_bfloat16*)dst)[idx] = h;
        ((__nv_bfloat16*)(dst + 8192))[idx] = lo;
    }
    for (int idx = tid; idx < 4096; idx += 256) {
        float v = W2[(size_t)l * 4096 + idx];
        __nv_bfloat16 h = __float2bfloat16(v);
        __nv_bfloat16 lo = __float2bfloat16(v - __bfloat162float(h));
        ((__nv_bfloat16*)(dst + 16384))[idx] = h;
        ((__nv_bfloat16*)(dst + 24576))[idx] = lo;
    }
    for (int idx = tid; idx < 2048; idx += 256) {
        int n = idx >> 6, k = idx & 63;
        float v = (n < OD) ? W3[(size_t)l * OD * 64 + n * 64 + k] : 0.f;
        __nv_bfloat16 h = __float2bfloat16(v);
        __nv_bfloat16 lo = __float2bfloat16(v - __bfloat162float(h));
        ((__nv_bfloat16*)(dst + 32768))[idx] = h;
        ((__nv_bfloat16*)(dst + 36864))[idx] = lo;
    }
}

// copy one [rows][64] bf16 plane to smem with rows padded to 144 B
__device__ __forceinline__ void copy_plane(unsigned char* dst, const unsigned char* src,
                                           int rows, int tid) {
    int n = rows * 8;
    for (int i = tid; i < n; i += 128) {
        int r = i >> 3, q = i & 7;
        ((uint4*)(dst + r * WROWB))[q] = ((const uint4*)src)[i];
    }
}

// ---------------------------------------------------------------------------
// main fused kernel: one (layer l, 128-row tile) per CTA, 128 threads (4 warps)
// warp w owns batch rows [32w, 32w+32); activations stay in registers.
// ---------------------------------------------------------------------------
__global__ void __launch_bounds__(128, 3) nsf_main(
    const float* __restrict__ x,
    const float* __restrict__ b1, const float* __restrict__ b2,
    const float* __restrict__ b3, float* __restrict__ z) {
    extern __shared__ unsigned char smp[];
    float* xs = (float*)(smp + XS_OFF);
    float* bsm = (float*)(smp + BIAS_OFF);

    const int tid = threadIdx.x;
    const int warp = tid >> 5, lane = tid & 31;
    const int g = lane >> 2, tg = lane & 3;
    const int l = blockIdx.y, m0 = blockIdx.x * 128;
    const int mbase = warp * 32;

    // ---- stage: masked x tile (floats), W1 planes, biases ----
    const float4* xg = (const float4*)(x + (size_t)m0 * DIMS);
    for (int idx = tid; idx < 128 * 16; idx += 128) {
        int r = idx >> 4, c4 = idx & 15;
        float4 v = xg[idx];
        int c = c4 << 2;
        if (c + 0 > l) v.x = 0.f;
        if (c + 1 > l) v.y = 0.f;
        if (c + 2 > l) v.z = 0.f;
        if (c + 3 > l) v.w = 0.f;
        *(float4*)(&xs[r * XSTR + c]) = v;
    }
    const unsigned char* wsrc = g_w + (size_t)l * 40960;
    copy_plane(smp + WB0_OFF,        wsrc,        64, tid);   // W1 hi
    copy_plane(smp + WB0_OFF + 9216, wsrc + 8192, 64, tid);   // W1 lo
    if (tid < 64) { bsm[tid] = b1[l * 64 + tid]; bsm[64 + tid] = b2[l * 64 + tid]; }
    if (tid < OD)  bsm[128 + tid] = b3[l * OD + tid];
    float xv = x[(size_t)(m0 + tid) * DIMS + (l + 1)];
    __syncthreads();

    // ---- build layer-1 A fragments from xs (hi/lo split) ----
    uint32_t Ahi[2][4][4], Alo[2][4][4];
#pragma unroll
    for (int i = 0; i < 2; i++) {
#pragma unroll
        for (int s = 0; s < 4; s++) {
            int r0 = mbase + 16 * i + g;
            int c0 = 16 * s + 2 * tg;
            uint2 p;
            p = split2(xs[r0 * XSTR + c0],           xs[r0 * XSTR + c0 + 1]);
            Ahi[i][s][0] = p.x; Alo[i][s][0] = p.y;
            p = split2(xs[(r0 + 8) * XSTR + c0],     xs[(r0 + 8) * XSTR + c0 + 1]);
            Ahi[i][s][1] = p.x; Alo[i][s][1] = p.y;
            p = split2(xs[r0 * XSTR + c0 + 8],       xs[r0 * XSTR + c0 + 9]);
            Ahi[i][s][2] = p.x; Alo[i][s][2] = p.y;
            p = split2(xs[(r0 + 8) * XSTR + c0 + 8], xs[(r0 + 8) * XSTR + c0 + 9]);
            Ahi[i][s][3] = p.x; Alo[i][s][3] = p.y;
        }
    }

    float acc[2][8][4];

    // ================= layer 1 =================
#pragma unroll
    for (int i = 0; i < 2; i++)
#pragma unroll
        for (int n = 0; n < 8; n++)
#pragma unroll
            for (int q = 0; q < 4; q++) acc[i][n][q] = 0.f;
    {
        const unsigned char* whi = smp + WB0_OFF;
        const unsigned char* wlo = whi + 9216;
#pragma unroll
        for (int n = 0; n < 8; n++)
#pragma unroll
            for (int s = 0; s < 4; s++) {
                int off = (8 * n + g) * WROWB + (16 * s + 2 * tg) * 2;
                uint32_t bh[2] = { *(const uint32_t*)(whi + off), *(const uint32_t*)(whi + off + 16) };
                uint32_t bl[2] = { *(const uint32_t*)(wlo + off), *(const uint32_t*)(wlo + off + 16) };
                mma16816(acc[0][n], Ahi[0][s], bh);
                mma16816(acc[1][n], Ahi[1][s], bh);
                mma16816(acc[0][n], Ahi[0][s], bl);
                mma16816(acc[1][n], Ahi[1][s], bl);
                mma16816(acc[0][n], Alo[0][s], bh);
                mma16816(acc[1][n], Alo[1][s], bh);
            }
    }
    // epilogue 1: tanh + split -> next A frags (registers only)
#pragma unroll
    for (int i = 0; i < 2; i++)
#pragma unroll
        for (int n = 0; n < 8; n++) {
            int c0 = 8 * n + 2 * tg;
            float h0 = tanh_(acc[i][n][0] + bsm[c0]);
            float h1 = tanh_(acc[i][n][1] + bsm[c0 + 1]);
            float h2 = tanh_(acc[i][n][2] + bsm[c0]);
            float h3 = tanh_(acc[i][n][3] + bsm[c0 + 1]);
            uint2 p01 = split2(h0, h1);
            uint2 p23 = split2(h2, h3);
            int j = n >> 1, b = n & 1;
            Ahi[i][j][2 * b]     = p01.x; Alo[i][j][2 * b]     = p01.y;
            Ahi[i][j][2 * b + 1] = p23.x; Alo[i][j][2 * b + 1] = p23.y;
        }
    // stage W2 into buffer 1
    copy_plane(smp + WB1_OFF,        wsrc + 16384, 64, tid);
    copy_plane(smp + WB1_OFF + 9216, wsrc + 24576, 64, tid);
    __syncthreads();

    // ================= layer 2 =================
#pragma unroll
    for (int i = 0; i < 2; i++)
#pragma unroll
        for (int n = 0; n < 8; n++)
#pragma unroll
            for (int q = 0; q < 4; q++) acc[i][n][q] = 0.f;
    {
        const unsigned char* whi = smp + WB1_OFF;
        const unsigned char* wlo = whi + 9216;
#pragma unroll
        for (int n = 0; n < 8; n++)
#pragma unroll
            for (int s = 0; s < 4; s++) {
                int off = (8 * n + g) * WROWB + (16 * s + 2 * tg) * 2;
                uint32_t bh[2] = { *(const uint32_t*)(whi + off), *(const uint32_t*)(whi + off + 16) };
                uint32_t bl[2] = { *(const uint32_t*)(wlo + off), *(const uint32_t*)(wlo + off + 16) };
                mma16816(acc[0][n], Ahi[0][s], bh);
                mma16816(acc[1][n], Ahi[1][s], bh);
                mma16816(acc[0][n], Ahi[0][s], bl);
                mma16816(acc[1][n], Ahi[1][s], bl);
                mma16816(acc[0][n], Alo[0][s], bh);
                mma16816(acc[1][n], Alo[1][s], bh);
            }
    }
    // epilogue 2
#pragma unroll
    for (int i = 0; i < 2; i++)
#pragma unroll
        for (int n = 0; n < 8; n++) {
            int c0 = 8 * n + 2 * tg;
            float h0 = tanh_(acc[i][n][0] + bsm[64 + c0]);
            float h1 = tanh_(acc[i][n][1] + bsm[64 + c0 + 1]);
            float h2 = tanh_(acc[i][n][2] + bsm[64 + c0]);
            float h3 = tanh_(acc[i][n][3] + bsm[64 + c0 + 1]);
            uint2 p01 = split2(h0, h1);
            uint2 p23 = split2(h2, h3);
            int j = n >> 1, b = n & 1;
            Ahi[i][j][2 * b]     = p01.x; Alo[i][j][2 * b]     = p01.y;
            Ahi[i][j][2 * b + 1] = p23.x; Alo[i][j][2 * b + 1] = p23.y;
        }
    // stage W3 into buffer 0 (all warps are past their buffer-0 reads)
    copy_plane(smp + WB0_OFF,        wsrc + 32768, 32, tid);
    copy_plane(smp + WB0_OFF + 9216, wsrc + 36864, 32, tid);
    __syncthreads();

    // ================= layer 3 (N=32; cols >= 23 are zero pad) =================
#pragma unroll
    for (int i = 0; i < 2; i++)
#pragma unroll
        for (int n = 0; n < 4; n++)
#pragma unroll
            for (int q = 0; q < 4; q++) acc[i][n][q] = 0.f;
    {
        const unsigned char* whi = smp + WB0_OFF;
        const unsigned char* wlo = whi + 9216;
#pragma unroll
        for (int n = 0; n < 4; n++)
#pragma unroll
            for (int s = 0; s < 4; s++) {
                int off = (8 * n + g) * WROWB + (16 * s + 2 * tg) * 2;
                uint32_t bh[2] = { *(const uint32_t*)(whi + off), *(const uint32_t*)(whi + off + 16) };
                uint32_t bl[2] = { *(const uint32_t*)(wlo + off), *(const uint32_t*)(wlo + off + 16) };
                mma16816(acc[0][n], Ahi[0][s], bh);
                mma16816(acc[1][n], Ahi[1][s], bh);
                mma16816(acc[0][n], Ahi[0][s], bl);
                mma16816(acc[1][n], Ahi[1][s], bl);
                mma16816(acc[0][n], Alo[0][s], bh);
                mma16816(acc[1][n], Alo[1][s], bh);
            }
    }
    // write spline params to smem (reuse xs region), stride 24 floats
    float* psm = xs;
#pragma unroll
    for (int i = 0; i < 2; i++)
#pragma unroll
        for (int n = 0; n < 4; n++) {
            int c0 = 8 * n + 2 * tg;
            int r0 = mbase + 16 * i + g;
            if (c0 < OD)     psm[r0 * 24 + c0]           = acc[i][n][0] + bsm[128 + c0];
            if (c0 + 1 < OD) psm[r0 * 24 + c0 + 1]       = acc[i][n][1] + bsm[128 + c0 + 1];
            if (c0 < OD)     psm[(r0 + 8) * 24 + c0]     = acc[i][n][2] + bsm[128 + c0];
            if (c0 + 1 < OD) psm[(r0 + 8) * 24 + c0 + 1] = acc[i][n][3] + bsm[128 + c0 + 1];
        }
    __syncthreads();

    // ---- spline: one thread per batch row ----
    float zo, ldo;
    rqs23(xv, &psm[tid * 24], &zo, &ldo);
    z[(size_t)(m0 + tid) * DIMS + (l + 1)] = zo;
    g_ld[(size_t)(l + 1) * BATCH + m0 + tid] = ldo;
}

// ---------------------------------------------------------------------------
// dim 0 spline + logdet reduce
// ---------------------------------------------------------------------------
__global__ void __launch_bounds__(256) nsf_dim0(const float* __restrict__ x,
                                                const float* __restrict__ ip,
                                                float* __restrict__ z) {
    int b = blockIdx.x * blockDim.x + threadIdx.x;
    float p[23];
#pragma unroll
    for (int i = 0; i < 23; i++) p[i] = ip[i];
    float zo, ldo;
    rqs23(x[(size_t)b * DIMS], p, &zo, &ldo);
    z[(size_t)b * DIMS] = zo;
    g_ld[b] = ldo;
}

__global__ void __launch_bounds__(256) nsf_reduce(float* __restrict__ ldo) {
    int b = blockIdx.x * blockDim.x + threadIdx.x;
    float s = 0.f;
#pragma unroll
    for (int d = 0; d < DIMS; d++) s += g_ld[(size_t)d * BATCH + b];
    ldo[b] = s;
}

// ---------------------------------------------------------------------------
extern "C" void kernel_launch(void* const* d_in, const int* in_sizes, int n_in,
                              void* d_out, int out_size) {
    const float* x  = (const float*)d_in[0];
    const float* ip = (const float*)d_in[1];
    const float* W1 = (const float*)d_in[2];
    const float* b1 = (const float*)d_in[3];
    const float* W2 = (const float*)d_in[4];
    const float* b2 = (const float*)d_in[5];
    const float* W3 = (const float*)d_in[6];
    const float* b3 = (const float*)d_in[7];

    float* z   = (float*)d_out;
    float* ldo = z + (size_t)BATCH * DIMS;

    cudaFuncSetAttribute(nsf_main, cudaFuncAttributeMaxDynamicSharedMemorySize, SMEM_BYTES);

    nsf_prep<<<LAYERS, 256>>>(W1, W2, W3);
    nsf_dim0<<<BATCH / 256, 256>>>(x, ip, z);
    nsf_main<<<dim3(128, LAYERS), 128, SMEM_BYTES>>>(x, b1, b2, b3, z);
    nsf_reduce<<<BATCH / 256, 256>>>(ldo);
}

// round 7
// speedup vs baseline: 2.2498x; 1.2536x over previous
#include <cuda_runtime.h>
#include <cuda_bf16.h>
#include <math.h>
#include <stdint.h>

#define BATCH 16384
#define DIMS  64
#define LAYERS 63
#define HID   64
#define OD    23
#define BTAIL 3.0f
#define XSTR  68            // xs row stride in floats

// per-(dim,batch) logdet partials (deterministic reduce)
__device__ float g_ld[DIMS * BATCH];
// pre-split bf16 weight planes per layer:
// [W1hi 8K][W1lo 8K][W2hi 8K][W2lo 8K][W3hi 4K][W3lo 4K] = 40960 B
__device__ __align__(16) unsigned char g_w[(size_t)LAYERS * 40960];

// dynamic smem layout (bytes)
#define XS_OFF   0            // 128 x 68 floats = 34816 (reused as psm [128][24])
#define WB0_OFF  34816        // hi plane +0, lo plane +9216 (rows padded to 144B)
#define WB1_OFF  53248
#define BIAS_OFF 71680        // b1[64] b2[64] b3[23]
#define SMEM_BYTES 72320
#define WROWB 144             // 72 bf16 per weight row

// ---------------------------------------------------------------------------
// mma.sync m16n8k16 bf16 (baseline PTX, works on plain sm_103)
// ---------------------------------------------------------------------------
__device__ __forceinline__ void mma16816(float* c, const uint32_t* a, const uint32_t* b) {
    asm volatile(
        "mma.sync.aligned.m16n8k16.row.col.f32.bf16.bf16.f32 "
        "{%0,%1,%2,%3}, {%4,%5,%6,%7}, {%8,%9}, {%0,%1,%2,%3};"
        : "+f"(c[0]), "+f"(c[1]), "+f"(c[2]), "+f"(c[3])
        : "r"(a[0]), "r"(a[1]), "r"(a[2]), "r"(a[3]), "r"(b[0]), "r"(b[1]));
}

// split pair of floats into bf16 hi plane + bf16 lo (residual) plane, packed
__device__ __forceinline__ uint2 split2(float f0, float f1) {
    __nv_bfloat162 h = __floats2bfloat162_rn(f0, f1);
    float r0 = f0 - __bfloat162float(h.x);
    float r1 = f1 - __bfloat162float(h.y);
    __nv_bfloat162 l = __floats2bfloat162_rn(r0, r1);
    uint2 o;
    o.x = *(uint32_t*)&h;
    o.y = *(uint32_t*)&l;
    return o;
}

// single-instruction MUFU tanh (abs err ~2^-11)
__device__ __forceinline__ float tanha(float v) {
    float r;
    asm("tanh.approx.f32 %0, %1;" : "=f"(r) : "f"(v));
    return r;
}

// ---------------------------------------------------------------------------
// math helpers for the spline (exact path, unchanged numerics)
// ---------------------------------------------------------------------------
__device__ __forceinline__ float softplus_(float x) {
    return (x > 15.f) ? x : log1pf(__expf(x));
}
__device__ __forceinline__ void softmax8(const float* in, float* out, float scale) {
    float m = in[0];
#pragma unroll
    for (int i = 1; i < 8; i++) m = fmaxf(m, in[i]);
    float e[8], s = 0.f;
#pragma unroll
    for (int i = 0; i < 8; i++) { e[i] = __expf(in[i] - m); s += e[i]; }
    float inv = scale / s;
#pragma unroll
    for (int i = 0; i < 8; i++) out[i] = e[i] * inv;
}

__device__ __forceinline__ void rqs23(float xval, const float* __restrict__ p,
                                      float* zo, float* ldo) {
    float W[8], H[8], wi[8], he[8];
    softmax8(p,     W, 2.f * BTAIL);
    softmax8(p + 8, H, 2.f * BTAIL);
    softmax8(W, wi, 1.f);
    softmax8(H, he, 1.f);

    float cw[9], ch[9];
    cw[0] = -BTAIL; ch[0] = -BTAIL;
    float aw = 0.f, ah = 0.f;
#pragma unroll
    for (int i = 0; i < 8; i++) {
        float wv = 1e-3f + (1.f - 8e-3f) * wi[i];
        float hv = 1e-3f + (1.f - 8e-3f) * he[i];
        aw += wv; ah += hv;
        cw[i + 1] = 2.f * BTAIL * aw - BTAIL;
        ch[i + 1] = 2.f * BTAIL * ah - BTAIL;
    }
    cw[8] = BTAIL; ch[8] = BTAIL;

    float der[9];
    const float UDC = logf(expf(1.0f - 1e-3f) - 1.0f);
    float edge = 1e-3f + softplus_(UDC);
    der[0] = edge; der[8] = edge;
#pragma unroll
    for (int i = 0; i < 7; i++) der[i + 1] = 1e-3f + softplus_(softplus_(p[16 + i]));

    bool inside = (xval >= -BTAIL) && (xval <= BTAIL);
    float x = fminf(fmaxf(xval, -BTAIL), BTAIL);

    int bin = 0;
#pragma unroll
    for (int i = 1; i < 8; i++) bin += (x >= cw[i]) ? 1 : 0;

    float icw = 0.f, iw = 1.f, ich = 0.f, ih = 1.f, dk = 1.f, dk1 = 1.f;
#pragma unroll
    for (int i = 0; i < 8; i++) {
        if (bin == i) {
            icw = cw[i];  iw = cw[i + 1] - cw[i];
            ich = ch[i];  ih = ch[i + 1] - ch[i];
            dk = der[i];  dk1 = der[i + 1];
        }
    }

    float delta = ih / iw;
    float th  = (x - icw) / iw;
    float t1  = th * (1.f - th);
    float numer = ih * (delta * th * th + dk * t1);
    float denom = delta + (dk + dk1 - 2.f * delta) * t1;
    float out = ich + numer / denom;
    float om = 1.f - th;
    float dnum = delta * delta * (dk1 * th * th + 2.f * delta * t1 + dk * om * om);
    float ld = logf(dnum) - 2.f * logf(denom);

    *zo  = inside ? out : xval;
    *ldo = inside ? ld  : 0.f;
}

// ---------------------------------------------------------------------------
// prep: split fp32 weights into bf16 hi/lo planes ([n][k] row-major, no pad)
// ---------------------------------------------------------------------------
__global__ void __launch_bounds__(256) nsf_prep(const float* __restrict__ W1,
                                                const float* __restrict__ W2,
                                                const float* __restrict__ W3) {
    int l = blockIdx.x, tid = threadIdx.x;
    unsigned char* dst = g_w + (size_t)l * 40960;
    for (int idx = tid; idx < 4096; idx += 256) {
        float v = W1[(size_t)l * 4096 + idx];
        __nv_bfloat16 h = __float2bfloat16(v);
        __nv_bfloat16 lo = __float2bfloat16(v - __bfloat162float(h));
        ((__nv_bfloat16*)dst)[idx] = h;
        ((__nv_bfloat16*)(dst + 8192))[idx] = lo;
    }
    for (int idx = tid; idx < 4096; idx += 256) {
        float v = W2[(size_t)l * 4096 + idx];
        __nv_bfloat16 h = __float2bfloat16(v);
        __nv_bfloat16 lo = __float2bfloat16(v - __bfloat162float(h));
        ((__nv_bfloat16*)(dst + 16384))[idx] = h;
        ((__nv_bfloat16*)(dst + 24576))[idx] = lo;
    }
    for (int idx = tid; idx < 2048; idx += 256) {
        int n = idx >> 6, k = idx & 63;
        float v = (n < OD) ? W3[(size_t)l * OD * 64 + n * 64 + k] : 0.f;
        __nv_bfloat16 h = __float2bfloat16(v);
        __nv_bfloat16 lo = __float2bfloat16(v - __bfloat162float(h));
        ((__nv_bfloat16*)(dst + 32768))[idx] = h;
        ((__nv_bfloat16*)(dst + 36864))[idx] = lo;
    }
}

// copy a [rows][64]-bf16 plane (src 128B rows) to smem rows padded to 144B,
// copying only the first C4 uint4 (=C4*8 bf16 cols) of each row
template <int ROWS, int C4>
__device__ __forceinline__ void copy_plane(unsigned char* dst, const unsigned char* src,
                                           int tid) {
#pragma unroll 2
    for (int i = tid; i < ROWS * C4; i += 128) {
        int r = i / C4, q = i % C4;
        ((uint4*)(dst + r * WROWB))[q] = ((const uint4*)src)[r * 8 + q];
    }
}

// ---------------------------------------------------------------------------
// main fused kernel, templated on NS = number of live 16-wide K-chunks of x
// (layer l has l+1 live input columns -> NS = l/16 + 1)
// ---------------------------------------------------------------------------
template <int NS>
__global__ void __launch_bounds__(128, 3) nsf_main(
    const float* __restrict__ x,
    const float* __restrict__ b1, const float* __restrict__ b2,
    const float* __restrict__ b3, float* __restrict__ z, int lbase) {
    extern __shared__ unsigned char smp[];
    float* xs = (float*)(smp + XS_OFF);
    float* bsm = (float*)(smp + BIAS_OFF);

    const int tid = threadIdx.x;
    const int warp = tid >> 5, lane = tid & 31;
    const int g = lane >> 2, tg = lane & 3;
    const int l = lbase + blockIdx.y, m0 = blockIdx.x * 128;
    const int mbase = warp * 32;

    // ---- stage: masked x tile (only live K-chunks), W1 planes, biases ----
    constexpr int NC4 = NS * 4;              // float4 per row staged
    for (int idx = tid; idx < 128 * NC4; idx += 128) {
        int r = idx / NC4, c4 = idx % NC4;
        float4 v = ((const float4*)(x + (size_t)(m0 + r) * DIMS))[c4];
        int c = c4 << 2;
        if (c + 0 > l) v.x = 0.f;
        if (c + 1 > l) v.y = 0.f;
        if (c + 2 > l) v.z = 0.f;
        if (c + 3 > l) v.w = 0.f;
        *(float4*)(&xs[r * XSTR + c]) = v;
    }
    const unsigned char* wsrc = g_w + (size_t)l * 40960;
    copy_plane<64, NS * 2>(smp + WB0_OFF,        wsrc,        tid);   // W1 hi (live cols)
    copy_plane<64, NS * 2>(smp + WB0_OFF + 9216, wsrc + 8192, tid);   // W1 lo
    if (tid < 64) { bsm[tid] = b1[l * 64 + tid]; bsm[64 + tid] = b2[l * 64 + tid]; }
    if (tid < OD)  bsm[128 + tid] = b3[l * OD + tid];
    float xv = x[(size_t)(m0 + tid) * DIMS + (l + 1)];
    __syncthreads();

    // ---- build layer-1 A fragments from xs (hi/lo split), live chunks only ----
    uint32_t Ahi[2][4][4], Alo[2][4][4];
#pragma unroll
    for (int i = 0; i < 2; i++) {
#pragma unroll
        for (int s = 0; s < NS; s++) {
            int r0 = mbase + 16 * i + g;
            int c0 = 16 * s + 2 * tg;
            uint2 p;
            p = split2(xs[r0 * XSTR + c0],           xs[r0 * XSTR + c0 + 1]);
            Ahi[i][s][0] = p.x; Alo[i][s][0] = p.y;
            p = split2(xs[(r0 + 8) * XSTR + c0],     xs[(r0 + 8) * XSTR + c0 + 1]);
            Ahi[i][s][1] = p.x; Alo[i][s][1] = p.y;
            p = split2(xs[r0 * XSTR + c0 + 8],       xs[r0 * XSTR + c0 + 9]);
            Ahi[i][s][2] = p.x; Alo[i][s][2] = p.y;
            p = split2(xs[(r0 + 8) * XSTR + c0 + 8], xs[(r0 + 8) * XSTR + c0 + 9]);
            Ahi[i][s][3] = p.x; Alo[i][s][3] = p.y;
        }
    }

    float acc[2][8][4];

    // ================= layer 1 (K = 16*NS) =================
#pragma unroll
    for (int i = 0; i < 2; i++)
#pragma unroll
        for (int n = 0; n < 8; n++)
#pragma unroll
            for (int q = 0; q < 4; q++) acc[i][n][q] = 0.f;
    {
        const unsigned char* whi = smp + WB0_OFF;
        const unsigned char* wlo = whi + 9216;
#pragma unroll
        for (int n = 0; n < 8; n++)
#pragma unroll
            for (int s = 0; s < NS; s++) {
                int off = (8 * n + g) * WROWB + (16 * s + 2 * tg) * 2;
                uint32_t bh[2] = { *(const uint32_t*)(whi + off), *(const uint32_t*)(whi + off + 16) };
                uint32_t bl[2] = { *(const uint32_t*)(wlo + off), *(const uint32_t*)(wlo + off + 16) };
                mma16816(acc[0][n], Ahi[0][s], bh);
                mma16816(acc[1][n], Ahi[1][s], bh);
                mma16816(acc[0][n], Ahi[0][s], bl);
                mma16816(acc[1][n], Ahi[1][s], bl);
                mma16816(acc[0][n], Alo[0][s], bh);
                mma16816(acc[1][n], Alo[1][s], bh);
            }
    }
    // epilogue 1: tanh + split -> next A frags (registers only)
#pragma unroll
    for (int i = 0; i < 2; i++)
#pragma unroll
        for (int n = 0; n < 8; n++) {
            int c0 = 8 * n + 2 * tg;
            float h0 = tanha(acc[i][n][0] + bsm[c0]);
            float h1 = tanha(acc[i][n][1] + bsm[c0 + 1]);
            float h2 = tanha(acc[i][n][2] + bsm[c0]);
            float h3 = tanha(acc[i][n][3] + bsm[c0 + 1]);
            uint2 p01 = split2(h0, h1);
            uint2 p23 = split2(h2, h3);
            int j = n >> 1, b = n & 1;
            Ahi[i][j][2 * b]     = p01.x; Alo[i][j][2 * b]     = p01.y;
            Ahi[i][j][2 * b + 1] = p23.x; Alo[i][j][2 * b + 1] = p23.y;
        }
    // stage W2 into buffer 1
    copy_plane<64, 8>(smp + WB1_OFF,        wsrc + 16384, tid);
    copy_plane<64, 8>(smp + WB1_OFF + 9216, wsrc + 24576, tid);
    __syncthreads();

    // ================= layer 2 =================
#pragma unroll
    for (int i = 0; i < 2; i++)
#pragma unroll
        for (int n = 0; n < 8; n++)
#pragma unroll
            for (int q = 0; q < 4; q++) acc[i][n][q] = 0.f;
    {
        const unsigned char* whi = smp + WB1_OFF;
        const unsigned char* wlo = whi + 9216;
#pragma unroll
        for (int n = 0; n < 8; n++)
#pragma unroll
            for (int s = 0; s < 4; s++) {
                int off = (8 * n + g) * WROWB + (16 * s + 2 * tg) * 2;
                uint32_t bh[2] = { *(const uint32_t*)(whi + off), *(const uint32_t*)(whi + off + 16) };
                uint32_t bl[2] = { *(const uint32_t*)(wlo + off), *(const uint32_t*)(wlo + off + 16) };
                mma16816(acc[0][n], Ahi[0][s], bh);
                mma16816(acc[1][n], Ahi[1][s], bh);
                mma16816(acc[0][n], Ahi[0][s], bl);
                mma16816(acc[1][n], Ahi[1][s], bl);
                mma16816(acc[0][n], Alo[0][s], bh);
                mma16816(acc[1][n], Alo[1][s], bh);
            }
    }
    // epilogue 2
#pragma unroll
    for (int i = 0; i < 2; i++)
#pragma unroll
        for (int n = 0; n < 8; n++) {
            int c0 = 8 * n + 2 * tg;
            float h0 = tanha(acc[i][n][0] + bsm[64 + c0]);
            float h1 = tanha(acc[i][n][1] + bsm[64 + c0 + 1]);
            float h2 = tanha(acc[i][n][2] + bsm[64 + c0]);
            float h3 = tanha(acc[i][n][3] + bsm[64 + c0 + 1]);
            uint2 p01 = split2(h0, h1);
            uint2 p23 = split2(h2, h3);
            int j = n >> 1, b = n & 1;
            Ahi[i][j][2 * b]     = p01.x; Alo[i][j][2 * b]     = p01.y;
            Ahi[i][j][2 * b + 1] = p23.x; Alo[i][j][2 * b + 1] = p23.y;
        }
    // stage W3 into buffer 0 (all warps are past their buffer-0 reads)
    copy_plane<24, 8>(smp + WB0_OFF,        wsrc + 32768, tid);
    copy_plane<24, 8>(smp + WB0_OFF + 9216, wsrc + 36864, tid);
    __syncthreads();

    // ================= layer 3 (3 n-tiles = 24 cols >= OD) =================
#pragma unroll
    for (int i = 0; i < 2; i++)
#pragma unroll
        for (int n = 0; n < 3; n++)
#pragma unroll
            for (int q = 0; q < 4; q++) acc[i][n][q] = 0.f;
    {
        const unsigned char* whi = smp + WB0_OFF;
        const unsigned char* wlo = whi + 9216;
#pragma unroll
        for (int n = 0; n < 3; n++)
#pragma unroll
            for (int s = 0; s < 4; s++) {
                int off = (8 * n + g) * WROWB + (16 * s + 2 * tg) * 2;
                uint32_t bh[2] = { *(const uint32_t*)(whi + off), *(const uint32_t*)(whi + off + 16) };
                uint32_t bl[2] = { *(const uint32_t*)(wlo + off), *(const uint32_t*)(wlo + off + 16) };
                mma16816(acc[0][n], Ahi[0][s], bh);
                mma16816(acc[1][n], Ahi[1][s], bh);
                mma16816(acc[0][n], Ahi[0][s], bl);
                mma16816(acc[1][n], Ahi[1][s], bl);
                mma16816(acc[0][n], Alo[0][s], bh);
                mma16816(acc[1][n], Alo[1][s], bh);
            }
    }
    // write spline params to smem (reuse xs region), stride 24 floats
    float* psm = xs;
#pragma unroll
    for (int i = 0; i < 2; i++)
#pragma unroll
        for (int n = 0; n < 3; n++) {
            int c0 = 8 * n + 2 * tg;
            int r0 = mbase + 16 * i + g;
            if (c0 < OD)     psm[r0 * 24 + c0]           = acc[i][n][0] + bsm[128 + c0];
            if (c0 + 1 < OD) psm[r0 * 24 + c0 + 1]       = acc[i][n][1] + bsm[128 + c0 + 1];
            if (c0 < OD)     psm[(r0 + 8) * 24 + c0]     = acc[i][n][2] + bsm[128 + c0];
            if (c0 + 1 < OD) psm[(r0 + 8) * 24 + c0 + 1] = acc[i][n][3] + bsm[128 + c0 + 1];
        }
    __syncthreads();

    // ---- spline: one thread per batch row ----
    float zo, ldo;
    rqs23(xv, &psm[tid * 24], &zo, &ldo);
    z[(size_t)(m0 + tid) * DIMS + (l + 1)] = zo;
    g_ld[(size_t)(l + 1) * BATCH + m0 + tid] = ldo;
}

// ---------------------------------------------------------------------------
// dim 0 spline + logdet reduce
// ---------------------------------------------------------------------------
__global__ void __launch_bounds__(128) nsf_dim0(const float* __restrict__ x,
                                                const float* __restrict__ ip,
                                                float* __restrict__ z) {
    int b = blockIdx.x * blockDim.x + threadIdx.x;
    float p[23];
#pragma unroll
    for (int i = 0; i < 23; i++) p[i] = ip[i];
    float zo, ldo;
    rqs23(x[(size_t)b * DIMS], p, &zo, &ldo);
    z[(size_t)b * DIMS] = zo;
    g_ld[b] = ldo;
}

__global__ void __launch_bounds__(128) nsf_reduce(float* __restrict__ ldo) {
    int b = blockIdx.x * blockDim.x + threadIdx.x;
    float s = 0.f;
#pragma unroll
    for (int d = 0; d < DIMS; d++) s += g_ld[(size_t)d * BATCH + b];
    ldo[b] = s;
}

// ---------------------------------------------------------------------------
extern "C" void kernel_launch(void* const* d_in, const int* in_sizes, int n_in,
                              void* d_out, int out_size) {
    const float* x  = (const float*)d_in[0];
    const float* ip = (const float*)d_in[1];
    const float* W1 = (const float*)d_in[2];
    const float* b1 = (const float*)d_in[3];
    const float* W2 = (const float*)d_in[4];
    const float* b2 = (const float*)d_in[5];
    const float* W3 = (const float*)d_in[6];
    const float* b3 = (const float*)d_in[7];

    float* z   = (float*)d_out;
    float* ldo = z + (size_t)BATCH * DIMS;

    cudaFuncSetAttribute(nsf_main<1>, cudaFuncAttributeMaxDynamicSharedMemorySize, SMEM_BYTES);
    cudaFuncSetAttribute(nsf_main<2>, cudaFuncAttributeMaxDynamicSharedMemorySize, SMEM_BYTES);
    cudaFuncSetAttribute(nsf_main<3>, cudaFuncAttributeMaxDynamicSharedMemorySize, SMEM_BYTES);
    cudaFuncSetAttribute(nsf_main<4>, cudaFuncAttributeMaxDynamicSharedMemorySize, SMEM_BYTES);

    nsf_prep<<<LAYERS, 256>>>(W1, W2, W3);
    nsf_dim0<<<BATCH / 128, 128>>>(x, ip, z);
    nsf_main<1><<<dim3(128, 16), 128, SMEM_BYTES>>>(x, b1, b2, b3, z, 0);
    nsf_main<2><<<dim3(128, 16), 128, SMEM_BYTES>>>(x, b1, b2, b3, z, 16);
    nsf_main<3><<<dim3(128, 16), 128, SMEM_BYTES>>>(x, b1, b2, b3, z, 32);
    nsf_main<4><<<dim3(128, 15), 128, SMEM_BYTES>>>(x, b1, b2, b3, z, 48);
    nsf_reduce<<<BATCH / 128, 128>>>(ldo);
}

// round 8
// speedup vs baseline: 2.7899x; 1.2400x over previous
#include <cuda_runtime.h>
#include <cuda_bf16.h>
#include <math.h>
#include <stdint.h>

#define BATCH 16384
#define DIMS  64
#define LAYERS 63
#define HID   64
#define OD    23
#define BTAIL 3.0f

// per-(batch,dim) logdet partials, [b][d] layout (coalesced reduce)
__device__ float g_ld[BATCH * DIMS];
// fragment-ordered packed weights, per layer stride 38912 B:
//   W1 frags @0 (16384), W2 @16384 (16384), W3 @32768 (6144)
//   frag record = uint4 {hi0,hi1,lo0,lo1}
__device__ __align__(16) unsigned char g_w[(size_t)LAYERS * 38912];
// pre-split x: pair-packed planes, g_xpk[b*32+p] = {hi(2p,2p+1), lo(2p,2p+1)}
__device__ __align__(16) uint2 g_xpk[(size_t)BATCH * 32];

// dynamic smem layout (bytes)
#define WB1_OFF  0          // 16384 (W1 frags; later W3 frags)
#define WB2_OFF  16384      // 16384 (W2 frags)
#define PSM_OFF  32768      // 128 x 25 floats = 12800
#define BIAS_OFF 45568      // b1[64] b2[64] b3[23]
#define SMEM_BYTES 46208

// ---------------------------------------------------------------------------
// mma.sync m16n8k16 bf16
// ---------------------------------------------------------------------------
__device__ __forceinline__ void mma16816(float* c, const uint32_t* a, const uint32_t* b) {
    asm volatile(
        "mma.sync.aligned.m16n8k16.row.col.f32.bf16.bf16.f32 "
        "{%0,%1,%2,%3}, {%4,%5,%6,%7}, {%8,%9}, {%0,%1,%2,%3};"
        : "+f"(c[0]), "+f"(c[1]), "+f"(c[2]), "+f"(c[3])
        : "r"(a[0]), "r"(a[1]), "r"(a[2]), "r"(a[3]), "r"(b[0]), "r"(b[1]));
}

__device__ __forceinline__ uint2 split2(float f0, float f1) {
    __nv_bfloat162 h = __floats2bfloat162_rn(f0, f1);
    float r0 = f0 - __bfloat162float(h.x);
    float r1 = f1 - __bfloat162float(h.y);
    __nv_bfloat162 l = __floats2bfloat162_rn(r0, r1);
    uint2 o;
    o.x = *(uint32_t*)&h;
    o.y = *(uint32_t*)&l;
    return o;
}

__device__ __forceinline__ float tanha(float v) {
    float r;
    asm("tanh.approx.f32 %0, %1;" : "=f"(r) : "f"(v));
    return r;
}

// ---------------------------------------------------------------------------
// spline math (identical numerics to round-7 kernel), split into
// table-build + eval so dim0 can share tables across the batch
// ---------------------------------------------------------------------------
__device__ __forceinline__ float softplus_(float x) {
    return (x > 15.f) ? x : log1pf(__expf(x));
}
__device__ __forceinline__ void softmax8(const float* in, float* out, float scale) {
    float m = in[0];
#pragma unroll
    for (int i = 1; i < 8; i++) m = fmaxf(m, in[i]);
    float e[8], s = 0.f;
#pragma unroll
    for (int i = 0; i < 8; i++) { e[i] = __expf(in[i] - m); s += e[i]; }
    float inv = scale / s;
#pragma unroll
    for (int i = 0; i < 8; i++) out[i] = e[i] * inv;
}

__device__ __forceinline__ void rqs_tables(const float* __restrict__ p,
                                           float* cw, float* ch, float* der) {
    float W[8], H[8], wi[8], he[8];
    softmax8(p,     W, 2.f * BTAIL);
    softmax8(p + 8, H, 2.f * BTAIL);
    softmax8(W, wi, 1.f);
    softmax8(H, he, 1.f);

    cw[0] = -BTAIL; ch[0] = -BTAIL;
    float aw = 0.f, ah = 0.f;
#pragma unroll
    for (int i = 0; i < 8; i++) {
        float wv = 1e-3f + (1.f - 8e-3f) * wi[i];
        float hv = 1e-3f + (1.f - 8e-3f) * he[i];
        aw += wv; ah += hv;
        cw[i + 1] = 2.f * BTAIL * aw - BTAIL;
        ch[i + 1] = 2.f * BTAIL * ah - BTAIL;
    }
    cw[8] = BTAIL; ch[8] = BTAIL;

    const float UDC = logf(expf(1.0f - 1e-3f) - 1.0f);
    float edge = 1e-3f + softplus_(UDC);
    der[0] = edge; der[8] = edge;
#pragma unroll
    for (int i = 0; i < 7; i++) der[i + 1] = 1e-3f + softplus_(softplus_(p[16 + i]));
}

__device__ __forceinline__ void rqs_eval(float xval, const float* __restrict__ cw,
                                         const float* __restrict__ ch,
                                         const float* __restrict__ der,
                                         float* zo, float* ldo) {
    bool inside = (xval >= -BTAIL) && (xval <= BTAIL);
    float x = fminf(fmaxf(xval, -BTAIL), BTAIL);

    int bin = 0;
#pragma unroll
    for (int i = 1; i < 8; i++) bin += (x >= cw[i]) ? 1 : 0;

    float icw = 0.f, iw = 1.f, ich = 0.f, ih = 1.f, dk = 1.f, dk1 = 1.f;
#pragma unroll
    for (int i = 0; i < 8; i++) {
        if (bin == i) {
            icw = cw[i];  iw = cw[i + 1] - cw[i];
            ich = ch[i];  ih = ch[i + 1] - ch[i];
            dk = der[i];  dk1 = der[i + 1];
        }
    }

    float delta = ih / iw;
    float th  = (x - icw) / iw;
    float t1  = th * (1.f - th);
    float numer = ih * (delta * th * th + dk * t1);
    float denom = delta + (dk + dk1 - 2.f * delta) * t1;
    float out = ich + numer / denom;
    float om = 1.f - th;
    float dnum = delta * delta * (dk1 * th * th + 2.f * delta * t1 + dk * om * om);
    float ld = logf(dnum) - 2.f * logf(denom);

    *zo  = inside ? out : xval;
    *ldo = inside ? ld  : 0.f;
}

__device__ __forceinline__ void rqs23(float xval, const float* __restrict__ p,
                                      float* zo, float* ldo) {
    float cw[9], ch[9], der[9];
    rqs_tables(p, cw, ch, der);
    rqs_eval(xval, cw, ch, der, zo, ldo);
}

// ---------------------------------------------------------------------------
// prep: weights -> fragment-ordered hi/lo records; x -> pair-packed planes
// ---------------------------------------------------------------------------
__global__ void __launch_bounds__(256) nsf_prep_w(const float* __restrict__ W1,
                                                  const float* __restrict__ W2,
                                                  const float* __restrict__ W3) {
    int l = blockIdx.x, tid = threadIdx.x;
    uint4* base = (uint4*)(g_w + (size_t)l * 38912);
    // W1, W2: frag f = (s*8+n)*32 + lane
    for (int f = tid; f < 1024; f += 256) {
        int s = f >> 8, n = (f >> 5) & 7, lane = f & 31;
        int g = lane >> 2, tg = lane & 3;
        int row = 8 * n + g, c0 = 16 * s + 2 * tg;
        const float* w = W1 + (size_t)l * 4096 + row * 64;
        uint2 a = split2(w[c0], w[c0 + 1]);
        uint2 b = split2(w[c0 + 8], w[c0 + 9]);
        base[f] = make_uint4(a.x, b.x, a.y, b.y);
        w = W2 + (size_t)l * 4096 + row * 64;
        a = split2(w[c0], w[c0 + 1]);
        b = split2(w[c0 + 8], w[c0 + 9]);
        base[1024 + f] = make_uint4(a.x, b.x, a.y, b.y);
    }
    // W3: frag f = (s*3+n)*32 + lane, rows >= OD are zero pad
    for (int f = tid; f < 384; f += 256) {
        int sn = f >> 5, lane = f & 31;
        int s = sn / 3, n = sn % 3;
        int g = lane >> 2, tg = lane & 3;
        int row = 8 * n + g, c0 = 16 * s + 2 * tg;
        uint4 rec = make_uint4(0, 0, 0, 0);
        if (row < OD) {
            const float* w = W3 + (size_t)l * OD * 64 + row * 64;
            uint2 a = split2(w[c0], w[c0 + 1]);
            uint2 b = split2(w[c0 + 8], w[c0 + 9]);
            rec = make_uint4(a.x, b.x, a.y, b.y);
        }
        base[2048 + f] = rec;
    }
}

__global__ void __launch_bounds__(256) nsf_prep_x(const float* __restrict__ x) {
    int idx = blockIdx.x * 256 + threadIdx.x;   // b*32 + p
    int c = (idx & 31) * 2;
    const float* xr = x + (size_t)(idx >> 5) * DIMS;
    g_xpk[idx] = split2(xr[c], xr[c + 1]);
}

// ---------------------------------------------------------------------------
// main fused kernel: merged over all layers, dispatch on NS = l/16+1
// ---------------------------------------------------------------------------
template <int NS>
__device__ __forceinline__ void run_main(unsigned char* smp, int l,
                                         const float* __restrict__ x,
                                         const float* __restrict__ b1,
                                         const float* __restrict__ b2,
                                         const float* __restrict__ b3,
                                         float* __restrict__ z) {
    float* psm = (float*)(smp + PSM_OFF);
    float* bsm = (float*)(smp + BIAS_OFF);
    const uint4* wb1 = (const uint4*)(smp + WB1_OFF);
    const uint4* wb2 = (const uint4*)(smp + WB2_OFF);

    const int tid = threadIdx.x;
    const int warp = tid >> 5, lane = tid & 31;
    const int g = lane >> 2, tg = lane & 3;
    const int m0 = blockIdx.x * 128;
    const int mbase = warp * 32;

    // ---- stage W1 live-chunk frags + biases ----
    const uint4* wsrc = (const uint4*)(g_w + (size_t)l * 38912);
    {
        uint4* d = (uint4*)(smp + WB1_OFF);
#pragma unroll
        for (int i = 0; i < NS * 2; i++) d[i * 128 + tid] = wsrc[i * 128 + tid];
    }
    if (tid < 64) { bsm[tid] = b1[l * 64 + tid]; bsm[64 + tid] = b2[l * 64 + tid]; }
    if (tid < OD)  bsm[128 + tid] = b3[l * OD + tid];
    float xv = x[(size_t)(m0 + tid) * DIMS + (l + 1)];

    // ---- layer-1 A fragments straight from packed global x ----
    uint32_t Ahi[2][4][4], Alo[2][4][4];
    // boundary-chunk column masks (chunk NS-1)
    uint32_t mA, mB;
    {
        int cA = 16 * (NS - 1) + 2 * tg, cB = cA + 8;
        mA = (cA + 1 <= l) ? 0xFFFFFFFFu : ((cA <= l) ? 0x0000FFFFu : 0u);
        mB = (cB + 1 <= l) ? 0xFFFFFFFFu : ((cB <= l) ? 0x0000FFFFu : 0u);
    }
#pragma unroll
    for (int i = 0; i < 2; i++) {
        int r0 = m0 + mbase + 16 * i + g;
#pragma unroll
        for (int s = 0; s < NS; s++) {
            int p0 = 8 * s + tg;
            uint2 v00 = g_xpk[(size_t)r0 * 32 + p0];
            uint2 v01 = g_xpk[(size_t)(r0 + 8) * 32 + p0];
            uint2 v10 = g_xpk[(size_t)r0 * 32 + p0 + 4];
            uint2 v11 = g_xpk[(size_t)(r0 + 8) * 32 + p0 + 4];
            if (s == NS - 1) {
                v00.x &= mA; v00.y &= mA; v01.x &= mA; v01.y &= mA;
                v10.x &= mB; v10.y &= mB; v11.x &= mB; v11.y &= mB;
            }
            Ahi[i][s][0] = v00.x; Alo[i][s][0] = v00.y;
            Ahi[i][s][1] = v01.x; Alo[i][s][1] = v01.y;
            Ahi[i][s][2] = v10.x; Alo[i][s][2] = v10.y;
            Ahi[i][s][3] = v11.x; Alo[i][s][3] = v11.y;
        }
    }
    __syncthreads();

    float acc[2][8][4];

    // ================= layer 1 (K = 16*NS) =================
#pragma unroll
    for (int i = 0; i < 2; i++)
#pragma unroll
        for (int n = 0; n < 8; n++)
#pragma unroll
            for (int q = 0; q < 4; q++) acc[i][n][q] = 0.f;
#pragma unroll
    for (int n = 0; n < 8; n++)
#pragma unroll
        for (int s = 0; s < NS; s++) {
            uint4 w = wb1[(s * 8 + n) * 32 + lane];
            uint32_t bh[2] = { w.x, w.y }, bl[2] = { w.z, w.w };
            mma16816(acc[0][n], Ahi[0][s], bh);
            mma16816(acc[1][n], Ahi[1][s], bh);
            mma16816(acc[0][n], Ahi[0][s], bl);
            mma16816(acc[1][n], Ahi[1][s], bl);
            mma16816(acc[0][n], Alo[0][s], bh);
            mma16816(acc[1][n], Alo[1][s], bh);
        }
    // epilogue 1: tanh + split -> next A frags (registers only)
#pragma unroll
    for (int i = 0; i < 2; i++)
#pragma unroll
        for (int n = 0; n < 8; n++) {
            int c0 = 8 * n + 2 * tg;
            float h0 = tanha(acc[i][n][0] + bsm[c0]);
            float h1 = tanha(acc[i][n][1] + bsm[c0 + 1]);
            float h2 = tanha(acc[i][n][2] + bsm[c0]);
            float h3 = tanha(acc[i][n][3] + bsm[c0 + 1]);
            uint2 p01 = split2(h0, h1);
            uint2 p23 = split2(h2, h3);
            int j = n >> 1, b = n & 1;
            Ahi[i][j][2 * b]     = p01.x; Alo[i][j][2 * b]     = p01.y;
            Ahi[i][j][2 * b + 1] = p23.x; Alo[i][j][2 * b + 1] = p23.y;
        }
    // stage W2 frags
    {
        uint4* d = (uint4*)(smp + WB2_OFF);
#pragma unroll
        for (int i = 0; i < 8; i++) d[i * 128 + tid] = wsrc[1024 + i * 128 + tid];
    }
    __syncthreads();

    // ================= layer 2 =================
#pragma unroll
    for (int i = 0; i < 2; i++)
#pragma unroll
        for (int n = 0; n < 8; n++)
#pragma unroll
            for (int q = 0; q < 4; q++) acc[i][n][q] = 0.f;
#pragma unroll
    for (int n = 0; n < 8; n++)
#pragma unroll
        for (int s = 0; s < 4; s++) {
            uint4 w = wb2[(s * 8 + n) * 32 + lane];
            uint32_t bh[2] = { w.x, w.y }, bl[2] = { w.z, w.w };
            mma16816(acc[0][n], Ahi[0][s], bh);
            mma16816(acc[1][n], Ahi[1][s], bh);
            mma16816(acc[0][n], Ahi[0][s], bl);
            mma16816(acc[1][n], Ahi[1][s], bl);
            mma16816(acc[0][n], Alo[0][s], bh);
            mma16816(acc[1][n], Alo[1][s], bh);
        }
    // epilogue 2
#pragma unroll
    for (int i = 0; i < 2; i++)
#pragma unroll
        for (int n = 0; n < 8; n++) {
            int c0 = 8 * n + 2 * tg;
            float h0 = tanha(acc[i][n][0] + bsm[64 + c0]);
            float h1 = tanha(acc[i][n][1] + bsm[64 + c0 + 1]);
            float h2 = tanha(acc[i][n][2] + bsm[64 + c0]);
            float h3 = tanha(acc[i][n][3] + bsm[64 + c0 + 1]);
            uint2 p01 = split2(h0, h1);
            uint2 p23 = split2(h2, h3);
            int j = n >> 1, b = n & 1;
            Ahi[i][j][2 * b]     = p01.x; Alo[i][j][2 * b]     = p01.y;
            Ahi[i][j][2 * b + 1] = p23.x; Alo[i][j][2 * b + 1] = p23.y;
        }
    // stage W3 frags into buffer 0 (all warps are past their layer-1 reads)
    {
        uint4* d = (uint4*)(smp + WB1_OFF);
#pragma unroll
        for (int i = 0; i < 3; i++) d[i * 128 + tid] = wsrc[2048 + i * 128 + tid];
    }
    __syncthreads();

    // ================= layer 3 (3 n-tiles = 24 cols >= OD) =================
#pragma unroll
    for (int i = 0; i < 2; i++)
#pragma unroll
        for (int n = 0; n < 3; n++)
#pragma unroll
            for (int q = 0; q < 4; q++) acc[i][n][q] = 0.f;
#pragma unroll
    for (int n = 0; n < 3; n++)
#pragma unroll
        for (int s = 0; s < 4; s++) {
            uint4 w = wb1[(s * 3 + n) * 32 + lane];
            uint32_t bh[2] = { w.x, w.y }, bl[2] = { w.z, w.w };
            mma16816(acc[0][n], Ahi[0][s], bh);
            mma16816(acc[1][n], Ahi[1][s], bh);
            mma16816(acc[0][n], Ahi[0][s], bl);
            mma16816(acc[1][n], Ahi[1][s], bl);
            mma16816(acc[0][n], Alo[0][s], bh);
            mma16816(acc[1][n], Alo[1][s], bh);
        }
    // write spline params to smem, stride 25 (conflict-free)
#pragma unroll
    for (int i = 0; i < 2; i++)
#pragma unroll
        for (int n = 0; n < 3; n++) {
            int c0 = 8 * n + 2 * tg;
            int r0 = mbase + 16 * i + g;
            if (c0 < OD)     psm[r0 * 25 + c0]           = acc[i][n][0] + bsm[128 + c0];
            if (c0 + 1 < OD) psm[r0 * 25 + c0 + 1]       = acc[i][n][1] + bsm[128 + c0 + 1];
            if (c0 < OD)     psm[(r0 + 8) * 25 + c0]     = acc[i][n][2] + bsm[128 + c0];
            if (c0 + 1 < OD) psm[(r0 + 8) * 25 + c0 + 1] = acc[i][n][3] + bsm[128 + c0 + 1];
        }
    __syncthreads();

    // ---- spline: one thread per batch row ----
    float zo, ldo;
    rqs23(xv, &psm[tid * 25], &zo, &ldo);
    z[(size_t)(m0 + tid) * DIMS + (l + 1)] = zo;
    g_ld[(size_t)(m0 + tid) * DIMS + (l + 1)] = ldo;
}

__global__ void __launch_bounds__(128, 3) nsf_main(
    const float* __restrict__ x,
    const float* __restrict__ b1, const float* __restrict__ b2,
    const float* __restrict__ b3, float* __restrict__ z) {
    extern __shared__ unsigned char smp[];
    int l = blockIdx.y;
    switch (l >> 4) {
        case 0:  run_main<1>(smp, l, x, b1, b2, b3, z); break;
        case 1:  run_main<2>(smp, l, x, b1, b2, b3, z); break;
        case 2:  run_main<3>(smp, l, x, b1, b2, b3, z); break;
        default: run_main<4>(smp, l, x, b1, b2, b3, z); break;
    }
}

// ---------------------------------------------------------------------------
// dim 0: spline tables are batch-invariant -> build once per block
// ---------------------------------------------------------------------------
__global__ void __launch_bounds__(128) nsf_dim0(const float* __restrict__ x,
                                                const float* __restrict__ ip,
                                                float* __restrict__ z) {
    __shared__ float cw[9], ch[9], der[9];
    if (threadIdx.x == 0) {
        float p[23];
#pragma unroll
        for (int i = 0; i < 23; i++) p[i] = ip[i];
        rqs_tables(p, cw, ch, der);
    }
    __syncthreads();
    int b = blockIdx.x * 128 + threadIdx.x;
    float zo, ldo;
    rqs_eval(x[(size_t)b * DIMS], cw, ch, der, &zo, &ldo);
    z[(size_t)b * DIMS] = zo;
    g_ld[(size_t)b * DIMS] = ldo;
}

// sum logdet over dims; [b][d] layout -> 16 coalesced LDG.128 per thread
__global__ void __launch_bounds__(128) nsf_reduce(float* __restrict__ ldo) {
    int b = blockIdx.x * 128 + threadIdx.x;
    const float4* r = (const float4*)(g_ld + (size_t)b * DIMS);
    float s = 0.f;
#pragma unroll
    for (int i = 0; i < 16; i++) {
        float4 v = r[i];
        s += v.x; s += v.y; s += v.z; s += v.w;
    }
    ldo[b] = s;
}

// ---------------------------------------------------------------------------
extern "C" void kernel_launch(void* const* d_in, const int* in_sizes, int n_in,
                              void* d_out, int out_size) {
    const float* x  = (const float*)d_in[0];
    const float* ip = (const float*)d_in[1];
    const float* W1 = (const float*)d_in[2];
    const float* b1 = (const float*)d_in[3];
    const float* W2 = (const float*)d_in[4];
    const float* b2 = (const float*)d_in[5];
    const float* W3 = (const float*)d_in[6];
    const float* b3 = (const float*)d_in[7];

    float* z   = (float*)d_out;
    float* ldo = z + (size_t)BATCH * DIMS;

    cudaFuncSetAttribute(nsf_main, cudaFuncAttributeMaxDynamicSharedMemorySize, SMEM_BYTES);

    nsf_prep_w<<<LAYERS, 256>>>(W1, W2, W3);
    nsf_prep_x<<<BATCH * 32 / 256, 256>>>(x);
    nsf_dim0<<<BATCH / 128, 128>>>(x, ip, z);
    nsf_main<<<dim3(128, 63), 128, SMEM_BYTES>>>(x, b1, b2, b3, z);
    nsf_reduce<<<BATCH / 128, 128>>>(ldo);
}

// round 9
// speedup vs baseline: 2.9371x; 1.0528x over previous
#include <cuda_runtime.h>
#include <cuda_bf16.h>
#include <math.h>
#include <stdint.h>

#define BATCH 16384
#define DIMS  64
#define LAYERS 63
#define HID   64
#define OD    23
#define BTAIL 3.0f

// per-(batch,dim) logdet partials, [b][d] layout
__device__ float g_ld[BATCH * DIMS];
// fragment-ordered packed weights, per layer stride 38912 B:
//   W1 frags @0 (16384), W2 @16384 (16384), W3 @32768 (6144)
//   frag record = uint4 {hi0,hi1,lo0,lo1}
__device__ __align__(16) unsigned char g_w[(size_t)LAYERS * 38912];
// pre-split x: pair-packed planes, g_xpk[b*32+p] = {hi(2p,2p+1), lo(2p,2p+1)}
__device__ __align__(16) uint2 g_xpk[(size_t)BATCH * 32];

// dynamic smem layout (bytes)
#define WB1_OFF  0          // 16384 (W1 frags; later W3 frags)
#define WB2_OFF  16384      // 16384 (W2 frags)
#define PSM_OFF  32768      // 64 x 25 floats = 6400
#define BIAS_OFF 39168      // b1[64] b2[64] b3[23]
#define SMEM_BYTES 39808

// ---------------------------------------------------------------------------
// mma.sync m16n8k16 bf16
// ---------------------------------------------------------------------------
__device__ __forceinline__ void mma16816(float* c, const uint32_t* a, const uint32_t* b) {
    asm volatile(
        "mma.sync.aligned.m16n8k16.row.col.f32.bf16.bf16.f32 "
        "{%0,%1,%2,%3}, {%4,%5,%6,%7}, {%8,%9}, {%0,%1,%2,%3};"
        : "+f"(c[0]), "+f"(c[1]), "+f"(c[2]), "+f"(c[3])
        : "r"(a[0]), "r"(a[1]), "r"(a[2]), "r"(a[3]), "r"(b[0]), "r"(b[1]));
}

__device__ __forceinline__ uint2 split2(float f0, float f1) {
    __nv_bfloat162 h = __floats2bfloat162_rn(f0, f1);
    float r0 = f0 - __bfloat162float(h.x);
    float r1 = f1 - __bfloat162float(h.y);
    __nv_bfloat162 l = __floats2bfloat162_rn(r0, r1);
    uint2 o;
    o.x = *(uint32_t*)&h;
    o.y = *(uint32_t*)&l;
    return o;
}

__device__ __forceinline__ float tanha(float v) {
    float r;
    asm("tanh.approx.f32 %0, %1;" : "=f"(r) : "f"(v));
    return r;
}

// ---------------------------------------------------------------------------
// spline math
// ---------------------------------------------------------------------------
__device__ __forceinline__ float softplus_(float x) {
    return (x > 15.f) ? x : __logf(1.f + __expf(x));
}
__device__ __forceinline__ void softmax8(const float* in, float* out, float scale) {
    float m = in[0];
#pragma unroll
    for (int i = 1; i < 8; i++) m = fmaxf(m, in[i]);
    float e[8], s = 0.f;
#pragma unroll
    for (int i = 0; i < 8; i++) { e[i] = __expf(in[i] - m); s += e[i]; }
    float inv = scale / s;
#pragma unroll
    for (int i = 0; i < 8; i++) out[i] = e[i] * inv;
}

__device__ __forceinline__ void rqs_tables(const float* __restrict__ p,
                                           float* cw, float* ch, float* der) {
    float W[8], H[8], wi[8], he[8];
    softmax8(p,     W, 2.f * BTAIL);
    softmax8(p + 8, H, 2.f * BTAIL);
    softmax8(W, wi, 1.f);
    softmax8(H, he, 1.f);

    cw[0] = -BTAIL; ch[0] = -BTAIL;
    float aw = 0.f, ah = 0.f;
#pragma unroll
    for (int i = 0; i < 8; i++) {
        float wv = 1e-3f + (1.f - 8e-3f) * wi[i];
        float hv = 1e-3f + (1.f - 8e-3f) * he[i];
        aw += wv; ah += hv;
        cw[i + 1] = 2.f * BTAIL * aw - BTAIL;
        ch[i + 1] = 2.f * BTAIL * ah - BTAIL;
    }
    cw[8] = BTAIL; ch[8] = BTAIL;

    const float UDC = logf(expf(1.0f - 1e-3f) - 1.0f);
    float edge = 1e-3f + softplus_(UDC);
    der[0] = edge; der[8] = edge;
#pragma unroll
    for (int i = 0; i < 7; i++) der[i + 1] = 1e-3f + softplus_(softplus_(p[16 + i]));
}

__device__ __forceinline__ void rqs_eval(float xval, const float* __restrict__ cw,
                                         const float* __restrict__ ch,
                                         const float* __restrict__ der,
                                         float* zo, float* ldo) {
    bool inside = (xval >= -BTAIL) && (xval <= BTAIL);
    float x = fminf(fmaxf(xval, -BTAIL), BTAIL);

    int bin = 0;
#pragma unroll
    for (int i = 1; i < 8; i++) bin += (x >= cw[i]) ? 1 : 0;

    float icw = 0.f, iw = 1.f, ich = 0.f, ih = 1.f, dk = 1.f, dk1 = 1.f;
#pragma unroll
    for (int i = 0; i < 8; i++) {
        if (bin == i) {
            icw = cw[i];  iw = cw[i + 1] - cw[i];
            ich = ch[i];  ih = ch[i + 1] - ch[i];
            dk = der[i];  dk1 = der[i + 1];
        }
    }

    float delta = ih / iw;
    float th  = (x - icw) / iw;
    float t1  = th * (1.f - th);
    float numer = ih * (delta * th * th + dk * t1);
    float denom = delta + (dk + dk1 - 2.f * delta) * t1;
    float out = ich + numer / denom;
    float om = 1.f - th;
    float dnum = delta * delta * (dk1 * th * th + 2.f * delta * t1 + dk * om * om);
    float ld = __logf(dnum) - 2.f * __logf(denom);

    *zo  = inside ? out : xval;
    *ldo = inside ? ld  : 0.f;
}

__device__ __forceinline__ void rqs23(float xval, const float* __restrict__ p,
                                      float* zo, float* ldo) {
    float cw[9], ch[9], der[9];
    rqs_tables(p, cw, ch, der);
    rqs_eval(xval, cw, ch, der, zo, ldo);
}

// ---------------------------------------------------------------------------
// prep kernels
// ---------------------------------------------------------------------------
__global__ void __launch_bounds__(256) nsf_prep_w(const float* __restrict__ W1,
                                                  const float* __restrict__ W2,
                                                  const float* __restrict__ W3) {
    int l = blockIdx.x, tid = threadIdx.x;
    uint4* base = (uint4*)(g_w + (size_t)l * 38912);
    for (int f = tid; f < 1024; f += 256) {
        int s = f >> 8, n = (f >> 5) & 7, lane = f & 31;
        int g = lane >> 2, tg = lane & 3;
        int row = 8 * n + g, c0 = 16 * s + 2 * tg;
        const float* w = W1 + (size_t)l * 4096 + row * 64;
        uint2 a = split2(w[c0], w[c0 + 1]);
        uint2 b = split2(w[c0 + 8], w[c0 + 9]);
        base[f] = make_uint4(a.x, b.x, a.y, b.y);
        w = W2 + (size_t)l * 4096 + row * 64;
        a = split2(w[c0], w[c0 + 1]);
        b = split2(w[c0 + 8], w[c0 + 9]);
        base[1024 + f] = make_uint4(a.x, b.x, a.y, b.y);
    }
    for (int f = tid; f < 384; f += 256) {
        int sn = f >> 5, lane = f & 31;
        int s = sn / 3, n = sn % 3;
        int g = lane >> 2, tg = lane & 3;
        int row = 8 * n + g, c0 = 16 * s + 2 * tg;
        uint4 rec = make_uint4(0, 0, 0, 0);
        if (row < OD) {
            const float* w = W3 + (size_t)l * OD * 64 + row * 64;
            uint2 a = split2(w[c0], w[c0 + 1]);
            uint2 b = split2(w[c0 + 8], w[c0 + 9]);
            rec = make_uint4(a.x, b.x, a.y, b.y);
        }
        base[2048 + f] = rec;
    }
}

__global__ void __launch_bounds__(256) nsf_prep_x(const float* __restrict__ x) {
    int idx = blockIdx.x * 256 + threadIdx.x;   // b*32 + p
    int c = (idx & 31) * 2;
    const float* xr = x + (size_t)(idx >> 5) * DIMS;
    g_xpk[idx] = split2(xr[c], xr[c + 1]);
}

// ---------------------------------------------------------------------------
// main fused kernel: 64-row CTA, 4 warps x one m16 tile each
// ---------------------------------------------------------------------------
template <int NS>
__device__ __forceinline__ void run_main(unsigned char* smp, int l,
                                         const float* __restrict__ x,
                                         const float* __restrict__ b1,
                                         const float* __restrict__ b2,
                                         const float* __restrict__ b3,
                                         float* __restrict__ z) {
    float* psm = (float*)(smp + PSM_OFF);
    float* bsm = (float*)(smp + BIAS_OFF);
    const uint4* wb1 = (const uint4*)(smp + WB1_OFF);
    const uint4* wb2 = (const uint4*)(smp + WB2_OFF);

    const int tid = threadIdx.x;
    const int warp = tid >> 5, lane = tid & 31;
    const int g = lane >> 2, tg = lane & 3;
    const int m0 = blockIdx.x * 64;
    const int rb = 16 * warp + g;          // local row

    // ---- stage W1 live-chunk frags + biases ----
    const uint4* wsrc = (const uint4*)(g_w + (size_t)l * 38912);
    {
        uint4* d = (uint4*)(smp + WB1_OFF);
#pragma unroll
        for (int i = 0; i < NS * 2; i++) d[i * 128 + tid] = wsrc[i * 128 + tid];
    }
    if (tid < 64) { bsm[tid] = b1[l * 64 + tid]; bsm[64 + tid] = b2[l * 64 + tid]; }
    if (tid < OD)  bsm[128 + tid] = b3[l * OD + tid];
    float xv = (tid < 64) ? x[(size_t)(m0 + tid) * DIMS + (l + 1)] : 0.f;

    // ---- layer-1 A fragments straight from packed global x ----
    uint32_t Ahi[4][4], Alo[4][4];
    uint32_t mA, mB;
    {
        int cA = 16 * (NS - 1) + 2 * tg, cB = cA + 8;
        mA = (cA + 1 <= l) ? 0xFFFFFFFFu : ((cA <= l) ? 0x0000FFFFu : 0u);
        mB = (cB + 1 <= l) ? 0xFFFFFFFFu : ((cB <= l) ? 0x0000FFFFu : 0u);
    }
    {
        int r0 = m0 + rb;
#pragma unroll
        for (int s = 0; s < NS; s++) {
            int p0 = 8 * s + tg;
            uint2 v00 = g_xpk[(size_t)r0 * 32 + p0];
            uint2 v01 = g_xpk[(size_t)(r0 + 8) * 32 + p0];
            uint2 v10 = g_xpk[(size_t)r0 * 32 + p0 + 4];
            uint2 v11 = g_xpk[(size_t)(r0 + 8) * 32 + p0 + 4];
            if (s == NS - 1) {
                v00.x &= mA; v00.y &= mA; v01.x &= mA; v01.y &= mA;
                v10.x &= mB; v10.y &= mB; v11.x &= mB; v11.y &= mB;
            }
            Ahi[s][0] = v00.x; Alo[s][0] = v00.y;
            Ahi[s][1] = v01.x; Alo[s][1] = v01.y;
            Ahi[s][2] = v10.x; Alo[s][2] = v10.y;
            Ahi[s][3] = v11.x; Alo[s][3] = v11.y;
        }
    }
    __syncthreads();

    float acc[8][4];

    // ================= layer 1 (K = 16*NS) =================
#pragma unroll
    for (int n = 0; n < 8; n++)
#pragma unroll
        for (int q = 0; q < 4; q++) acc[n][q] = 0.f;
#pragma unroll
    for (int n = 0; n < 8; n++)
#pragma unroll
        for (int s = 0; s < NS; s++) {
            uint4 w = wb1[(s * 8 + n) * 32 + lane];
            uint32_t bh[2] = { w.x, w.y }, bl[2] = { w.z, w.w };
            mma16816(acc[n], Ahi[s], bh);
            mma16816(acc[n], Ahi[s], bl);
            mma16816(acc[n], Alo[s], bh);
        }
    // epilogue 1
#pragma unroll
    for (int n = 0; n < 8; n++) {
        int c0 = 8 * n + 2 * tg;
        float h0 = tanha(acc[n][0] + bsm[c0]);
        float h1 = tanha(acc[n][1] + bsm[c0 + 1]);
        float h2 = tanha(acc[n][2] + bsm[c0]);
        float h3 = tanha(acc[n][3] + bsm[c0 + 1]);
        uint2 p01 = split2(h0, h1);
        uint2 p23 = split2(h2, h3);
        int j = n >> 1, b = n & 1;
        Ahi[j][2 * b]     = p01.x; Alo[j][2 * b]     = p01.y;
        Ahi[j][2 * b + 1] = p23.x; Alo[j][2 * b + 1] = p23.y;
    }
    // stage W2 frags
    {
        uint4* d = (uint4*)(smp + WB2_OFF);
#pragma unroll
        for (int i = 0; i < 8; i++) d[i * 128 + tid] = wsrc[1024 + i * 128 + tid];
    }
    __syncthreads();

    // ================= layer 2 =================
#pragma unroll
    for (int n = 0; n < 8; n++)
#pragma unroll
        for (int q = 0; q < 4; q++) acc[n][q] = 0.f;
#pragma unroll
    for (int n = 0; n < 8; n++)
#pragma unroll
        for (int s = 0; s < 4; s++) {
            uint4 w = wb2[(s * 8 + n) * 32 + lane];
            uint32_t bh[2] = { w.x, w.y }, bl[2] = { w.z, w.w };
            mma16816(acc[n], Ahi[s], bh);
            mma16816(acc[n], Ahi[s], bl);
            mma16816(acc[n], Alo[s], bh);
        }
    // epilogue 2
#pragma unroll
    for (int n = 0; n < 8; n++) {
        int c0 = 8 * n + 2 * tg;
        float h0 = tanha(acc[n][0] + bsm[64 + c0]);
        float h1 = tanha(acc[n][1] + bsm[64 + c0 + 1]);
        float h2 = tanha(acc[n][2] + bsm[64 + c0]);
        float h3 = tanha(acc[n][3] + bsm[64 + c0 + 1]);
        uint2 p01 = split2(h0, h1);
        uint2 p23 = split2(h2, h3);
        int j = n >> 1, b = n & 1;
        Ahi[j][2 * b]     = p01.x; Alo[j][2 * b]     = p01.y;
        Ahi[j][2 * b + 1] = p23.x; Alo[j][2 * b + 1] = p23.y;
    }
    // stage W3 frags into buffer 0
    {
        uint4* d = (uint4*)(smp + WB1_OFF);
#pragma unroll
        for (int i = 0; i < 3; i++) d[i * 128 + tid] = wsrc[2048 + i * 128 + tid];
    }
    __syncthreads();

    // ================= layer 3 (3 n-tiles) =================
#pragma unroll
    for (int n = 0; n < 3; n++)
#pragma unroll
        for (int q = 0; q < 4; q++) acc[n][q] = 0.f;
#pragma unroll
    for (int n = 0; n < 3; n++)
#pragma unroll
        for (int s = 0; s < 4; s++) {
            uint4 w = wb1[(s * 3 + n) * 32 + lane];
            uint32_t bh[2] = { w.x, w.y }, bl[2] = { w.z, w.w };
            mma16816(acc[n], Ahi[s], bh);
            mma16816(acc[n], Ahi[s], bl);
            mma16816(acc[n], Alo[s], bh);
        }
    // write spline params (stride 25)
#pragma unroll
    for (int n = 0; n < 3; n++) {
        int c0 = 8 * n + 2 * tg;
        if (c0 < OD)     psm[rb * 25 + c0]           = acc[n][0] + bsm[128 + c0];
        if (c0 + 1 < OD) psm[rb * 25 + c0 + 1]       = acc[n][1] + bsm[128 + c0 + 1];
        if (c0 < OD)     psm[(rb + 8) * 25 + c0]     = acc[n][2] + bsm[128 + c0];
        if (c0 + 1 < OD) psm[(rb + 8) * 25 + c0 + 1] = acc[n][3] + bsm[128 + c0 + 1];
    }
    __syncthreads();

    // ---- spline: one thread per batch row (64 rows) ----
    if (tid < 64) {
        float zo, ldo;
        rqs23(xv, &psm[tid * 25], &zo, &ldo);
        z[(size_t)(m0 + tid) * DIMS + (l + 1)] = zo;
        g_ld[(size_t)(m0 + tid) * DIMS + (l + 1)] = ldo;
    }
}

__global__ void __launch_bounds__(128, 4) nsf_main(
    const float* __restrict__ x,
    const float* __restrict__ b1, const float* __restrict__ b2,
    const float* __restrict__ b3, float* __restrict__ z) {
    extern __shared__ unsigned char smp[];
    int l = blockIdx.y;
    switch (l >> 4) {
        case 0:  run_main<1>(smp, l, x, b1, b2, b3, z); break;
        case 1:  run_main<2>(smp, l, x, b1, b2, b3, z); break;
        case 2:  run_main<3>(smp, l, x, b1, b2, b3, z); break;
        default: run_main<4>(smp, l, x, b1, b2, b3, z); break;
    }
}

// ---------------------------------------------------------------------------
// tail: dim-0 spline (shared tables) + logdet reduce, one kernel
// ---------------------------------------------------------------------------
__global__ void __launch_bounds__(128) nsf_tail(const float* __restrict__ x,
                                                const float* __restrict__ ip,
                                                float* __restrict__ z,
                                                float* __restrict__ ldo) {
    __shared__ float cw[9], ch[9], der[9];
    if (threadIdx.x == 0) {
        float p[23];
#pragma unroll
        for (int i = 0; i < 23; i++) p[i] = ip[i];
        rqs_tables(p, cw, ch, der);
    }
    __syncthreads();
    int b = blockIdx.x * 128 + threadIdx.x;
    float zo, ld0;
    rqs_eval(x[(size_t)b * DIMS], cw, ch, der, &zo, &ld0);
    z[(size_t)b * DIMS] = zo;

    const float4* r = (const float4*)(g_ld + (size_t)b * DIMS);
    float s = ld0;
    {
        float4 v = r[0];              // v.x is dim-0 slot (unwritten) -> skip
        s += v.y + v.z + v.w;
    }
#pragma unroll
    for (int i = 1; i < 16; i++) {
        float4 v = r[i];
        s += v.x + v.y + v.z + v.w;
    }
    ldo[b] = s;
}

// ---------------------------------------------------------------------------
extern "C" void kernel_launch(void* const* d_in, const int* in_sizes, int n_in,
                              void* d_out, int out_size) {
    const float* x  = (const float*)d_in[0];
    const float* ip = (const float*)d_in[1];
    const float* W1 = (const float*)d_in[2];
    const float* b1 = (const float*)d_in[3];
    const float* W2 = (const float*)d_in[4];
    const float* b2 = (const float*)d_in[5];
    const float* W3 = (const float*)d_in[6];
    const float* b3 = (const float*)d_in[7];

    float* z   = (float*)d_out;
    float* ldo = z + (size_t)BATCH * DIMS;

    cudaFuncSetAttribute(nsf_main, cudaFuncAttributeMaxDynamicSharedMemorySize, SMEM_BYTES);

    nsf_prep_w<<<LAYERS, 256>>>(W1, W2, W3);
    nsf_prep_x<<<BATCH * 32 / 256, 256>>>(x);
    nsf_main<<<dim3(256, 63), 128, SMEM_BYTES>>>(x, b1, b2, b3, z);
    nsf_tail<<<BATCH / 128, 128>>>(x, ip, z, ldo);
}

// round 10
// speedup vs baseline: 3.2848x; 1.1184x over previous
#include <cuda_runtime.h>
#include <cuda_bf16.h>
#include <math.h>
#include <stdint.h>

#define BATCH 16384
#define DIMS  64
#define LAYERS 63
#define HID   64
#define OD    23
#define BTAIL 3.0f

// per-(batch,dim) logdet partials, [b][d] layout
__device__ float g_ld[BATCH * DIMS];
// fragment-ordered packed weights, per layer stride 38912 B:
//   W1 frags @0 (16384), W2 @16384 (16384), W3 @32768 (6144)
//   frag record = uint4 {hi0,hi1,lo0,lo1}
__device__ __align__(16) unsigned char g_w[(size_t)LAYERS * 38912];
// pre-split x: pair-packed planes, g_xpk[b*32+p] = {hi(2p,2p+1), lo(2p,2p+1)}
__device__ __align__(16) uint2 g_xpk[(size_t)BATCH * 32];

// dynamic smem layout (bytes)
#define WB1_OFF  0          // 16384
#define WB2_OFF  16384      // 16384
#define WB3_OFF  32768      // 6144
#define PSM_OFF  38912      // 64 x 25 floats = 6400
#define BIAS_OFF 45312      // b1[64] b2[64] b3pad[32] floats = 640
#define SMEM_BYTES 45952

// ---------------------------------------------------------------------------
// PTX helpers
// ---------------------------------------------------------------------------
__device__ __forceinline__ void mma16816(float* c, const uint32_t* a, const uint32_t* b) {
    asm volatile(
        "mma.sync.aligned.m16n8k16.row.col.f32.bf16.bf16.f32 "
        "{%0,%1,%2,%3}, {%4,%5,%6,%7}, {%8,%9}, {%0,%1,%2,%3};"
        : "+f"(c[0]), "+f"(c[1]), "+f"(c[2]), "+f"(c[3])
        : "r"(a[0]), "r"(a[1]), "r"(a[2]), "r"(a[3]), "r"(b[0]), "r"(b[1]));
}

__device__ __forceinline__ uint32_t smem_u32(const void* p) {
    uint32_t a;
    asm("{ .reg .u64 t; cvta.to.shared.u64 t, %1; cvt.u32.u64 %0, t; }" : "=r"(a) : "l"(p));
    return a;
}
__device__ __forceinline__ void cp_async16(uint32_t dst, const void* src) {
    asm volatile("cp.async.cg.shared.global [%0], [%1], 16;" :: "r"(dst), "l"(src));
}
#define CP_COMMIT() asm volatile("cp.async.commit_group;" ::: "memory")
#define CP_WAIT(n)  asm volatile("cp.async.wait_group %0;" :: "n"(n) : "memory")

__device__ __forceinline__ uint2 split2(float f0, float f1) {
    __nv_bfloat162 h = __floats2bfloat162_rn(f0, f1);
    float r0 = f0 - __bfloat162float(h.x);
    float r1 = f1 - __bfloat162float(h.y);
    __nv_bfloat162 l = __floats2bfloat162_rn(r0, r1);
    uint2 o;
    o.x = *(uint32_t*)&h;
    o.y = *(uint32_t*)&l;
    return o;
}

__device__ __forceinline__ float tanha(float v) {
    float r;
    asm("tanh.approx.f32 %0, %1;" : "=f"(r) : "f"(v));
    return r;
}

// ---------------------------------------------------------------------------
// spline math
// ---------------------------------------------------------------------------
__device__ __forceinline__ float softplus_(float x) {
    return (x > 15.f) ? x : __logf(1.f + __expf(x));
}
__device__ __forceinline__ void softmax8(const float* in, float* out, float scale) {
    float m = in[0];
#pragma unroll
    for (int i = 1; i < 8; i++) m = fmaxf(m, in[i]);
    float e[8], s = 0.f;
#pragma unroll
    for (int i = 0; i < 8; i++) { e[i] = __expf(in[i] - m); s += e[i]; }
    float inv = scale / s;
#pragma unroll
    for (int i = 0; i < 8; i++) out[i] = e[i] * inv;
}

__device__ __forceinline__ void rqs_tables(const float* __restrict__ p,
                                           float* cw, float* ch, float* der) {
    float W[8], H[8], wi[8], he[8];
    softmax8(p,     W, 2.f * BTAIL);
    softmax8(p + 8, H, 2.f * BTAIL);
    softmax8(W, wi, 1.f);
    softmax8(H, he, 1.f);

    cw[0] = -BTAIL; ch[0] = -BTAIL;
    float aw = 0.f, ah = 0.f;
#pragma unroll
    for (int i = 0; i < 8; i++) {
        float wv = 1e-3f + (1.f - 8e-3f) * wi[i];
        float hv = 1e-3f + (1.f - 8e-3f) * he[i];
        aw += wv; ah += hv;
        cw[i + 1] = 2.f * BTAIL * aw - BTAIL;
        ch[i + 1] = 2.f * BTAIL * ah - BTAIL;
    }
    cw[8] = BTAIL; ch[8] = BTAIL;

    const float UDC = logf(expf(1.0f - 1e-3f) - 1.0f);
    float edge = 1e-3f + softplus_(UDC);
    der[0] = edge; der[8] = edge;
#pragma unroll
    for (int i = 0; i < 7; i++) der[i + 1] = 1e-3f + softplus_(softplus_(p[16 + i]));
}

__device__ __forceinline__ void rqs_eval(float xval, const float* __restrict__ cw,
                                         const float* __restrict__ ch,
                                         const float* __restrict__ der,
                                         float* zo, float* ldo) {
    bool inside = (xval >= -BTAIL) && (xval <= BTAIL);
    float x = fminf(fmaxf(xval, -BTAIL), BTAIL);

    int bin = 0;
#pragma unroll
    for (int i = 1; i < 8; i++) bin += (x >= cw[i]) ? 1 : 0;

    float icw = 0.f, iw = 1.f, ich = 0.f, ih = 1.f, dk = 1.f, dk1 = 1.f;
#pragma unroll
    for (int i = 0; i < 8; i++) {
        if (bin == i) {
            icw = cw[i];  iw = cw[i + 1] - cw[i];
            ich = ch[i];  ih = ch[i + 1] - ch[i];
            dk = der[i];  dk1 = der[i + 1];
        }
    }

    float delta = ih / iw;
    float th  = (x - icw) / iw;
    float t1  = th * (1.f - th);
    float numer = ih * (delta * th * th + dk * t1);
    float denom = delta + (dk + dk1 - 2.f * delta) * t1;
    float out = ich + numer / denom;
    float om = 1.f - th;
    float dnum = delta * delta * (dk1 * th * th + 2.f * delta * t1 + dk * om * om);
    float ld = __logf(dnum) - 2.f * __logf(denom);

    *zo  = inside ? out : xval;
    *ldo = inside ? ld  : 0.f;
}

__device__ __forceinline__ void rqs23(float xval, const float* __restrict__ p,
                                      float* zo, float* ldo) {
    float cw[9], ch[9], der[9];
    rqs_tables(p, cw, ch, der);
    rqs_eval(xval, cw, ch, der, zo, ldo);
}

// ---------------------------------------------------------------------------
// prep kernels
// ---------------------------------------------------------------------------
__global__ void __launch_bounds__(256) nsf_prep_w(const float* __restrict__ W1,
                                                  const float* __restrict__ W2,
                                                  const float* __restrict__ W3) {
    int l = blockIdx.x, tid = threadIdx.x;
    uint4* base = (uint4*)(g_w + (size_t)l * 38912);
    for (int f = tid; f < 1024; f += 256) {
        int s = f >> 8, n = (f >> 5) & 7, lane = f & 31;
        int g = lane >> 2, tg = lane & 3;
        int row = 8 * n + g, c0 = 16 * s + 2 * tg;
        const float* w = W1 + (size_t)l * 4096 + row * 64;
        uint2 a = split2(w[c0], w[c0 + 1]);
        uint2 b = split2(w[c0 + 8], w[c0 + 9]);
        base[f] = make_uint4(a.x, b.x, a.y, b.y);
        w = W2 + (size_t)l * 4096 + row * 64;
        a = split2(w[c0], w[c0 + 1]);
        b = split2(w[c0 + 8], w[c0 + 9]);
        base[1024 + f] = make_uint4(a.x, b.x, a.y, b.y);
    }
    for (int f = tid; f < 384; f += 256) {
        int sn = f >> 5, lane = f & 31;
        int s = sn / 3, n = sn % 3;
        int g = lane >> 2, tg = lane & 3;
        int row = 8 * n + g, c0 = 16 * s + 2 * tg;
        uint4 rec = make_uint4(0, 0, 0, 0);
        if (row < OD) {
            const float* w = W3 + (size_t)l * OD * 64 + row * 64;
            uint2 a = split2(w[c0], w[c0 + 1]);
            uint2 b = split2(w[c0 + 8], w[c0 + 9]);
            rec = make_uint4(a.x, b.x, a.y, b.y);
        }
        base[2048 + f] = rec;
    }
}

__global__ void __launch_bounds__(256) nsf_prep_x(const float* __restrict__ x) {
    int idx = blockIdx.x * 256 + threadIdx.x;   // b*32 + p
    int c = (idx & 31) * 2;
    const float* xr = x + (size_t)(idx >> 5) * DIMS;
    g_xpk[idx] = split2(xr[c], xr[c + 1]);
}

// ---------------------------------------------------------------------------
// main fused kernel: 64-row CTA, 4 warps x one m16 tile each,
// cp.async triple-buffer weight prefetch
// ---------------------------------------------------------------------------
template <int NS>
__device__ __forceinline__ void run_main(unsigned char* smp, int l,
                                         const float* __restrict__ x,
                                         const float* __restrict__ b1,
                                         const float* __restrict__ b2,
                                         const float* __restrict__ b3,
                                         float* __restrict__ z) {
    float* psm = (float*)(smp + PSM_OFF);
    float* bsm = (float*)(smp + BIAS_OFF);
    const uint4* wb1 = (const uint4*)(smp + WB1_OFF);
    const uint4* wb2 = (const uint4*)(smp + WB2_OFF);
    const uint4* wb3 = (const uint4*)(smp + WB3_OFF);

    const int tid = threadIdx.x;
    const int warp = tid >> 5, lane = tid & 31;
    const int g = lane >> 2, tg = lane & 3;
    const int m0 = blockIdx.x * 64;
    const int rb = 16 * warp + g;          // local row
    const uint32_t sbase = smem_u32(smp);

    // ---- prefetch all three weight buffers via cp.async (3 commit groups) ----
    const uint4* wsrc = (const uint4*)(g_w + (size_t)l * 38912);
#pragma unroll
    for (int i = 0; i < NS * 2; i++)
        cp_async16(sbase + WB1_OFF + (i * 128 + tid) * 16, wsrc + i * 128 + tid);
    CP_COMMIT();
#pragma unroll
    for (int i = 0; i < 8; i++)
        cp_async16(sbase + WB2_OFF + (i * 128 + tid) * 16, wsrc + 1024 + i * 128 + tid);
    CP_COMMIT();
#pragma unroll
    for (int i = 0; i < 3; i++)
        cp_async16(sbase + WB3_OFF + (i * 128 + tid) * 16, wsrc + 2048 + i * 128 + tid);
    CP_COMMIT();

    // ---- biases (normal LDG/STS, hidden behind frag-build LDGs) ----
    if (tid < 64) { bsm[tid] = b1[l * 64 + tid]; bsm[64 + tid] = b2[l * 64 + tid]; }
    if (tid >= 96) bsm[128 + tid - 96] = (tid - 96 < OD) ? b3[l * OD + tid - 96] : 0.f;
    float xv = (tid < 64) ? x[(size_t)(m0 + tid) * DIMS + (l + 1)] : 0.f;

    // ---- layer-1 A fragments straight from packed global x ----
    uint32_t Ahi[4][4], Alo[4][4];
    uint32_t mA, mB;
    {
        int cA = 16 * (NS - 1) + 2 * tg, cB = cA + 8;
        mA = (cA + 1 <= l) ? 0xFFFFFFFFu : ((cA <= l) ? 0x0000FFFFu : 0u);
        mB = (cB + 1 <= l) ? 0xFFFFFFFFu : ((cB <= l) ? 0x0000FFFFu : 0u);
    }
    {
        int r0 = m0 + rb;
#pragma unroll
        for (int s = 0; s < NS; s++) {
            int p0 = 8 * s + tg;
            uint2 v00 = g_xpk[(size_t)r0 * 32 + p0];
            uint2 v01 = g_xpk[(size_t)(r0 + 8) * 32 + p0];
            uint2 v10 = g_xpk[(size_t)r0 * 32 + p0 + 4];
            uint2 v11 = g_xpk[(size_t)(r0 + 8) * 32 + p0 + 4];
            if (s == NS - 1) {
                v00.x &= mA; v00.y &= mA; v01.x &= mA; v01.y &= mA;
                v10.x &= mB; v10.y &= mB; v11.x &= mB; v11.y &= mB;
            }
            Ahi[s][0] = v00.x; Alo[s][0] = v00.y;
            Ahi[s][1] = v01.x; Alo[s][1] = v01.y;
            Ahi[s][2] = v10.x; Alo[s][2] = v10.y;
            Ahi[s][3] = v11.x; Alo[s][3] = v11.y;
        }
    }
    CP_WAIT(2);           // W1 landed
    __syncthreads();

    float acc[8][4];

    // ================= layer 1 (K = 16*NS), bias in acc init =================
#pragma unroll
    for (int n = 0; n < 8; n++) {
        int c0 = 8 * n + 2 * tg;
        acc[n][0] = bsm[c0]; acc[n][1] = bsm[c0 + 1];
        acc[n][2] = bsm[c0]; acc[n][3] = bsm[c0 + 1];
    }
#pragma unroll
    for (int n = 0; n < 8; n++)
#pragma unroll
        for (int s = 0; s < NS; s++) {
            uint4 w = wb1[(s * 8 + n) * 32 + lane];
            uint32_t bh[2] = { w.x, w.y }, bl[2] = { w.z, w.w };
            mma16816(acc[n], Ahi[s], bh);
            mma16816(acc[n], Ahi[s], bl);
            mma16816(acc[n], Alo[s], bh);
        }
    // epilogue 1: tanh + split -> next A frags (registers only)
#pragma unroll
    for (int n = 0; n < 8; n++) {
        float h0 = tanha(acc[n][0]);
        float h1 = tanha(acc[n][1]);
        float h2 = tanha(acc[n][2]);
        float h3 = tanha(acc[n][3]);
        uint2 p01 = split2(h0, h1);
        uint2 p23 = split2(h2, h3);
        int j = n >> 1, b = n & 1;
        Ahi[j][2 * b]     = p01.x; Alo[j][2 * b]     = p01.y;
        Ahi[j][2 * b + 1] = p23.x; Alo[j][2 * b + 1] = p23.y;
    }
    CP_WAIT(1);           // W2 landed (flew in during layer 1)
    __syncthreads();

    // ================= layer 2 =================
#pragma unroll
    for (int n = 0; n < 8; n++) {
        int c0 = 8 * n + 2 * tg;
        acc[n][0] = bsm[64 + c0]; acc[n][1] = bsm[64 + c0 + 1];
        acc[n][2] = bsm[64 + c0]; acc[n][3] = bsm[64 + c0 + 1];
    }
#pragma unroll
    for (int n = 0; n < 8; n++)
#pragma unroll
        for (int s = 0; s < 4; s++) {
            uint4 w = wb2[(s * 8 + n) * 32 + lane];
            uint32_t bh[2] = { w.x, w.y }, bl[2] = { w.z, w.w };
            mma16816(acc[n], Ahi[s], bh);
            mma16816(acc[n], Ahi[s], bl);
            mma16816(acc[n], Alo[s], bh);
        }
    // epilogue 2
#pragma unroll
    for (int n = 0; n < 8; n++) {
        float h0 = tanha(acc[n][0]);
        float h1 = tanha(acc[n][1]);
        float h2 = tanha(acc[n][2]);
        float h3 = tanha(acc[n][3]);
        uint2 p01 = split2(h0, h1);
        uint2 p23 = split2(h2, h3);
        int j = n >> 1, b = n & 1;
        Ahi[j][2 * b]     = p01.x; Alo[j][2 * b]     = p01.y;
        Ahi[j][2 * b + 1] = p23.x; Alo[j][2 * b + 1] = p23.y;
    }
    CP_WAIT(0);           // W3 landed
    __syncthreads();

    // ================= layer 3 (3 n-tiles), bias in acc init =================
#pragma unroll
    for (int n = 0; n < 3; n++) {
        int c0 = 8 * n + 2 * tg;
        acc[n][0] = bsm[128 + c0]; acc[n][1] = bsm[128 + c0 + 1];
        acc[n][2] = bsm[128 + c0]; acc[n][3] = bsm[128 + c0 + 1];
    }
#pragma unroll
    for (int n = 0; n < 3; n++)
#pragma unroll
        for (int s = 0; s < 4; s++) {
            uint4 w = wb3[(s * 3 + n) * 32 + lane];
            uint32_t bh[2] = { w.x, w.y }, bl[2] = { w.z, w.w };
            mma16816(acc[n], Ahi[s], bh);
            mma16816(acc[n], Ahi[s], bl);
            mma16816(acc[n], Alo[s], bh);
        }
    // write spline params (stride 25)
#pragma unroll
    for (int n = 0; n < 3; n++) {
        int c0 = 8 * n + 2 * tg;
        if (c0 < OD)     psm[rb * 25 + c0]           = acc[n][0];
        if (c0 + 1 < OD) psm[rb * 25 + c0 + 1]       = acc[n][1];
        if (c0 < OD)     psm[(rb + 8) * 25 + c0]     = acc[n][2];
        if (c0 + 1 < OD) psm[(rb + 8) * 25 + c0 + 1] = acc[n][3];
    }
    __syncthreads();

    // ---- spline: one thread per batch row (64 rows) ----
    if (tid < 64) {
        float zo, ldo;
        rqs23(xv, &psm[tid * 25], &zo, &ldo);
        z[(size_t)(m0 + tid) * DIMS + (l + 1)] = zo;
        g_ld[(size_t)(m0 + tid) * DIMS + (l + 1)] = ldo;
    }
}

__global__ void __launch_bounds__(128, 4) nsf_main(
    const float* __restrict__ x,
    const float* __restrict__ b1, const float* __restrict__ b2,
    const float* __restrict__ b3, float* __restrict__ z) {
    extern __shared__ unsigned char smp[];
    int l = blockIdx.y;
    switch (l >> 4) {
        case 0:  run_main<1>(smp, l, x, b1, b2, b3, z); break;
        case 1:  run_main<2>(smp, l, x, b1, b2, b3, z); break;
        case 2:  run_main<3>(smp, l, x, b1, b2, b3, z); break;
        default: run_main<4>(smp, l, x, b1, b2, b3, z); break;
    }
}

// ---------------------------------------------------------------------------
// tail: dim-0 spline (shared tables) + logdet reduce, one kernel
// ---------------------------------------------------------------------------
__global__ void __launch_bounds__(128) nsf_tail(const float* __restrict__ x,
                                                const float* __restrict__ ip,
                                                float* __restrict__ z,
                                                float* __restrict__ ldo) {
    __shared__ float cw[9], ch[9], der[9];
    if (threadIdx.x == 0) {
        float p[23];
#pragma unroll
        for (int i = 0; i < 23; i++) p[i] = ip[i];
        rqs_tables(p, cw, ch, der);
    }
    __syncthreads();
    int b = blockIdx.x * 128 + threadIdx.x;
    float zo, ld0;
    rqs_eval(x[(size_t)b * DIMS], cw, ch, der, &zo, &ld0);
    z[(size_t)b * DIMS] = zo;

    const float4* r = (const float4*)(g_ld + (size_t)b * DIMS);
    float s = ld0;
    {
        float4 v = r[0];              // v.x is dim-0 slot (unwritten) -> skip
        s += v.y + v.z + v.w;
    }
#pragma unroll
    for (int i = 1; i < 16; i++) {
        float4 v = r[i];
        s += v.x + v.y + v.z + v.w;
    }
    ldo[b] = s;
}

// ---------------------------------------------------------------------------
extern "C" void kernel_launch(void* const* d_in, const int* in_sizes, int n_in,
                              void* d_out, int out_size) {
    const float* x  = (const float*)d_in[0];
    const float* ip = (const float*)d_in[1];
    const float* W1 = (const float*)d_in[2];
    const float* b1 = (const float*)d_in[3];
    const float* W2 = (const float*)d_in[4];
    const float* b2 = (const float*)d_in[5];
    const float* W3 = (const float*)d_in[6];
    const float* b3 = (const float*)d_in[7];

    float* z   = (float*)d_out;
    float* ldo = z + (size_t)BATCH * DIMS;

    cudaFuncSetAttribute(nsf_main, cudaFuncAttributeMaxDynamicSharedMemorySize, SMEM_BYTES);

    nsf_prep_w<<<LAYERS, 256>>>(W1, W2, W3);
    nsf_prep_x<<<BATCH * 32 / 256, 256>>>(x);
    nsf_main<<<dim3(256, 63), 128, SMEM_BYTES>>>(x, b1, b2, b3, z);
    nsf_tail<<<BATCH / 128, 128>>>(x, ip, z, ldo);
}

// round 11
// speedup vs baseline: 3.4465x; 1.0492x over previous
#include <cuda_runtime.h>
#include <cuda_bf16.h>
#include <math.h>
#include <stdint.h>

#define BATCH 16384
#define DIMS  64
#define LAYERS 63
#define HID   64
#define OD    23
#define BTAIL 3.0f

// per-(batch,dim) logdet partials, [b][d] layout
__device__ float g_ld[BATCH * DIMS];
// fragment-ordered packed weights, per layer stride 38912 B:
//   W1 frags @0 (16384), W2 @16384 (16384), W3 @32768 (6144)
//   frag record = uint4 {hi0,hi1,lo0,lo1}
__device__ __align__(16) unsigned char g_w[(size_t)LAYERS * 38912];
// pre-split x: pair-packed planes, g_xpk[b*32+p] = {hi(2p,2p+1), lo(2p,2p+1)}
__device__ __align__(16) uint2 g_xpk[(size_t)BATCH * 32];

// dynamic smem layout (bytes)
#define WB1_OFF  0          // 16384 (W1 frags; psm aliases this after layer 1)
#define WB2_OFF  16384      // 16384
#define WB3_OFF  32768      // 6144
#define PSM_OFF  0          // 64 x 25 floats = 6400, aliases WB1
#define BIAS_OFF 38912      // b1[64] b2[64] b3pad[32] floats = 640
#define SMEM_BYTES 39552

// ---------------------------------------------------------------------------
// PTX helpers
// ---------------------------------------------------------------------------
__device__ __forceinline__ void mma16816(float* c, const uint32_t* a, const uint32_t* b) {
    asm volatile(
        "mma.sync.aligned.m16n8k16.row.col.f32.bf16.bf16.f32 "
        "{%0,%1,%2,%3}, {%4,%5,%6,%7}, {%8,%9}, {%0,%1,%2,%3};"
        : "+f"(c[0]), "+f"(c[1]), "+f"(c[2]), "+f"(c[3])
        : "r"(a[0]), "r"(a[1]), "r"(a[2]), "r"(a[3]), "r"(b[0]), "r"(b[1]));
}

__device__ __forceinline__ uint32_t smem_u32(const void* p) {
    uint32_t a;
    asm("{ .reg .u64 t; cvta.to.shared.u64 t, %1; cvt.u32.u64 %0, t; }" : "=r"(a) : "l"(p));
    return a;
}
__device__ __forceinline__ void cp_async16(uint32_t dst, const void* src) {
    asm volatile("cp.async.cg.shared.global [%0], [%1], 16;" :: "r"(dst), "l"(src));
}
#define CP_COMMIT() asm volatile("cp.async.commit_group;" ::: "memory")
#define CP_WAIT(n)  asm volatile("cp.async.wait_group %0;" :: "n"(n) : "memory")

__device__ __forceinline__ uint2 split2(float f0, float f1) {
    __nv_bfloat162 h = __floats2bfloat162_rn(f0, f1);
    float r0 = f0 - __bfloat162float(h.x);
    float r1 = f1 - __bfloat162float(h.y);
    __nv_bfloat162 l = __floats2bfloat162_rn(r0, r1);
    uint2 o;
    o.x = *(uint32_t*)&h;
    o.y = *(uint32_t*)&l;
    return o;
}

__device__ __forceinline__ float tanha(float v) {
    float r;
    asm("tanh.approx.f32 %0, %1;" : "=f"(r) : "f"(v));
    return r;
}

// ---------------------------------------------------------------------------
// spline math
// ---------------------------------------------------------------------------
__device__ __forceinline__ float softplus_(float x) {
    return (x > 15.f) ? x : __logf(1.f + __expf(x));
}
__device__ __forceinline__ void softmax8(const float* in, float* out, float scale) {
    float m = in[0];
#pragma unroll
    for (int i = 1; i < 8; i++) m = fmaxf(m, in[i]);
    float e[8], s = 0.f;
#pragma unroll
    for (int i = 0; i < 8; i++) { e[i] = __expf(in[i] - m); s += e[i]; }
    float inv = scale / s;
#pragma unroll
    for (int i = 0; i < 8; i++) out[i] = e[i] * inv;
}

__device__ __forceinline__ void rqs_tables(const float* __restrict__ p,
                                           float* cw, float* ch, float* der) {
    float W[8], H[8], wi[8], he[8];
    softmax8(p,     W, 2.f * BTAIL);
    softmax8(p + 8, H, 2.f * BTAIL);
    softmax8(W, wi, 1.f);
    softmax8(H, he, 1.f);

    cw[0] = -BTAIL; ch[0] = -BTAIL;
    float aw = 0.f, ah = 0.f;
#pragma unroll
    for (int i = 0; i < 8; i++) {
        float wv = 1e-3f + (1.f - 8e-3f) * wi[i];
        float hv = 1e-3f + (1.f - 8e-3f) * he[i];
        aw += wv; ah += hv;
        cw[i + 1] = 2.f * BTAIL * aw - BTAIL;
        ch[i + 1] = 2.f * BTAIL * ah - BTAIL;
    }
    cw[8] = BTAIL; ch[8] = BTAIL;

    const float UDC = logf(expf(1.0f - 1e-3f) - 1.0f);
    float edge = 1e-3f + softplus_(UDC);
    der[0] = edge; der[8] = edge;
#pragma unroll
    for (int i = 0; i < 7; i++) der[i + 1] = 1e-3f + softplus_(softplus_(p[16 + i]));
}

__device__ __forceinline__ void rqs_eval(float xval, const float* __restrict__ cw,
                                         const float* __restrict__ ch,
                                         const float* __restrict__ der,
                                         float* zo, float* ldo) {
    bool inside = (xval >= -BTAIL) && (xval <= BTAIL);
    float x = fminf(fmaxf(xval, -BTAIL), BTAIL);

    int bin = 0;
#pragma unroll
    for (int i = 1; i < 8; i++) bin += (x >= cw[i]) ? 1 : 0;

    float icw = 0.f, iw = 1.f, ich = 0.f, ih = 1.f, dk = 1.f, dk1 = 1.f;
#pragma unroll
    for (int i = 0; i < 8; i++) {
        if (bin == i) {
            icw = cw[i];  iw = cw[i + 1] - cw[i];
            ich = ch[i];  ih = ch[i + 1] - ch[i];
            dk = der[i];  dk1 = der[i + 1];
        }
    }

    float delta = ih / iw;
    float th  = (x - icw) / iw;
    float t1  = th * (1.f - th);
    float numer = ih * (delta * th * th + dk * t1);
    float denom = delta + (dk + dk1 - 2.f * delta) * t1;
    float out = ich + numer / denom;
    float om = 1.f - th;
    float dnum = delta * delta * (dk1 * th * th + 2.f * delta * t1 + dk * om * om);
    float ld = __logf(dnum) - 2.f * __logf(denom);

    *zo  = inside ? out : xval;
    *ldo = inside ? ld  : 0.f;
}

__device__ __forceinline__ void rqs23(float xval, const float* __restrict__ p,
                                      float* zo, float* ldo) {
    float cw[9], ch[9], der[9];
    rqs_tables(p, cw, ch, der);
    rqs_eval(xval, cw, ch, der, zo, ldo);
}

// ---------------------------------------------------------------------------
// prep kernels
// ---------------------------------------------------------------------------
__global__ void __launch_bounds__(256) nsf_prep_w(const float* __restrict__ W1,
                                                  const float* __restrict__ W2,
                                                  const float* __restrict__ W3) {
    int l = blockIdx.x, tid = threadIdx.x;
    uint4* base = (uint4*)(g_w + (size_t)l * 38912);
    for (int f = tid; f < 1024; f += 256) {
        int s = f >> 8, n = (f >> 5) & 7, lane = f & 31;
        int g = lane >> 2, tg = lane & 3;
        int row = 8 * n + g, c0 = 16 * s + 2 * tg;
        const float* w = W1 + (size_t)l * 4096 + row * 64;
        uint2 a = split2(w[c0], w[c0 + 1]);
        uint2 b = split2(w[c0 + 8], w[c0 + 9]);
        base[f] = make_uint4(a.x, b.x, a.y, b.y);
        w = W2 + (size_t)l * 4096 + row * 64;
        a = split2(w[c0], w[c0 + 1]);
        b = split2(w[c0 + 8], w[c0 + 9]);
        base[1024 + f] = make_uint4(a.x, b.x, a.y, b.y);
    }
    for (int f = tid; f < 384; f += 256) {
        int sn = f >> 5, lane = f & 31;
        int s = sn / 3, n = sn % 3;
        int g = lane >> 2, tg = lane & 3;
        int row = 8 * n + g, c0 = 16 * s + 2 * tg;
        uint4 rec = make_uint4(0, 0, 0, 0);
        if (row < OD) {
            const float* w = W3 + (size_t)l * OD * 64 + row * 64;
            uint2 a = split2(w[c0], w[c0 + 1]);
            uint2 b = split2(w[c0 + 8], w[c0 + 9]);
            rec = make_uint4(a.x, b.x, a.y, b.y);
        }
        base[2048 + f] = rec;
    }
}

__global__ void __launch_bounds__(256) nsf_prep_x(const float* __restrict__ x) {
    int idx = blockIdx.x * 256 + threadIdx.x;   // b*32 + p
    int c = (idx & 31) * 2;
    const float* xr = x + (size_t)(idx >> 5) * DIMS;
    g_xpk[idx] = split2(xr[c], xr[c + 1]);
}

// ---------------------------------------------------------------------------
// main fused kernel: 64-row CTA, 4 warps x one m16 tile each,
// cp.async triple-buffer weight prefetch, psm aliases W1 buffer
// ---------------------------------------------------------------------------
template <int NS>
__device__ __forceinline__ void run_main(unsigned char* smp, int l,
                                         const float* __restrict__ x,
                                         const float* __restrict__ b1,
                                         const float* __restrict__ b2,
                                         const float* __restrict__ b3,
                                         float* __restrict__ z) {
    float* psm = (float*)(smp + PSM_OFF);
    float* bsm = (float*)(smp + BIAS_OFF);
    const uint4* wb1 = (const uint4*)(smp + WB1_OFF);
    const uint4* wb2 = (const uint4*)(smp + WB2_OFF);
    const uint4* wb3 = (const uint4*)(smp + WB3_OFF);

    const int tid = threadIdx.x;
    const int warp = tid >> 5, lane = tid & 31;
    const int g = lane >> 2, tg = lane & 3;
    const int m0 = blockIdx.x * 64;
    const int rb = 16 * warp + g;          // local row
    const uint32_t sbase = smem_u32(smp);

    // ---- prefetch all three weight buffers via cp.async (3 commit groups) ----
    const uint4* wsrc = (const uint4*)(g_w + (size_t)l * 38912);
#pragma unroll
    for (int i = 0; i < NS * 2; i++)
        cp_async16(sbase + WB1_OFF + (i * 128 + tid) * 16, wsrc + i * 128 + tid);
    CP_COMMIT();
#pragma unroll
    for (int i = 0; i < 8; i++)
        cp_async16(sbase + WB2_OFF + (i * 128 + tid) * 16, wsrc + 1024 + i * 128 + tid);
    CP_COMMIT();
#pragma unroll
    for (int i = 0; i < 3; i++)
        cp_async16(sbase + WB3_OFF + (i * 128 + tid) * 16, wsrc + 2048 + i * 128 + tid);
    CP_COMMIT();

    // ---- biases (normal LDG/STS, hidden behind frag-build LDGs) ----
    if (tid < 64) { bsm[tid] = b1[l * 64 + tid]; bsm[64 + tid] = b2[l * 64 + tid]; }
    if (tid >= 96) bsm[128 + tid - 96] = (tid - 96 < OD) ? b3[l * OD + tid - 96] : 0.f;
    float xv = (tid < 64) ? x[(size_t)(m0 + tid) * DIMS + (l + 1)] : 0.f;

    // ---- layer-1 A fragments straight from packed global x ----
    uint32_t Ahi[4][4], Alo[4][4];
    uint32_t mA, mB;
    {
        int cA = 16 * (NS - 1) + 2 * tg, cB = cA + 8;
        mA = (cA + 1 <= l) ? 0xFFFFFFFFu : ((cA <= l) ? 0x0000FFFFu : 0u);
        mB = (cB + 1 <= l) ? 0xFFFFFFFFu : ((cB <= l) ? 0x0000FFFFu : 0u);
    }
    {
        int r0 = m0 + rb;
#pragma unroll
        for (int s = 0; s < NS; s++) {
            int p0 = 8 * s + tg;
            uint2 v00 = g_xpk[(size_t)r0 * 32 + p0];
            uint2 v01 = g_xpk[(size_t)(r0 + 8) * 32 + p0];
            uint2 v10 = g_xpk[(size_t)r0 * 32 + p0 + 4];
            uint2 v11 = g_xpk[(size_t)(r0 + 8) * 32 + p0 + 4];
            if (s == NS - 1) {
                v00.x &= mA; v00.y &= mA; v01.x &= mA; v01.y &= mA;
                v10.x &= mB; v10.y &= mB; v11.x &= mB; v11.y &= mB;
            }
            Ahi[s][0] = v00.x; Alo[s][0] = v00.y;
            Ahi[s][1] = v01.x; Alo[s][1] = v01.y;
            Ahi[s][2] = v10.x; Alo[s][2] = v10.y;
            Ahi[s][3] = v11.x; Alo[s][3] = v11.y;
        }
    }
    CP_WAIT(2);           // W1 landed
    __syncthreads();

    float acc[8][4];

    // ================= layer 1 (K = 16*NS), bias in acc init =================
#pragma unroll
    for (int n = 0; n < 8; n++) {
        int c0 = 8 * n + 2 * tg;
        acc[n][0] = bsm[c0]; acc[n][1] = bsm[c0 + 1];
        acc[n][2] = bsm[c0]; acc[n][3] = bsm[c0 + 1];
    }
#pragma unroll
    for (int n = 0; n < 8; n++)
#pragma unroll
        for (int s = 0; s < NS; s++) {
            uint4 w = wb1[(s * 8 + n) * 32 + lane];
            uint32_t bh[2] = { w.x, w.y }, bl[2] = { w.z, w.w };
            mma16816(acc[n], Ahi[s], bh);
            mma16816(acc[n], Ahi[s], bl);
            mma16816(acc[n], Alo[s], bh);
        }
    // epilogue 1: tanh + split -> next A frags (registers only)
#pragma unroll
    for (int n = 0; n < 8; n++) {
        float h0 = tanha(acc[n][0]);
        float h1 = tanha(acc[n][1]);
        float h2 = tanha(acc[n][2]);
        float h3 = tanha(acc[n][3]);
        uint2 p01 = split2(h0, h1);
        uint2 p23 = split2(h2, h3);
        int j = n >> 1, b = n & 1;
        Ahi[j][2 * b]     = p01.x; Alo[j][2 * b]     = p01.y;
        Ahi[j][2 * b + 1] = p23.x; Alo[j][2 * b + 1] = p23.y;
    }
    CP_WAIT(1);           // W2 landed (flew in during layer 1)
    __syncthreads();

    // ================= layer 2 =================
#pragma unroll
    for (int n = 0; n < 8; n++) {
        int c0 = 8 * n + 2 * tg;
        acc[n][0] = bsm[64 + c0]; acc[n][1] = bsm[64 + c0 + 1];
        acc[n][2] = bsm[64 + c0]; acc[n][3] = bsm[64 + c0 + 1];
    }
#pragma unroll
    for (int n = 0; n < 8; n++)
#pragma unroll
        for (int s = 0; s < 4; s++) {
            uint4 w = wb2[(s * 8 + n) * 32 + lane];
            uint32_t bh[2] = { w.x, w.y }, bl[2] = { w.z, w.w };
            mma16816(acc[n], Ahi[s], bh);
            mma16816(acc[n], Ahi[s], bl);
            mma16816(acc[n], Alo[s], bh);
        }
    // epilogue 2
#pragma unroll
    for (int n = 0; n < 8; n++) {
        float h0 = tanha(acc[n][0]);
        float h1 = tanha(acc[n][1]);
        float h2 = tanha(acc[n][2]);
        float h3 = tanha(acc[n][3]);
        uint2 p01 = split2(h0, h1);
        uint2 p23 = split2(h2, h3);
        int j = n >> 1, b = n & 1;
        Ahi[j][2 * b]     = p01.x; Alo[j][2 * b]     = p01.y;
        Ahi[j][2 * b + 1] = p23.x; Alo[j][2 * b + 1] = p23.y;
    }
    CP_WAIT(0);           // W3 landed
    __syncthreads();

    // ================= layer 3 (3 n-tiles), bias in acc init =================
#pragma unroll
    for (int n = 0; n < 3; n++) {
        int c0 = 8 * n + 2 * tg;
        acc[n][0] = bsm[128 + c0]; acc[n][1] = bsm[128 + c0 + 1];
        acc[n][2] = bsm[128 + c0]; acc[n][3] = bsm[128 + c0 + 1];
    }
#pragma unroll
    for (int n = 0; n < 3; n++)
#pragma unroll
        for (int s = 0; s < 4; s++) {
            uint4 w = wb3[(s * 3 + n) * 32 + lane];
            uint32_t bh[2] = { w.x, w.y }, bl[2] = { w.z, w.w };
            mma16816(acc[n], Ahi[s], bh);
            mma16816(acc[n], Ahi[s], bl);
            mma16816(acc[n], Alo[s], bh);
        }
    __syncthreads();      // all wb1 reads done long ago; psm aliases wb1
    // write spline params (stride 25)
#pragma unroll
    for (int n = 0; n < 3; n++) {
        int c0 = 8 * n + 2 * tg;
        if (c0 < OD)     psm[rb * 25 + c0]           = acc[n][0];
        if (c0 + 1 < OD) psm[rb * 25 + c0 + 1]       = acc[n][1];
        if (c0 < OD)     psm[(rb + 8) * 25 + c0]     = acc[n][2];
        if (c0 + 1 < OD) psm[(rb + 8) * 25 + c0 + 1] = acc[n][3];
    }
    __syncthreads();

    // ---- spline: one thread per batch row (64 rows) ----
    if (tid < 64) {
        float zo, ldo;
        rqs23(xv, &psm[tid * 25], &zo, &ldo);
        z[(size_t)(m0 + tid) * DIMS + (l + 1)] = zo;
        g_ld[(size_t)(m0 + tid) * DIMS + (l + 1)] = ldo;
    }
}

__global__ void __launch_bounds__(128, 5) nsf_main(
    const float* __restrict__ x,
    const float* __restrict__ b1, const float* __restrict__ b2,
    const float* __restrict__ b3, float* __restrict__ z) {
    extern __shared__ unsigned char smp[];
    int l = blockIdx.y;
    switch (l >> 4) {
        case 0:  run_main<1>(smp, l, x, b1, b2, b3, z); break;
        case 1:  run_main<2>(smp, l, x, b1, b2, b3, z); break;
        case 2:  run_main<3>(smp, l, x, b1, b2, b3, z); break;
        default: run_main<4>(smp, l, x, b1, b2, b3, z); break;
    }
}

// ---------------------------------------------------------------------------
// tail: dim-0 spline (shared tables) + logdet reduce, one kernel
// ---------------------------------------------------------------------------
__global__ void __launch_bounds__(128) nsf_tail(const float* __restrict__ x,
                                                const float* __restrict__ ip,
                                                float* __restrict__ z,
                                                float* __restrict__ ldo) {
    __shared__ float cw[9], ch[9], der[9];
    if (threadIdx.x == 0) {
        float p[23];
#pragma unroll
        for (int i = 0; i < 23; i++) p[i] = ip[i];
        rqs_tables(p, cw, ch, der);
    }
    __syncthreads();
    int b = blockIdx.x * 128 + threadIdx.x;
    float zo, ld0;
    rqs_eval(x[(size_t)b * DIMS], cw, ch, der, &zo, &ld0);
    z[(size_t)b * DIMS] = zo;

    const float4* r = (const float4*)(g_ld + (size_t)b * DIMS);
    float s = ld0;
    {
        float4 v = r[0];              // v.x is dim-0 slot (unwritten) -> skip
        s += v.y + v.z + v.w;
    }
#pragma unroll
    for (int i = 1; i < 16; i++) {
        float4 v = r[i];
        s += v.x + v.y + v.z + v.w;
    }
    ldo[b] = s;
}

// ---------------------------------------------------------------------------
extern "C" void kernel_launch(void* const* d_in, const int* in_sizes, int n_in,
                              void* d_out, int out_size) {
    const float* x  = (const float*)d_in[0];
    const float* ip = (const float*)d_in[1];
    const float* W1 = (const float*)d_in[2];
    const float* b1 = (const float*)d_in[3];
    const float* W2 = (const float*)d_in[4];
    const float* b2 = (const float*)d_in[5];
    const float* W3 = (const float*)d_in[6];
    const float* b3 = (const float*)d_in[7];

    float* z   = (float*)d_out;
    float* ldo = z + (size_t)BATCH * DIMS;

    cudaFuncSetAttribute(nsf_main, cudaFuncAttributeMaxDynamicSharedMemorySize, SMEM_BYTES);

    nsf_prep_w<<<LAYERS, 256>>>(W1, W2, W3);
    nsf_prep_x<<<BATCH * 32 / 256, 256>>>(x);
    nsf_main<<<dim3(256, 63), 128, SMEM_BYTES>>>(x, b1, b2, b3, z);
    nsf_tail<<<BATCH / 128, 128>>>(x, ip, z, ldo);
}

// round 13
// speedup vs baseline: 3.4572x; 1.0031x over previous
#include <cuda_runtime.h>
#include <cuda_bf16.h>
#include <math.h>
#include <stdint.h>

#define BATCH 16384
#define DIMS  64
#define LAYERS 63
#define HID   64
#define OD    23
#define BTAIL 3.0f

// per-(batch,dim) logdet partials, [b][d] layout
__device__ float g_ld[BATCH * DIMS];
// fragment-ordered packed weights, per layer stride 38912 B:
//   W1 frags @0 (16384), W2 @16384 (16384), W3 @32768 (6144)
//   frag record = uint4 {hi0,hi1,lo0,lo1}
__device__ __align__(16) unsigned char g_w[(size_t)LAYERS * 38912];
// pre-split x: pair-packed planes, g_xpk[b*32+p] = {hi(2p,2p+1), lo(2p,2p+1)}
__device__ __align__(16) uint2 g_xpk[(size_t)BATCH * 32];

// dynamic smem layout (bytes)
// WB1 region [0,16384): W1 frags; after layer 1 it is dead and is reused as
//   psm @0 (6400 B) and W3 frags @8192 (6144 B, cp.async'd at layer-2 start)
#define WB1_OFF  0
#define PSM_OFF  0
#define WB3_OFF  8192
#define WB2_OFF  16384      // 16384
#define BIAS_OFF 32768      // b1[64] b2[64] b3pad[32] floats = 640
#define SMEM_BYTES 33408

// ---------------------------------------------------------------------------
// PTX helpers
// ---------------------------------------------------------------------------
__device__ __forceinline__ void mma16816(float* c, const uint32_t* a, const uint32_t* b) {
    asm volatile(
        "mma.sync.aligned.m16n8k16.row.col.f32.bf16.bf16.f32 "
        "{%0,%1,%2,%3}, {%4,%5,%6,%7}, {%8,%9}, {%0,%1,%2,%3};"
        : "+f"(c[0]), "+f"(c[1]), "+f"(c[2]), "+f"(c[3])
        : "r"(a[0]), "r"(a[1]), "r"(a[2]), "r"(a[3]), "r"(b[0]), "r"(b[1]));
}

__device__ __forceinline__ uint32_t smem_u32(const void* p) {
    uint32_t a;
    asm("{ .reg .u64 t; cvta.to.shared.u64 t, %1; cvt.u32.u64 %0, t; }" : "=r"(a) : "l"(p));
    return a;
}
__device__ __forceinline__ void cp_async16(uint32_t dst, const void* src) {
    asm volatile("cp.async.cg.shared.global [%0], [%1], 16;" :: "r"(dst), "l"(src));
}
#define CP_COMMIT() asm volatile("cp.async.commit_group;" ::: "memory")
#define CP_WAIT(n)  asm volatile("cp.async.wait_group %0;" :: "n"(n) : "memory")

__device__ __forceinline__ uint2 split2(float f0, float f1) {
    __nv_bfloat162 h = __floats2bfloat162_rn(f0, f1);
    float r0 = f0 - __bfloat162float(h.x);
    float r1 = f1 - __bfloat162float(h.y);
    __nv_bfloat162 l = __floats2bfloat162_rn(r0, r1);
    uint2 o;
    o.x = *(uint32_t*)&h;
    o.y = *(uint32_t*)&l;
    return o;
}

__device__ __forceinline__ float tanha(float v) {
    float r;
    asm("tanh.approx.f32 %0, %1;" : "=f"(r) : "f"(v));
    return r;
}

// ---------------------------------------------------------------------------
// spline math
// ---------------------------------------------------------------------------
__device__ __forceinline__ float softplus_(float x) {
    return (x > 15.f) ? x : __logf(1.f + __expf(x));
}
__device__ __forceinline__ void softmax8(const float* in, float* out, float scale) {
    float m = in[0];
#pragma unroll
    for (int i = 1; i < 8; i++) m = fmaxf(m, in[i]);
    float e[8], s = 0.f;
#pragma unroll
    for (int i = 0; i < 8; i++) { e[i] = __expf(in[i] - m); s += e[i]; }
    float inv = scale / s;
#pragma unroll
    for (int i = 0; i < 8; i++) out[i] = e[i] * inv;
}

__device__ __forceinline__ void rqs_tables(const float* __restrict__ p,
                                           float* cw, float* ch, float* der) {
    float W[8], H[8], wi[8], he[8];
    softmax8(p,     W, 2.f * BTAIL);
    softmax8(p + 8, H, 2.f * BTAIL);
    softmax8(W, wi, 1.f);
    softmax8(H, he, 1.f);

    cw[0] = -BTAIL; ch[0] = -BTAIL;
    float aw = 0.f, ah = 0.f;
#pragma unroll
    for (int i = 0; i < 8; i++) {
        float wv = 1e-3f + (1.f - 8e-3f) * wi[i];
        float hv = 1e-3f + (1.f - 8e-3f) * he[i];
        aw += wv; ah += hv;
        cw[i + 1] = 2.f * BTAIL * aw - BTAIL;
        ch[i + 1] = 2.f * BTAIL * ah - BTAIL;
    }
    cw[8] = BTAIL; ch[8] = BTAIL;

    const float UDC = logf(expf(1.0f - 1e-3f) - 1.0f);
    float edge = 1e-3f + softplus_(UDC);
    der[0] = edge; der[8] = edge;
#pragma unroll
    for (int i = 0; i < 7; i++) der[i + 1] = 1e-3f + softplus_(softplus_(p[16 + i]));
}

__device__ __forceinline__ void rqs_eval(float xval, const float* __restrict__ cw,
                                         const float* __restrict__ ch,
                                         const float* __restrict__ der,
                                         float* zo, float* ldo) {
    bool inside = (xval >= -BTAIL) && (xval <= BTAIL);
    float x = fminf(fmaxf(xval, -BTAIL), BTAIL);

    int bin = 0;
#pragma unroll
    for (int i = 1; i < 8; i++) bin += (x >= cw[i]) ? 1 : 0;

    float icw = 0.f, iw = 1.f, ich = 0.f, ih = 1.f, dk = 1.f, dk1 = 1.f;
#pragma unroll
    for (int i = 0; i < 8; i++) {
        if (bin == i) {
            icw = cw[i];  iw = cw[i + 1] - cw[i];
            ich = ch[i];  ih = ch[i + 1] - ch[i];
            dk = der[i];  dk1 = der[i + 1];
        }
    }

    float delta = ih / iw;
    float th  = (x - icw) / iw;
    float t1  = th * (1.f - th);
    float numer = ih * (delta * th * th + dk * t1);
    float denom = delta + (dk + dk1 - 2.f * delta) * t1;
    float out = ich + numer / denom;
    float om = 1.f - th;
    float dnum = delta * delta * (dk1 * th * th + 2.f * delta * t1 + dk * om * om);
    float ld = __logf(dnum) - 2.f * __logf(denom);

    *zo  = inside ? out : xval;
    *ldo = inside ? ld  : 0.f;
}

__device__ __forceinline__ void rqs23(float xval, const float* __restrict__ p,
                                      float* zo, float* ldo) {
    float cw[9], ch[9], der[9];
    rqs_tables(p, cw, ch, der);
    rqs_eval(xval, cw, ch, der, zo, ldo);
}

// ---------------------------------------------------------------------------
// merged prep: blocks [0,2048) pack x; blocks [2048, 2111) pack weights
// ---------------------------------------------------------------------------
__global__ void __launch_bounds__(256) nsf_prep(const float* __restrict__ x,
                                                const float* __restrict__ W1,
                                                const float* __restrict__ W2,
                                                const float* __restrict__ W3) {
    int tid = threadIdx.x;
    if (blockIdx.x < 2048) {
        int idx = blockIdx.x * 256 + tid;   // b*32 + p
        int c = (idx & 31) * 2;
        const float* xr = x + (size_t)(idx >> 5) * DIMS;
        g_xpk[idx] = split2(xr[c], xr[c + 1]);
        return;
    }
    int l = blockIdx.x - 2048;
    uint4* base = (uint4*)(g_w + (size_t)l * 38912);
    for (int f = tid; f < 1024; f += 256) {
        int s = f >> 8, n = (f >> 5) & 7, lane = f & 31;
        int g = lane >> 2, tg = lane & 3;
        int row = 8 * n + g, c0 = 16 * s + 2 * tg;
        const float* w = W1 + (size_t)l * 4096 + row * 64;
        uint2 a = split2(w[c0], w[c0 + 1]);
        uint2 b = split2(w[c0 + 8], w[c0 + 9]);
        base[f] = make_uint4(a.x, b.x, a.y, b.y);
        w = W2 + (size_t)l * 4096 + row * 64;
        a = split2(w[c0], w[c0 + 1]);
        b = split2(w[c0 + 8], w[c0 + 9]);
        base[1024 + f] = make_uint4(a.x, b.x, a.y, b.y);
    }
    for (int f = tid; f < 384; f += 256) {
        int sn = f >> 5, lane = f & 31;
        int s = sn / 3, n = sn % 3;
        int g = lane >> 2, tg = lane & 3;
        int row = 8 * n + g, c0 = 16 * s + 2 * tg;
        uint4 rec = make_uint4(0, 0, 0, 0);
        if (row < OD) {
            const float* w = W3 + (size_t)l * OD * 64 + row * 64;
            uint2 a = split2(w[c0], w[c0 + 1]);
            uint2 b = split2(w[c0 + 8], w[c0 + 9]);
            rec = make_uint4(a.x, b.x, a.y, b.y);
        }
        base[2048 + f] = rec;
    }
}

// ---------------------------------------------------------------------------
// main fused kernel: 64-row CTA, 4 warps x one m16 tile each,
// cp.async weight prefetch; W3 deferred into dead W1 region
// ---------------------------------------------------------------------------
template <int NS>
__device__ __forceinline__ void run_main(unsigned char* smp, int l,
                                         const float* __restrict__ x,
                                         const float* __restrict__ b1,
                                         const float* __restrict__ b2,
                                         const float* __restrict__ b3,
                                         float* __restrict__ z) {
    float* psm = (float*)(smp + PSM_OFF);
    float* bsm = (float*)(smp + BIAS_OFF);
    const uint4* wb1 = (const uint4*)(smp + WB1_OFF);
    const uint4* wb2 = (const uint4*)(smp + WB2_OFF);
    const uint4* wb3 = (const uint4*)(smp + WB3_OFF);

    const int tid = threadIdx.x;
    const int warp = tid >> 5, lane = tid & 31;
    const int g = lane >> 2, tg = lane & 3;
    const int m0 = blockIdx.x * 64;
    const int rb = 16 * warp + g;          // local row
    const uint32_t sbase = smem_u32(smp);

    // ---- prefetch W1, W2 via cp.async (2 commit groups) ----
    const uint4* wsrc = (const uint4*)(g_w + (size_t)l * 38912);
#pragma unroll
    for (int i = 0; i < NS * 2; i++)
        cp_async16(sbase + WB1_OFF + (i * 128 + tid) * 16, wsrc + i * 128 + tid);
    CP_COMMIT();
#pragma unroll
    for (int i = 0; i < 8; i++)
        cp_async16(sbase + WB2_OFF + (i * 128 + tid) * 16, wsrc + 1024 + i * 128 + tid);
    CP_COMMIT();

    // ---- biases (normal LDG/STS, hidden behind frag-build LDGs) ----
    if (tid < 64) { bsm[tid] = b1[l * 64 + tid]; bsm[64 + tid] = b2[l * 64 + tid]; }
    if (tid >= 96) bsm[128 + tid - 96] = (tid - 96 < OD) ? b3[l * OD + tid - 96] : 0.f;
    float xv = (tid < 64) ? x[(size_t)(m0 + tid) * DIMS + (l + 1)] : 0.f;

    // ---- layer-1 A fragments straight from packed global x ----
    uint32_t Ahi[4][4], Alo[4][4];
    uint32_t mA, mB;
    {
        int cA = 16 * (NS - 1) + 2 * tg, cB = cA + 8;
        mA = (cA + 1 <= l) ? 0xFFFFFFFFu : ((cA <= l) ? 0x0000FFFFu : 0u);
        mB = (cB + 1 <= l) ? 0xFFFFFFFFu : ((cB <= l) ? 0x0000FFFFu : 0u);
    }
    {
        int r0 = m0 + rb;
#pragma unroll
        for (int s = 0; s < NS; s++) {
            int p0 = 8 * s + tg;
            uint2 v00 = g_xpk[(size_t)r0 * 32 + p0];
            uint2 v01 = g_xpk[(size_t)(r0 + 8) * 32 + p0];
            uint2 v10 = g_xpk[(size_t)r0 * 32 + p0 + 4];
            uint2 v11 = g_xpk[(size_t)(r0 + 8) * 32 + p0 + 4];
            if (s == NS - 1) {
                v00.x &= mA; v00.y &= mA; v01.x &= mA; v01.y &= mA;
                v10.x &= mB; v10.y &= mB; v11.x &= mB; v11.y &= mB;
            }
            Ahi[s][0] = v00.x; Alo[s][0] = v00.y;
            Ahi[s][1] = v01.x; Alo[s][1] = v01.y;
            Ahi[s][2] = v10.x; Alo[s][2] = v10.y;
            Ahi[s][3] = v11.x; Alo[s][3] = v11.y;
        }
    }
    CP_WAIT(1);           // W1 landed (W2 may still be in flight)
    __syncthreads();

    float acc[8][4];

    // ================= layer 1 (K = 16*NS), bias in acc init =================
#pragma unroll
    for (int n = 0; n < 8; n++) {
        int c0 = 8 * n + 2 * tg;
        acc[n][0] = bsm[c0]; acc[n][1] = bsm[c0 + 1];
        acc[n][2] = bsm[c0]; acc[n][3] = bsm[c0 + 1];
    }
#pragma unroll
    for (int n = 0; n < 8; n++)
#pragma unroll
        for (int s = 0; s < NS; s++) {
            uint4 w = wb1[(s * 8 + n) * 32 + lane];
            uint32_t bh[2] = { w.x, w.y }, bl[2] = { w.z, w.w };
            mma16816(acc[n], Ahi[s], bh);
            mma16816(acc[n], Ahi[s], bl);
            mma16816(acc[n], Alo[s], bh);
        }
    // epilogue 1: tanh + split -> next A frags (registers only)
#pragma unroll
    for (int n = 0; n < 8; n++) {
        float h0 = tanha(acc[n][0]);
        float h1 = tanha(acc[n][1]);
        float h2 = tanha(acc[n][2]);
        float h3 = tanha(acc[n][3]);
        uint2 p01 = split2(h0, h1);
        uint2 p23 = split2(h2, h3);
        int j = n >> 1, b = n & 1;
        Ahi[j][2 * b]     = p01.x; Alo[j][2 * b]     = p01.y;
        Ahi[j][2 * b + 1] = p23.x; Alo[j][2 * b + 1] = p23.y;
    }
    CP_WAIT(0);           // W2 landed (flew in during layer 1)
    __syncthreads();      // all wb1 reads complete -> W1 region reusable

    // deferred W3 prefetch into dead W1 region (lands during layer 2)
#pragma unroll
    for (int i = 0; i < 3; i++)
        cp_async16(sbase + WB3_OFF + (i * 128 + tid) * 16, wsrc + 2048 + i * 128 + tid);
    CP_COMMIT();

    // ================= layer 2 =================
#pragma unroll
    for (int n = 0; n < 8; n++) {
        int c0 = 8 * n + 2 * tg;
        acc[n][0] = bsm[64 + c0]; acc[n][1] = bsm[64 + c0 + 1];
        acc[n][2] = bsm[64 + c0]; acc[n][3] = bsm[64 + c0 + 1];
    }
#pragma unroll
    for (int n = 0; n < 8; n++)
#pragma unroll
        for (int s = 0; s < 4; s++) {
            uint4 w = wb2[(s * 8 + n) * 32 + lane];
            uint32_t bh[2] = { w.x, w.y }, bl[2] = { w.z, w.w };
            mma16816(acc[n], Ahi[s], bh);
            mma16816(acc[n], Ahi[s], bl);
            mma16816(acc[n], Alo[s], bh);
        }
    // epilogue 2
#pragma unroll
    for (int n = 0; n < 8; n++) {
        float h0 = tanha(acc[n][0]);
        float h1 = tanha(acc[n][1]);
        float h2 = tanha(acc[n][2]);
        float h3 = tanha(acc[n][3]);
        uint2 p01 = split2(h0, h1);
        uint2 p23 = split2(h2, h3);
        int j = n >> 1, b = n & 1;
        Ahi[j][2 * b]     = p01.x; Alo[j][2 * b]     = p01.y;
        Ahi[j][2 * b + 1] = p23.x; Alo[j][2 * b + 1] = p23.y;
    }
    CP_WAIT(0);           // W3 landed
    __syncthreads();

    // ================= layer 3 (3 n-tiles), bias in acc init =================
#pragma unroll
    for (int n = 0; n < 3; n++) {
        int c0 = 8 * n + 2 * tg;
        acc[n][0] = bsm[128 + c0]; acc[n][1] = bsm[128 + c0 + 1];
        acc[n][2] = bsm[128 + c0]; acc[n][3] = bsm[128 + c0 + 1];
    }
#pragma unroll
    for (int n = 0; n < 3; n++)
#pragma unroll
        for (int s = 0; s < 4; s++) {
            uint4 w = wb3[(s * 3 + n) * 32 + lane];
            uint32_t bh[2] = { w.x, w.y }, bl[2] = { w.z, w.w };
            mma16816(acc[n], Ahi[s], bh);
            mma16816(acc[n], Ahi[s], bl);
            mma16816(acc[n], Alo[s], bh);
        }
    __syncthreads();      // psm (@0) does not overlap W3 (@8192); barrier orders wb3 reads
    // write spline params (stride 25)
#pragma unroll
    for (int n = 0; n < 3; n++) {
        int c0 = 8 * n + 2 * tg;
        if (c0 < OD)     psm[rb * 25 + c0]           = acc[n][0];
        if (c0 + 1 < OD) psm[rb * 25 + c0 + 1]       = acc[n][1];
        if (c0 < OD)     psm[(rb + 8) * 25 + c0]     = acc[n][2];
        if (c0 + 1 < OD) psm[(rb + 8) * 25 + c0 + 1] = acc[n][3];
    }
    __syncthreads();

    // ---- spline: one thread per batch row (64 rows) ----
    if (tid < 64) {
        float zo, ldo;
        rqs23(xv, &psm[tid * 25], &zo, &ldo);
        z[(size_t)(m0 + tid) * DIMS + (l + 1)] = zo;
        g_ld[(size_t)(m0 + tid) * DIMS + (l + 1)] = ldo;
    }
}

__global__ void __launch_bounds__(128, 6) nsf_main(
    const float* __restrict__ x,
    const float* __restrict__ b1, const float* __restrict__ b2,
    const float* __restrict__ b3, float* __restrict__ z) {
    extern __shared__ unsigned char smp[];
    int l = blockIdx.y;
    switch (l >> 4) {
        case 0:  run_main<1>(smp, l, x, b1, b2, b3, z); break;
        case 1:  run_main<2>(smp, l, x, b1, b2, b3, z); break;
        case 2:  run_main<3>(smp, l, x, b1, b2, b3, z); break;
        default: run_main<4>(smp, l, x, b1, b2, b3, z); break;
    }
}

// ---------------------------------------------------------------------------
// tail: dim-0 spline + logdet reduce, 4 threads per batch row
// ---------------------------------------------------------------------------
__global__ void __launch_bounds__(256) nsf_tail(const float* __restrict__ x,
                                                const float* __restrict__ ip,
                                                float* __restrict__ z,
                                                float* __restrict__ ldo) {
    __shared__ float cw[9], ch[9], der[9];
    if (threadIdx.x == 0) {
        float p[23];
#pragma unroll
        for (int i = 0; i < 23; i++) p[i] = ip[i];
        rqs_tables(p, cw, ch, der);
    }
    __syncthreads();
    int idx = blockIdx.x * 256 + threadIdx.x;
    int b = idx >> 2, q = idx & 3;

    const float4* r = (const float4*)(g_ld + (size_t)b * DIMS) + q * 4;
    float s = 0.f;
    if (q == 0) {
        float4 v = r[0];              // v.x is the unwritten dim-0 slot -> skip
        s += v.y + v.z + v.w;
#pragma unroll
        for (int i = 1; i < 4; i++) {
            float4 w = r[i];
            s += w.x + w.y + w.z + w.w;
        }
        float zo, ld0;
        rqs_eval(x[(size_t)b * DIMS], cw, ch, der, &zo, &ld0);
        z[(size_t)b * DIMS] = zo;
        s += ld0;
    } else {
#pragma unroll
        for (int i = 0; i < 4; i++) {
            float4 w = r[i];
            s += w.x + w.y + w.z + w.w;
        }
    }
    s += __shfl_xor_sync(0xFFFFFFFFu, s, 1);
    s += __shfl_xor_sync(0xFFFFFFFFu, s, 2);
    if (q == 0) ldo[b] = s;
}

// ---------------------------------------------------------------------------
extern "C" void kernel_launch(void* const* d_in, const int* in_sizes, int n_in,
                              void* d_out, int out_size) {
    const float* x  = (const float*)d_in[0];
    const float* ip = (const float*)d_in[1];
    const float* W1 = (const float*)d_in[2];
    const float* b1 = (const float*)d_in[3];
    const float* W2 = (const float*)d_in[4];
    const float* b2 = (const float*)d_in[5];
    const float* W3 = (const float*)d_in[6];
    const float* b3 = (const float*)d_in[7];

    float* z   = (float*)d_out;
    float* ldo = z + (size_t)BATCH * DIMS;

    cudaFuncSetAttribute(nsf_main, cudaFuncAttributeMaxDynamicSharedMemorySize, SMEM_BYTES);

    nsf_prep<<<2048 + LAYERS, 256>>>(x, W1, W2, W3);
    nsf_main<<<dim3(256, 63), 128, SMEM_BYTES>>>(x, b1, b2, b3, z);
    nsf_tail<<<BATCH * 4 / 256, 256>>>(x, ip, z, ldo);
}

// round 14
// speedup vs baseline: 4.0955x; 1.1846x over previous
#include <cuda_runtime.h>
#include <cuda_fp16.h>
#include <math.h>
#include <stdint.h>

#define BATCH 16384
#define DIMS  64
#define LAYERS 63
#define HID   64
#define OD    23
#define BTAIL 3.0f

// per-(batch,dim) logdet partials, [b][d] layout
__device__ float g_ld[BATCH * DIMS];
// fragment-ordered packed fp16 weights, per layer stride 38912 B:
//   W1 frags @0 (16384), W2 @16384 (16384), W3 @32768 (6144)
//   frag record = uint4 {hi0, hi1, lo0, lo1}  (half2-packed)
__device__ __align__(16) unsigned char g_w[(size_t)LAYERS * 38912];
// x packed as fp16 pairs: g_xpk[b*32+p] = half2(x[2p], x[2p+1])
__device__ __align__(8) uint32_t g_xpk[(size_t)BATCH * 32];

// dynamic smem layout (bytes)
// WB1 region [0,16384): W1 frags; dead after layer 1, reused as
//   psm @0 (6400 B) and W3 frags @8192 (6144 B, cp.async'd at layer-2 start)
#define WB1_OFF  0
#define PSM_OFF  0
#define WB3_OFF  8192
#define WB2_OFF  16384      // 16384
#define BIAS_OFF 32768      // b1[64] b2[64] b3pad[32] floats = 640
#define SMEM_BYTES 33408

// ---------------------------------------------------------------------------
// PTX helpers
// ---------------------------------------------------------------------------
__device__ __forceinline__ void mma16816(float* c, const uint32_t* a, const uint32_t* b) {
    asm volatile(
        "mma.sync.aligned.m16n8k16.row.col.f32.f16.f16.f32 "
        "{%0,%1,%2,%3}, {%4,%5,%6,%7}, {%8,%9}, {%0,%1,%2,%3};"
        : "+f"(c[0]), "+f"(c[1]), "+f"(c[2]), "+f"(c[3])
        : "r"(a[0]), "r"(a[1]), "r"(a[2]), "r"(a[3]), "r"(b[0]), "r"(b[1]));
}

__device__ __forceinline__ uint32_t smem_u32(const void* p) {
    uint32_t a;
    asm("{ .reg .u64 t; cvta.to.shared.u64 t, %1; cvt.u32.u64 %0, t; }" : "=r"(a) : "l"(p));
    return a;
}
__device__ __forceinline__ void cp_async16(uint32_t dst, const void* src) {
    asm volatile("cp.async.cg.shared.global [%0], [%1], 16;" :: "r"(dst), "l"(src));
}
#define CP_COMMIT() asm volatile("cp.async.commit_group;" ::: "memory")
#define CP_WAIT(n)  asm volatile("cp.async.wait_group %0;" :: "n"(n) : "memory")

// fp16 pair pack (single plane)
__device__ __forceinline__ uint32_t pack_h2(float f0, float f1) {
    __half2 h = __floats2half2_rn(f0, f1);
    return *(uint32_t*)&h;
}
// fp16 hi/lo split pair pack
__device__ __forceinline__ uint2 split2h(float f0, float f1) {
    __half h0 = __float2half_rn(f0), h1 = __float2half_rn(f1);
    __half l0 = __float2half_rn(f0 - __half2float(h0));
    __half l1 = __float2half_rn(f1 - __half2float(h1));
    __half2 hp = __halves2half2(h0, h1), lp = __halves2half2(l0, l1);
    uint2 o;
    o.x = *(uint32_t*)&hp;
    o.y = *(uint32_t*)&lp;
    return o;
}

__device__ __forceinline__ float tanha(float v) {
    float r;
    asm("tanh.approx.f32 %0, %1;" : "=f"(r) : "f"(v));
    return r;
}

// ---------------------------------------------------------------------------
// spline math
// ---------------------------------------------------------------------------
__device__ __forceinline__ float softplus_(float x) {
    return (x > 15.f) ? x : __logf(1.f + __expf(x));
}
__device__ __forceinline__ void softmax8(const float* in, float* out, float scale) {
    float m = in[0];
#pragma unroll
    for (int i = 1; i < 8; i++) m = fmaxf(m, in[i]);
    float e[8], s = 0.f;
#pragma unroll
    for (int i = 0; i < 8; i++) { e[i] = __expf(in[i] - m); s += e[i]; }
    float inv = scale / s;
#pragma unroll
    for (int i = 0; i < 8; i++) out[i] = e[i] * inv;
}

__device__ __forceinline__ void rqs_tables(const float* __restrict__ p,
                                           float* cw, float* ch, float* der) {
    float W[8], H[8], wi[8], he[8];
    softmax8(p,     W, 2.f * BTAIL);
    softmax8(p + 8, H, 2.f * BTAIL);
    softmax8(W, wi, 1.f);
    softmax8(H, he, 1.f);

    cw[0] = -BTAIL; ch[0] = -BTAIL;
    float aw = 0.f, ah = 0.f;
#pragma unroll
    for (int i = 0; i < 8; i++) {
        float wv = 1e-3f + (1.f - 8e-3f) * wi[i];
        float hv = 1e-3f + (1.f - 8e-3f) * he[i];
        aw += wv; ah += hv;
        cw[i + 1] = 2.f * BTAIL * aw - BTAIL;
        ch[i + 1] = 2.f * BTAIL * ah - BTAIL;
    }
    cw[8] = BTAIL; ch[8] = BTAIL;

    const float UDC = logf(expf(1.0f - 1e-3f) - 1.0f);
    float edge = 1e-3f + softplus_(UDC);
    der[0] = edge; der[8] = edge;
#pragma unroll
    for (int i = 0; i < 7; i++) der[i + 1] = 1e-3f + softplus_(softplus_(p[16 + i]));
}

__device__ __forceinline__ void rqs_eval(float xval, const float* __restrict__ cw,
                                         const float* __restrict__ ch,
                                         const float* __restrict__ der,
                                         float* zo, float* ldo) {
    bool inside = (xval >= -BTAIL) && (xval <= BTAIL);
    float x = fminf(fmaxf(xval, -BTAIL), BTAIL);

    int bin = 0;
#pragma unroll
    for (int i = 1; i < 8; i++) bin += (x >= cw[i]) ? 1 : 0;

    float icw = 0.f, iw = 1.f, ich = 0.f, ih = 1.f, dk = 1.f, dk1 = 1.f;
#pragma unroll
    for (int i = 0; i < 8; i++) {
        if (bin == i) {
            icw = cw[i];  iw = cw[i + 1] - cw[i];
            ich = ch[i];  ih = ch[i + 1] - ch[i];
            dk = der[i];  dk1 = der[i + 1];
        }
    }

    float delta = ih / iw;
    float th  = (x - icw) / iw;
    float t1  = th * (1.f - th);
    float numer = ih * (delta * th * th + dk * t1);
    float denom = delta + (dk + dk1 - 2.f * delta) * t1;
    float out = ich + numer / denom;
    float om = 1.f - th;
    float dnum = delta * delta * (dk1 * th * th + 2.f * delta * t1 + dk * om * om);
    float ld = __logf(dnum) - 2.f * __logf(denom);

    *zo  = inside ? out : xval;
    *ldo = inside ? ld  : 0.f;
}

__device__ __forceinline__ void rqs23(float xval, const float* __restrict__ p,
                                      float* zo, float* ldo) {
    float cw[9], ch[9], der[9];
    rqs_tables(p, cw, ch, der);
    rqs_eval(xval, cw, ch, der, zo, ldo);
}

// ---------------------------------------------------------------------------
// merged prep: blocks [0,2048) pack x (fp16 single); [2048,2111) pack weights
// ---------------------------------------------------------------------------
__global__ void __launch_bounds__(256) nsf_prep(const float* __restrict__ x,
                                                const float* __restrict__ W1,
                                                const float* __restrict__ W2,
                                                const float* __restrict__ W3) {
    int tid = threadIdx.x;
    if (blockIdx.x < 2048) {
        int idx = blockIdx.x * 256 + tid;   // b*32 + p
        int c = (idx & 31) * 2;
        const float* xr = x + (size_t)(idx >> 5) * DIMS;
        g_xpk[idx] = pack_h2(xr[c], xr[c + 1]);
        return;
    }
    int l = blockIdx.x - 2048;
    uint4* base = (uint4*)(g_w + (size_t)l * 38912);
    for (int f = tid; f < 1024; f += 256) {
        int s = f >> 8, n = (f >> 5) & 7, lane = f & 31;
        int g = lane >> 2, tg = lane & 3;
        int row = 8 * n + g, c0 = 16 * s + 2 * tg;
        const float* w = W1 + (size_t)l * 4096 + row * 64;
        uint2 a = split2h(w[c0], w[c0 + 1]);
        uint2 b = split2h(w[c0 + 8], w[c0 + 9]);
        base[f] = make_uint4(a.x, b.x, a.y, b.y);
        w = W2 + (size_t)l * 4096 + row * 64;
        a = split2h(w[c0], w[c0 + 1]);
        b = split2h(w[c0 + 8], w[c0 + 9]);
        base[1024 + f] = make_uint4(a.x, b.x, a.y, b.y);
    }
    for (int f = tid; f < 384; f += 256) {
        int sn = f >> 5, lane = f & 31;
        int s = sn / 3, n = sn % 3;
        int g = lane >> 2, tg = lane & 3;
        int row = 8 * n + g, c0 = 16 * s + 2 * tg;
        uint4 rec = make_uint4(0, 0, 0, 0);
        if (row < OD) {
            const float* w = W3 + (size_t)l * OD * 64 + row * 64;
            uint2 a = split2h(w[c0], w[c0 + 1]);
            uint2 b = split2h(w[c0 + 8], w[c0 + 9]);
            rec = make_uint4(a.x, b.x, a.y, b.y);
        }
        base[2048 + f] = rec;
    }
}

// ---------------------------------------------------------------------------
// main fused kernel: 64-row CTA, 4 warps x one m16 tile each
// fp16 A (single plane) x fp16 W (hi+lo) -> 2 MMAs per (n,s)
// ---------------------------------------------------------------------------
template <int NS>
__device__ __forceinline__ void run_main(unsigned char* smp, int l,
                                         const float* __restrict__ x,
                                         const float* __restrict__ b1,
                                         const float* __restrict__ b2,
                                         const float* __restrict__ b3,
                                         float* __restrict__ z) {
    float* psm = (float*)(smp + PSM_OFF);
    float* bsm = (float*)(smp + BIAS_OFF);
    const uint4* wb1 = (const uint4*)(smp + WB1_OFF);
    const uint4* wb2 = (const uint4*)(smp + WB2_OFF);
    const uint4* wb3 = (const uint4*)(smp + WB3_OFF);

    const int tid = threadIdx.x;
    const int warp = tid >> 5, lane = tid & 31;
    const int g = lane >> 2, tg = lane & 3;
    const int m0 = blockIdx.x * 64;
    const int rb = 16 * warp + g;          // local row
    const uint32_t sbase = smem_u32(smp);

    // ---- prefetch W1, W2 via cp.async (2 commit groups) ----
    const uint4* wsrc = (const uint4*)(g_w + (size_t)l * 38912);
#pragma unroll
    for (int i = 0; i < NS * 2; i++)
        cp_async16(sbase + WB1_OFF + (i * 128 + tid) * 16, wsrc + i * 128 + tid);
    CP_COMMIT();
#pragma unroll
    for (int i = 0; i < 8; i++)
        cp_async16(sbase + WB2_OFF + (i * 128 + tid) * 16, wsrc + 1024 + i * 128 + tid);
    CP_COMMIT();

    // ---- biases ----
    if (tid < 64) { bsm[tid] = b1[l * 64 + tid]; bsm[64 + tid] = b2[l * 64 + tid]; }
    if (tid >= 96) bsm[128 + tid - 96] = (tid - 96 < OD) ? b3[l * OD + tid - 96] : 0.f;
    float xv = (tid < 64) ? x[(size_t)(m0 + tid) * DIMS + (l + 1)] : 0.f;

    // ---- layer-1 A fragments (fp16, single plane) from packed global x ----
    uint32_t A[4][4];
    uint32_t mA, mB;
    {
        int cA = 16 * (NS - 1) + 2 * tg, cB = cA + 8;
        mA = (cA + 1 <= l) ? 0xFFFFFFFFu : ((cA <= l) ? 0x0000FFFFu : 0u);
        mB = (cB + 1 <= l) ? 0xFFFFFFFFu : ((cB <= l) ? 0x0000FFFFu : 0u);
    }
    {
        int r0 = m0 + rb;
#pragma unroll
        for (int s = 0; s < NS; s++) {
            int p0 = 8 * s + tg;
            uint32_t v0 = g_xpk[(size_t)r0 * 32 + p0];
            uint32_t v1 = g_xpk[(size_t)(r0 + 8) * 32 + p0];
            uint32_t v2 = g_xpk[(size_t)r0 * 32 + p0 + 4];
            uint32_t v3 = g_xpk[(size_t)(r0 + 8) * 32 + p0 + 4];
            if (s == NS - 1) { v0 &= mA; v1 &= mA; v2 &= mB; v3 &= mB; }
            A[s][0] = v0; A[s][1] = v1; A[s][2] = v2; A[s][3] = v3;
        }
    }
    CP_WAIT(1);           // W1 landed
    __syncthreads();

    float acc[8][4];

    // ================= layer 1 (K = 16*NS), bias in acc init =================
#pragma unroll
    for (int n = 0; n < 8; n++) {
        int c0 = 8 * n + 2 * tg;
        acc[n][0] = bsm[c0]; acc[n][1] = bsm[c0 + 1];
        acc[n][2] = bsm[c0]; acc[n][3] = bsm[c0 + 1];
    }
#pragma unroll
    for (int n = 0; n < 8; n++)
#pragma unroll
        for (int s = 0; s < NS; s++) {
            uint4 w = wb1[(s * 8 + n) * 32 + lane];
            uint32_t bh[2] = { w.x, w.y }, bl[2] = { w.z, w.w };
            mma16816(acc[n], A[s], bh);
            mma16816(acc[n], A[s], bl);
        }
    // epilogue 1: tanh + fp16 pack -> next A frags (registers only)
#pragma unroll
    for (int n = 0; n < 8; n++) {
        float h0 = tanha(acc[n][0]);
        float h1 = tanha(acc[n][1]);
        float h2 = tanha(acc[n][2]);
        float h3 = tanha(acc[n][3]);
        int j = n >> 1, b = n & 1;
        A[j][2 * b]     = pack_h2(h0, h1);
        A[j][2 * b + 1] = pack_h2(h2, h3);
    }
    CP_WAIT(0);           // W2 landed (flew in during layer 1)
    __syncthreads();      // all wb1 reads complete -> W1 region reusable

    // deferred W3 prefetch into dead W1 region (lands during layer 2)
#pragma unroll
    for (int i = 0; i < 3; i++)
        cp_async16(sbase + WB3_OFF + (i * 128 + tid) * 16, wsrc + 2048 + i * 128 + tid);
    CP_COMMIT();

    // ================= layer 2 =================
#pragma unroll
    for (int n = 0; n < 8; n++) {
        int c0 = 8 * n + 2 * tg;
        acc[n][0] = bsm[64 + c0]; acc[n][1] = bsm[64 + c0 + 1];
        acc[n][2] = bsm[64 + c0]; acc[n][3] = bsm[64 + c0 + 1];
    }
#pragma unroll
    for (int n = 0; n < 8; n++)
#pragma unroll
        for (int s = 0; s < 4; s++) {
            uint4 w = wb2[(s * 8 + n) * 32 + lane];
            uint32_t bh[2] = { w.x, w.y }, bl[2] = { w.z, w.w };
            mma16816(acc[n], A[s], bh);
            mma16816(acc[n], A[s], bl);
        }
    // epilogue 2
#pragma unroll
    for (int n = 0; n < 8; n++) {
        float h0 = tanha(acc[n][0]);
        float h1 = tanha(acc[n][1]);
        float h2 = tanha(acc[n][2]);
        float h3 = tanha(acc[n][3]);
        int j = n >> 1, b = n & 1;
        A[j][2 * b]     = pack_h2(h0, h1);
        A[j][2 * b + 1] = pack_h2(h2, h3);
    }
    CP_WAIT(0);           // W3 landed
    __syncthreads();

    // ================= layer 3 (3 n-tiles), bias in acc init =================
#pragma unroll
    for (int n = 0; n < 3; n++) {
        int c0 = 8 * n + 2 * tg;
        acc[n][0] = bsm[128 + c0]; acc[n][1] = bsm[128 + c0 + 1];
        acc[n][2] = bsm[128 + c0]; acc[n][3] = bsm[128 + c0 + 1];
    }
#pragma unroll
    for (int n = 0; n < 3; n++)
#pragma unroll
        for (int s = 0; s < 4; s++) {
            uint4 w = wb3[(s * 3 + n) * 32 + lane];
            uint32_t bh[2] = { w.x, w.y }, bl[2] = { w.z, w.w };
            mma16816(acc[n], A[s], bh);
            mma16816(acc[n], A[s], bl);
        }
    __syncthreads();      // psm (@0) does not overlap W3 (@8192); orders wb3 reads
    // write spline params (stride 25)
#pragma unroll
    for (int n = 0; n < 3; n++) {
        int c0 = 8 * n + 2 * tg;
        if (c0 < OD)     psm[rb * 25 + c0]           = acc[n][0];
        if (c0 + 1 < OD) psm[rb * 25 + c0 + 1]       = acc[n][1];
        if (c0 < OD)     psm[(rb + 8) * 25 + c0]     = acc[n][2];
        if (c0 + 1 < OD) psm[(rb + 8) * 25 + c0 + 1] = acc[n][3];
    }
    __syncthreads();

    // ---- spline: one thread per batch row (64 rows) ----
    if (tid < 64) {
        float zo, ldo;
        rqs23(xv, &psm[tid * 25], &zo, &ldo);
        z[(size_t)(m0 + tid) * DIMS + (l + 1)] = zo;
        g_ld[(size_t)(m0 + tid) * DIMS + (l + 1)] = ldo;
    }
}

__global__ void __launch_bounds__(128, 6) nsf_main(
    const float* __restrict__ x,
    const float* __restrict__ b1, const float* __restrict__ b2,
    const float* __restrict__ b3, float* __restrict__ z) {
    extern __shared__ unsigned char smp[];
    int l = blockIdx.y;
    switch (l >> 4) {
        case 0:  run_main<1>(smp, l, x, b1, b2, b3, z); break;
        case 1:  run_main<2>(smp, l, x, b1, b2, b3, z); break;
        case 2:  run_main<3>(smp, l, x, b1, b2, b3, z); break;
        default: run_main<4>(smp, l, x, b1, b2, b3, z); break;
    }
}

// ---------------------------------------------------------------------------
// tail: dim-0 spline + logdet reduce, 4 threads per batch row
// ---------------------------------------------------------------------------
__global__ void __launch_bounds__(256) nsf_tail(const float* __restrict__ x,
                                                const float* __restrict__ ip,
                                                float* __restrict__ z,
                                                float* __restrict__ ldo) {
    __shared__ float cw[9], ch[9], der[9];
    if (threadIdx.x == 0) {
        float p[23];
#pragma unroll
        for (int i = 0; i < 23; i++) p[i] = ip[i];
        rqs_tables(p, cw, ch, der);
    }
    __syncthreads();
    int idx = blockIdx.x * 256 + threadIdx.x;
    int b = idx >> 2, q = idx & 3;

    const float4* r = (const float4*)(g_ld + (size_t)b * DIMS) + q * 4;
    float s = 0.f;
    if (q == 0) {
        float4 v = r[0];              // v.x is the unwritten dim-0 slot -> skip
        s += v.y + v.z + v.w;
#pragma unroll
        for (int i = 1; i < 4; i++) {
            float4 w = r[i];
            s += w.x + w.y + w.z + w.w;
        }
        float zo, ld0;
        rqs_eval(x[(size_t)b * DIMS], cw, ch, der, &zo, &ld0);
        z[(size_t)b * DIMS] = zo;
        s += ld0;
    } else {
#pragma unroll
        for (int i = 0; i < 4; i++) {
            float4 w = r[i];
            s += w.x + w.y + w.z + w.w;
        }
    }
    s += __shfl_xor_sync(0xFFFFFFFFu, s, 1);
    s += __shfl_xor_sync(0xFFFFFFFFu, s, 2);
    if (q == 0) ldo[b] = s;
}

// ---------------------------------------------------------------------------
extern "C" void kernel_launch(void* const* d_in, const int* in_sizes, int n_in,
                              void* d_out, int out_size) {
    const float* x  = (const float*)d_in[0];
    const float* ip = (const float*)d_in[1];
    const float* W1 = (const float*)d_in[2];
    const float* b1 = (const float*)d_in[3];
    const float* W2 = (const float*)d_in[4];
    const float* b2 = (const float*)d_in[5];
    const float* W3 = (const float*)d_in[6];
    const float* b3 = (const float*)d_in[7];

    float* z   = (float*)d_out;
    float* ldo = z + (size_t)BATCH * DIMS;

    cudaFuncSetAttribute(nsf_main, cudaFuncAttributeMaxDynamicSharedMemorySize, SMEM_BYTES);

    nsf_prep<<<2048 + LAYERS, 256>>>(x, W1, W2, W3);
    nsf_main<<<dim3(256, 63), 128, SMEM_BYTES>>>(x, b1, b2, b3, z);
    nsf_tail<<<BATCH * 4 / 256, 256>>>(x, ip, z, ldo);
}

// round 15
// speedup vs baseline: 4.5731x; 1.1166x over previous
#include <cuda_runtime.h>
#include <cuda_fp16.h>
#include <math.h>
#include <stdint.h>

#define BATCH 16384
#define DIMS  64
#define LAYERS 63
#define HID   64
#define OD    23
#define BTAIL 3.0f

// per-(batch,dim) logdet partials, [b][d] layout
__device__ float g_ld[BATCH * DIMS];
// fragment-ordered packed fp16 weights, per layer stride 38912 B:
//   W1 frags @0 (16384), W2 @16384 (16384), W3 @32768 (6144)
//   frag record = uint4 {hi0, hi1, lo0, lo1}  (half2-packed)
__device__ __align__(16) unsigned char g_w[(size_t)LAYERS * 38912];
// x packed as fp16 pairs: g_xpk[b*32+p] = half2(x[2p], x[2p+1])
__device__ __align__(16) uint32_t g_xpk[(size_t)BATCH * 32];

// dynamic smem layout (bytes)
// WB1 [0,16384): W1 frags; dead after layer 1 -> psm (128*25*4 = 12800) aliases @0
#define WB1_OFF  0
#define PSM_OFF  0
#define WB2_OFF  16384      // 16384
#define WB3_OFF  32768      // 6144
#define BIAS_OFF 38912      // b1[64] b2[64] b3pad[32] floats = 640
#define SMEM_BYTES 39552

// ---------------------------------------------------------------------------
// PTX helpers
// ---------------------------------------------------------------------------
__device__ __forceinline__ void mma16816(float* c, const uint32_t* a, const uint32_t* b) {
    asm volatile(
        "mma.sync.aligned.m16n8k16.row.col.f32.f16.f16.f32 "
        "{%0,%1,%2,%3}, {%4,%5,%6,%7}, {%8,%9}, {%0,%1,%2,%3};"
        : "+f"(c[0]), "+f"(c[1]), "+f"(c[2]), "+f"(c[3])
        : "r"(a[0]), "r"(a[1]), "r"(a[2]), "r"(a[3]), "r"(b[0]), "r"(b[1]));
}

__device__ __forceinline__ uint32_t smem_u32(const void* p) {
    uint32_t a;
    asm("{ .reg .u64 t; cvta.to.shared.u64 t, %1; cvt.u32.u64 %0, t; }" : "=r"(a) : "l"(p));
    return a;
}
__device__ __forceinline__ void cp_async16(uint32_t dst, const void* src) {
    asm volatile("cp.async.cg.shared.global [%0], [%1], 16;" :: "r"(dst), "l"(src));
}
#define CP_COMMIT() asm volatile("cp.async.commit_group;" ::: "memory")
#define CP_WAIT(n)  asm volatile("cp.async.wait_group %0;" :: "n"(n) : "memory")

// fp16 pair pack (single plane)
__device__ __forceinline__ uint32_t pack_h2(float f0, float f1) {
    __half2 h = __floats2half2_rn(f0, f1);
    return *(uint32_t*)&h;
}
// fp16 hi/lo split pair pack
__device__ __forceinline__ uint2 split2h(float f0, float f1) {
    __half h0 = __float2half_rn(f0), h1 = __float2half_rn(f1);
    __half l0 = __float2half_rn(f0 - __half2float(h0));
    __half l1 = __float2half_rn(f1 - __half2float(h1));
    __half2 hp = __halves2half2(h0, h1), lp = __halves2half2(l0, l1);
    uint2 o;
    o.x = *(uint32_t*)&hp;
    o.y = *(uint32_t*)&lp;
    return o;
}

__device__ __forceinline__ float tanha(float v) {
    float r;
    asm("tanh.approx.f32 %0, %1;" : "=f"(r) : "f"(v));
    return r;
}

// ---------------------------------------------------------------------------
// spline math
// ---------------------------------------------------------------------------
__device__ __forceinline__ float softplus_(float x) {
    return (x > 15.f) ? x : __logf(1.f + __expf(x));
}
__device__ __forceinline__ void softmax8(const float* in, float* out, float scale) {
    float m = in[0];
#pragma unroll
    for (int i = 1; i < 8; i++) m = fmaxf(m, in[i]);
    float e[8], s = 0.f;
#pragma unroll
    for (int i = 0; i < 8; i++) { e[i] = __expf(in[i] - m); s += e[i]; }
    float inv = scale / s;
#pragma unroll
    for (int i = 0; i < 8; i++) out[i] = e[i] * inv;
}

__device__ __forceinline__ void rqs_tables(const float* __restrict__ p,
                                           float* cw, float* ch, float* der) {
    float W[8], H[8], wi[8], he[8];
    softmax8(p,     W, 2.f * BTAIL);
    softmax8(p + 8, H, 2.f * BTAIL);
    softmax8(W, wi, 1.f);
    softmax8(H, he, 1.f);

    cw[0] = -BTAIL; ch[0] = -BTAIL;
    float aw = 0.f, ah = 0.f;
#pragma unroll
    for (int i = 0; i < 8; i++) {
        float wv = 1e-3f + (1.f - 8e-3f) * wi[i];
        float hv = 1e-3f + (1.f - 8e-3f) * he[i];
        aw += wv; ah += hv;
        cw[i + 1] = 2.f * BTAIL * aw - BTAIL;
        ch[i + 1] = 2.f * BTAIL * ah - BTAIL;
    }
    cw[8] = BTAIL; ch[8] = BTAIL;

    const float UDC = logf(expf(1.0f - 1e-3f) - 1.0f);
    float edge = 1e-3f + softplus_(UDC);
    der[0] = edge; der[8] = edge;
#pragma unroll
    for (int i = 0; i < 7; i++) der[i + 1] = 1e-3f + softplus_(softplus_(p[16 + i]));
}

__device__ __forceinline__ void rqs_eval(float xval, const float* __restrict__ cw,
                                         const float* __restrict__ ch,
                                         const float* __restrict__ der,
                                         float* zo, float* ldo) {
    bool inside = (xval >= -BTAIL) && (xval <= BTAIL);
    float x = fminf(fmaxf(xval, -BTAIL), BTAIL);

    int bin = 0;
#pragma unroll
    for (int i = 1; i < 8; i++) bin += (x >= cw[i]) ? 1 : 0;

    float icw = 0.f, iw = 1.f, ich = 0.f, ih = 1.f, dk = 1.f, dk1 = 1.f;
#pragma unroll
    for (int i = 0; i < 8; i++) {
        if (bin == i) {
            icw = cw[i];  iw = cw[i + 1] - cw[i];
            ich = ch[i];  ih = ch[i + 1] - ch[i];
            dk = der[i];  dk1 = der[i + 1];
        }
    }

    float delta = ih / iw;
    float th  = (x - icw) / iw;
    float t1  = th * (1.f - th);
    float numer = ih * (delta * th * th + dk * t1);
    float denom = delta + (dk + dk1 - 2.f * delta) * t1;
    float out = ich + numer / denom;
    float om = 1.f - th;
    float dnum = delta * delta * (dk1 * th * th + 2.f * delta * t1 + dk * om * om);
    float ld = __logf(dnum) - 2.f * __logf(denom);

    *zo  = inside ? out : xval;
    *ldo = inside ? ld  : 0.f;
}

__device__ __forceinline__ void rqs23(float xval, const float* __restrict__ p,
                                      float* zo, float* ldo) {
    float cw[9], ch[9], der[9];
    rqs_tables(p, cw, ch, der);
    rqs_eval(xval, cw, ch, der, zo, ldo);
}

// ---------------------------------------------------------------------------
// merged prep: blocks [0,1024) pack x (float4 = 2 pairs/thread);
//              blocks [1024, 1087) pack weights
// ---------------------------------------------------------------------------
__global__ void __launch_bounds__(256) nsf_prep(const float* __restrict__ x,
                                                const float* __restrict__ W1,
                                                const float* __restrict__ W2,
                                                const float* __restrict__ W3) {
    int tid = threadIdx.x;
    if (blockIdx.x < 1024) {
        int idx = blockIdx.x * 256 + tid;     // one float4 = pairs (2idx, 2idx+1)
        float4 v = ((const float4*)x)[idx];
        g_xpk[2 * idx]     = pack_h2(v.x, v.y);
        g_xpk[2 * idx + 1] = pack_h2(v.z, v.w);
        return;
    }
    int l = blockIdx.x - 1024;
    uint4* base = (uint4*)(g_w + (size_t)l * 38912);
    for (int f = tid; f < 1024; f += 256) {
        int s = f >> 8, n = (f >> 5) & 7, lane = f & 31;
        int g = lane >> 2, tg = lane & 3;
        int row = 8 * n + g, c0 = 16 * s + 2 * tg;
        const float* w = W1 + (size_t)l * 4096 + row * 64;
        uint2 a = split2h(w[c0], w[c0 + 1]);
        uint2 b = split2h(w[c0 + 8], w[c0 + 9]);
        base[f] = make_uint4(a.x, b.x, a.y, b.y);
        w = W2 + (size_t)l * 4096 + row * 64;
        a = split2h(w[c0], w[c0 + 1]);
        b = split2h(w[c0 + 8], w[c0 + 9]);
        base[1024 + f] = make_uint4(a.x, b.x, a.y, b.y);
    }
    for (int f = tid; f < 384; f += 256) {
        int sn = f >> 5, lane = f & 31;
        int s = sn / 3, n = sn % 3;
        int g = lane >> 2, tg = lane & 3;
        int row = 8 * n + g, c0 = 16 * s + 2 * tg;
        uint4 rec = make_uint4(0, 0, 0, 0);
        if (row < OD) {
            const float* w = W3 + (size_t)l * OD * 64 + row * 64;
            uint2 a = split2h(w[c0], w[c0 + 1]);
            uint2 b = split2h(w[c0 + 8], w[c0 + 9]);
            rec = make_uint4(a.x, b.x, a.y, b.y);
        }
        base[2048 + f] = rec;
    }
}

// ---------------------------------------------------------------------------
// main fused kernel: 128-row CTA, 4 warps x two m16 tiles each
// fp16 A (single plane) x fp16 W (hi+lo) -> each W-frag LDS feeds 4 MMAs
// ---------------------------------------------------------------------------
template <int NS>
__device__ __forceinline__ void run_main(unsigned char* smp, int l,
                                         const float* __restrict__ x,
                                         const float* __restrict__ b1,
                                         const float* __restrict__ b2,
                                         const float* __restrict__ b3,
                                         float* __restrict__ z) {
    float* psm = (float*)(smp + PSM_OFF);
    float* bsm = (float*)(smp + BIAS_OFF);
    const uint4* wb1 = (const uint4*)(smp + WB1_OFF);
    const uint4* wb2 = (const uint4*)(smp + WB2_OFF);
    const uint4* wb3 = (const uint4*)(smp + WB3_OFF);

    const int tid = threadIdx.x;
    const int warp = tid >> 5, lane = tid & 31;
    const int g = lane >> 2, tg = lane & 3;
    const int m0 = blockIdx.x * 128;
    const int mbase = warp * 32;
    const uint32_t sbase = smem_u32(smp);

    // ---- prefetch all three weight buffers via cp.async (3 commit groups) ----
    const uint4* wsrc = (const uint4*)(g_w + (size_t)l * 38912);
#pragma unroll
    for (int i = 0; i < NS * 2; i++)
        cp_async16(sbase + WB1_OFF + (i * 128 + tid) * 16, wsrc + i * 128 + tid);
    CP_COMMIT();
#pragma unroll
    for (int i = 0; i < 8; i++)
        cp_async16(sbase + WB2_OFF + (i * 128 + tid) * 16, wsrc + 1024 + i * 128 + tid);
    CP_COMMIT();
#pragma unroll
    for (int i = 0; i < 3; i++)
        cp_async16(sbase + WB3_OFF + (i * 128 + tid) * 16, wsrc + 2048 + i * 128 + tid);
    CP_COMMIT();

    // ---- biases ----
    if (tid < 64) { bsm[tid] = b1[l * 64 + tid]; bsm[64 + tid] = b2[l * 64 + tid]; }
    if (tid >= 96) bsm[128 + tid - 96] = (tid - 96 < OD) ? b3[l * OD + tid - 96] : 0.f;
    float xv = x[(size_t)(m0 + tid) * DIMS + (l + 1)];

    // ---- layer-1 A fragments (fp16 single plane) from packed global x ----
    uint32_t A[2][4][4];
    uint32_t mA, mB;
    {
        int cA = 16 * (NS - 1) + 2 * tg, cB = cA + 8;
        mA = (cA + 1 <= l) ? 0xFFFFFFFFu : ((cA <= l) ? 0x0000FFFFu : 0u);
        mB = (cB + 1 <= l) ? 0xFFFFFFFFu : ((cB <= l) ? 0x0000FFFFu : 0u);
    }
#pragma unroll
    for (int i = 0; i < 2; i++) {
        int r0 = m0 + mbase + 16 * i + g;
#pragma unroll
        for (int s = 0; s < NS; s++) {
            int p0 = 8 * s + tg;
            uint32_t v0 = g_xpk[(size_t)r0 * 32 + p0];
            uint32_t v1 = g_xpk[(size_t)(r0 + 8) * 32 + p0];
            uint32_t v2 = g_xpk[(size_t)r0 * 32 + p0 + 4];
            uint32_t v3 = g_xpk[(size_t)(r0 + 8) * 32 + p0 + 4];
            if (s == NS - 1) { v0 &= mA; v1 &= mA; v2 &= mB; v3 &= mB; }
            A[i][s][0] = v0; A[i][s][1] = v1; A[i][s][2] = v2; A[i][s][3] = v3;
        }
    }
    CP_WAIT(2);           // W1 landed
    __syncthreads();

    float acc[2][8][4];

    // ================= layer 1 (K = 16*NS), bias in acc init =================
#pragma unroll
    for (int i = 0; i < 2; i++)
#pragma unroll
        for (int n = 0; n < 8; n++) {
            int c0 = 8 * n + 2 * tg;
            acc[i][n][0] = bsm[c0]; acc[i][n][1] = bsm[c0 + 1];
            acc[i][n][2] = bsm[c0]; acc[i][n][3] = bsm[c0 + 1];
        }
#pragma unroll
    for (int n = 0; n < 8; n++)
#pragma unroll
        for (int s = 0; s < NS; s++) {
            uint4 w = wb1[(s * 8 + n) * 32 + lane];
            uint32_t bh[2] = { w.x, w.y }, bl[2] = { w.z, w.w };
            mma16816(acc[0][n], A[0][s], bh);
            mma16816(acc[1][n], A[1][s], bh);
            mma16816(acc[0][n], A[0][s], bl);
            mma16816(acc[1][n], A[1][s], bl);
        }
    // epilogue 1: tanh + fp16 pack -> next A frags (registers only)
#pragma unroll
    for (int i = 0; i < 2; i++)
#pragma unroll
        for (int n = 0; n < 8; n++) {
            float h0 = tanha(acc[i][n][0]);
            float h1 = tanha(acc[i][n][1]);
            float h2 = tanha(acc[i][n][2]);
            float h3 = tanha(acc[i][n][3]);
            int j = n >> 1, b = n & 1;
            A[i][j][2 * b]     = pack_h2(h0, h1);
            A[i][j][2 * b + 1] = pack_h2(h2, h3);
        }
    CP_WAIT(1);           // W2 landed
    __syncthreads();      // all wb1 reads complete

    // ================= layer 2 =================
#pragma unroll
    for (int i = 0; i < 2; i++)
#pragma unroll
        for (int n = 0; n < 8; n++) {
            int c0 = 8 * n + 2 * tg;
            acc[i][n][0] = bsm[64 + c0]; acc[i][n][1] = bsm[64 + c0 + 1];
            acc[i][n][2] = bsm[64 + c0]; acc[i][n][3] = bsm[64 + c0 + 1];
        }
#pragma unroll
    for (int n = 0; n < 8; n++)
#pragma unroll
        for (int s = 0; s < 4; s++) {
            uint4 w = wb2[(s * 8 + n) * 32 + lane];
            uint32_t bh[2] = { w.x, w.y }, bl[2] = { w.z, w.w };
            mma16816(acc[0][n], A[0][s], bh);
            mma16816(acc[1][n], A[1][s], bh);
            mma16816(acc[0][n], A[0][s], bl);
            mma16816(acc[1][n], A[1][s], bl);
        }
    // epilogue 2
#pragma unroll
    for (int i = 0; i < 2; i++)
#pragma unroll
        for (int n = 0; n < 8; n++) {
            float h0 = tanha(acc[i][n][0]);
            float h1 = tanha(acc[i][n][1]);
            float h2 = tanha(acc[i][n][2]);
            float h3 = tanha(acc[i][n][3]);
            int j = n >> 1, b = n & 1;
            A[i][j][2 * b]     = pack_h2(h0, h1);
            A[i][j][2 * b + 1] = pack_h2(h2, h3);
        }
    CP_WAIT(0);           // W3 landed
    __syncthreads();

    // ================= layer 3 (3 n-tiles), bias in acc init =================
#pragma unroll
    for (int i = 0; i < 2; i++)
#pragma unroll
        for (int n = 0; n < 3; n++) {
            int c0 = 8 * n + 2 * tg;
            acc[i][n][0] = bsm[128 + c0]; acc[i][n][1] = bsm[128 + c0 + 1];
            acc[i][n][2] = bsm[128 + c0]; acc[i][n][3] = bsm[128 + c0 + 1];
        }
#pragma unroll
    for (int n = 0; n < 3; n++)
#pragma unroll
        for (int s = 0; s < 4; s++) {
            uint4 w = wb3[(s * 3 + n) * 32 + lane];
            uint32_t bh[2] = { w.x, w.y }, bl[2] = { w.z, w.w };
            mma16816(acc[0][n], A[0][s], bh);
            mma16816(acc[1][n], A[1][s], bh);
            mma16816(acc[0][n], A[0][s], bl);
            mma16816(acc[1][n], A[1][s], bl);
        }
    __syncthreads();      // orders last wb1-region use (layer-1 long past) + wb3 reads
    // write spline params (stride 25) into psm (aliases dead W1 region)
#pragma unroll
    for (int i = 0; i < 2; i++)
#pragma unroll
        for (int n = 0; n < 3; n++) {
            int c0 = 8 * n + 2 * tg;
            int r0 = mbase + 16 * i + g;
            if (c0 < OD)     psm[r0 * 25 + c0]           = acc[i][n][0];
            if (c0 + 1 < OD) psm[r0 * 25 + c0 + 1]       = acc[i][n][1];
            if (c0 < OD)     psm[(r0 + 8) * 25 + c0]     = acc[i][n][2];
            if (c0 + 1 < OD) psm[(r0 + 8) * 25 + c0 + 1] = acc[i][n][3];
        }
    __syncthreads();

    // ---- spline: one thread per batch row (128 rows) ----
    float zo, ldo;
    rqs23(xv, &psm[tid * 25], &zo, &ldo);
    z[(size_t)(m0 + tid) * DIMS + (l + 1)] = zo;
    g_ld[(size_t)(m0 + tid) * DIMS + (l + 1)] = ldo;
}

__global__ void __launch_bounds__(128, 3) nsf_main(
    const float* __restrict__ x,
    const float* __restrict__ b1, const float* __restrict__ b2,
    const float* __restrict__ b3, float* __restrict__ z) {
    extern __shared__ unsigned char smp[];
    int l = blockIdx.y;
    switch (l >> 4) {
        case 0:  run_main<1>(smp, l, x, b1, b2, b3, z); break;
        case 1:  run_main<2>(smp, l, x, b1, b2, b3, z); break;
        case 2:  run_main<3>(smp, l, x, b1, b2, b3, z); break;
        default: run_main<4>(smp, l, x, b1, b2, b3, z); break;
    }
}

// ---------------------------------------------------------------------------
// tail: dim-0 spline + logdet reduce, 4 threads per batch row
// ---------------------------------------------------------------------------
__global__ void __launch_bounds__(256) nsf_tail(const float* __restrict__ x,
                                                const float* __restrict__ ip,
                                                float* __restrict__ z,
                                                float* __restrict__ ldo) {
    __shared__ float cw[9], ch[9], der[9];
    if (threadIdx.x == 0) {
        float p[23];
#pragma unroll
        for (int i = 0; i < 23; i++) p[i] = ip[i];
        rqs_tables(p, cw, ch, der);
    }
    __syncthreads();
    int idx = blockIdx.x * 256 + threadIdx.x;
    int b = idx >> 2, q = idx & 3;

    const float4* r = (const float4*)(g_ld + (size_t)b * DIMS) + q * 4;
    float s = 0.f;
    if (q == 0) {
        float4 v = r[0];              // v.x is the unwritten dim-0 slot -> skip
        s += v.y + v.z + v.w;
#pragma unroll
        for (int i = 1; i < 4; i++) {
            float4 w = r[i];
            s += w.x + w.y + w.z + w.w;
        }
        float zo, ld0;
        rqs_eval(x[(size_t)b * DIMS], cw, ch, der, &zo, &ld0);
        z[(size_t)b * DIMS] = zo;
        s += ld0;
    } else {
#pragma unroll
        for (int i = 0; i < 4; i++) {
            float4 w = r[i];
            s += w.x + w.y + w.z + w.w;
        }
    }
    s += __shfl_xor_sync(0xFFFFFFFFu, s, 1);
    s += __shfl_xor_sync(0xFFFFFFFFu, s, 2);
    if (q == 0) ldo[b] = s;
}

// ---------------------------------------------------------------------------
extern "C" void kernel_launch(void* const* d_in, const int* in_sizes, int n_in,
                              void* d_out, int out_size) {
    const float* x  = (const float*)d_in[0];
    const float* ip = (const float*)d_in[1];
    const float* W1 = (const float*)d_in[2];
    const float* b1 = (const float*)d_in[3];
    const float* W2 = (const float*)d_in[4];
    const float* b2 = (const float*)d_in[5];
    const float* W3 = (const float*)d_in[6];
    const float* b3 = (const float*)d_in[7];

    float* z   = (float*)d_out;
    float* ldo = z + (size_t)BATCH * DIMS;

    cudaFuncSetAttribute(nsf_main, cudaFuncAttributeMaxDynamicSharedMemorySize, SMEM_BYTES);

    nsf_prep<<<1024 + LAYERS, 256>>>(x, W1, W2, W3);
    nsf_main<<<dim3(128, 63), 128, SMEM_BYTES>>>(x, b1, b2, b3, z);
    nsf_tail<<<BATCH * 4 / 256, 256>>>(x, ip, z, ldo);
}

// round 17
// speedup vs baseline: 5.6859x; 1.2433x over previous
#include <cuda_runtime.h>
#include <cuda_fp16.h>
#include <math.h>
#include <stdint.h>

#define BATCH 16384
#define DIMS  64
#define LAYERS 63
#define HID   64
#define OD    23
#define BTAIL 3.0f

// per-(batch,dim) logdet partials, [b][d] layout
__device__ float g_ld[BATCH * DIMS];
// packed fp16 weights, per layer stride 22528 B:
//   W1 hi-only frags @0     (8192 B, uint2 {hi0,hi1})
//   W2 hi-only frags @8192  (8192 B, uint2)
//   W3 hi+lo  frags @16384  (6144 B, uint4 {hi0,hi1,lo0,lo1})
#define WSTRIDE 22528
__device__ __align__(16) unsigned char g_w[(size_t)LAYERS * WSTRIDE];
// x packed as fp16 pairs: g_xpk[b*32+p] = half2(x[2p], x[2p+1])
__device__ __align__(16) uint32_t g_xpk[(size_t)BATCH * 32];

// dynamic smem layout (bytes)
// psm (128*25*4 = 12800) aliases WB1+WB2, both dead after layer-3 MMAs
#define WB1_OFF  0          // 8192
#define PSM_OFF  0
#define WB2_OFF  8192       // 8192
#define WB3_OFF  16384      // 6144
#define BIAS_OFF 22528      // b1[64] b2[64] b3pad[32] floats = 640
#define SMEM_BYTES 23168

// ---------------------------------------------------------------------------
// PTX helpers
// ---------------------------------------------------------------------------
__device__ __forceinline__ void mma16816(float* c, const uint32_t* a, const uint32_t* b) {
    asm volatile(
        "mma.sync.aligned.m16n8k16.row.col.f32.f16.f16.f32 "
        "{%0,%1,%2,%3}, {%4,%5,%6,%7}, {%8,%9}, {%0,%1,%2,%3};"
        : "+f"(c[0]), "+f"(c[1]), "+f"(c[2]), "+f"(c[3])
        : "r"(a[0]), "r"(a[1]), "r"(a[2]), "r"(a[3]), "r"(b[0]), "r"(b[1]));
}

__device__ __forceinline__ uint32_t smem_u32(const void* p) {
    uint32_t a;
    asm("{ .reg .u64 t; cvta.to.shared.u64 t, %1; cvt.u32.u64 %0, t; }" : "=r"(a) : "l"(p));
    return a;
}
__device__ __forceinline__ void cp_async16(uint32_t dst, const void* src) {
    asm volatile("cp.async.cg.shared.global [%0], [%1], 16;" :: "r"(dst), "l"(src));
}
#define CP_COMMIT() asm volatile("cp.async.commit_group;" ::: "memory")
#define CP_WAIT(n)  asm volatile("cp.async.wait_group %0;" :: "n"(n) : "memory")

// fp16 pair pack (round-to-nearest)
__device__ __forceinline__ uint32_t pack_h2(float f0, float f1) {
    __half2 h = __floats2half2_rn(f0, f1);
    return *(uint32_t*)&h;
}
// fp16 hi/lo split pair pack (layer-3 weights only)
__device__ __forceinline__ uint2 split2h(float f0, float f1) {
    __half h0 = __float2half_rn(f0), h1 = __float2half_rn(f1);
    __half l0 = __float2half_rn(f0 - __half2float(h0));
    __half l1 = __float2half_rn(f1 - __half2float(h1));
    __half2 hp = __halves2half2(h0, h1), lp = __halves2half2(l0, l1);
    uint2 o;
    o.x = *(uint32_t*)&hp;
    o.y = *(uint32_t*)&lp;
    return o;
}

__device__ __forceinline__ float tanha(float v) {
    float r;
    asm("tanh.approx.f32 %0, %1;" : "=f"(r) : "f"(v));
    return r;
}

// ---------------------------------------------------------------------------
// spline math
// ---------------------------------------------------------------------------
__device__ __forceinline__ float softplus_(float x) {
    return (x > 15.f) ? x : __logf(1.f + __expf(x));
}
__device__ __forceinline__ void softmax8(const float* in, float* out, float scale) {
    float m = in[0];
#pragma unroll
    for (int i = 1; i < 8; i++) m = fmaxf(m, in[i]);
    float e[8], s = 0.f;
#pragma unroll
    for (int i = 0; i < 8; i++) { e[i] = __expf(in[i] - m); s += e[i]; }
    float inv = scale / s;
#pragma unroll
    for (int i = 0; i < 8; i++) out[i] = e[i] * inv;
}

__device__ __forceinline__ void rqs_tables(const float* __restrict__ p,
                                           float* cw, float* ch, float* der) {
    float W[8], H[8], wi[8], he[8];
    softmax8(p,     W, 2.f * BTAIL);
    softmax8(p + 8, H, 2.f * BTAIL);
    softmax8(W, wi, 1.f);
    softmax8(H, he, 1.f);

    cw[0] = -BTAIL; ch[0] = -BTAIL;
    float aw = 0.f, ah = 0.f;
#pragma unroll
    for (int i = 0; i < 8; i++) {
        float wv = 1e-3f + (1.f - 8e-3f) * wi[i];
        float hv = 1e-3f + (1.f - 8e-3f) * he[i];
        aw += wv; ah += hv;
        cw[i + 1] = 2.f * BTAIL * aw - BTAIL;
        ch[i + 1] = 2.f * BTAIL * ah - BTAIL;
    }
    cw[8] = BTAIL; ch[8] = BTAIL;

    const float UDC = logf(expf(1.0f - 1e-3f) - 1.0f);
    float edge = 1e-3f + softplus_(UDC);
    der[0] = edge; der[8] = edge;
#pragma unroll
    for (int i = 0; i < 7; i++) der[i + 1] = 1e-3f + softplus_(softplus_(p[16 + i]));
}

__device__ __forceinline__ void rqs_eval(float xval, const float* __restrict__ cw,
                                         const float* __restrict__ ch,
                                         const float* __restrict__ der,
                                         float* zo, float* ldo) {
    bool inside = (xval >= -BTAIL) && (xval <= BTAIL);
    float x = fminf(fmaxf(xval, -BTAIL), BTAIL);

    int bin = 0;
#pragma unroll
    for (int i = 1; i < 8; i++) bin += (x >= cw[i]) ? 1 : 0;

    float icw = 0.f, iw = 1.f, ich = 0.f, ih = 1.f, dk = 1.f, dk1 = 1.f;
#pragma unroll
    for (int i = 0; i < 8; i++) {
        if (bin == i) {
            icw = cw[i];  iw = cw[i + 1] - cw[i];
            ich = ch[i];  ih = ch[i + 1] - ch[i];
            dk = der[i];  dk1 = der[i + 1];
        }
    }

    float delta = ih / iw;
    float th  = (x - icw) / iw;
    float t1  = th * (1.f - th);
    float numer = ih * (delta * th * th + dk * t1);
    float denom = delta + (dk + dk1 - 2.f * delta) * t1;
    float out = ich + numer / denom;
    float om = 1.f - th;
    float dnum = delta * delta * (dk1 * th * th + 2.f * delta * t1 + dk * om * om);
    float ld = __logf(dnum) - 2.f * __logf(denom);

    *zo  = inside ? out : xval;
    *ldo = inside ? ld  : 0.f;
}

__device__ __forceinline__ void rqs23(float xval, const float* __restrict__ p,
                                      float* zo, float* ldo) {
    float cw[9], ch[9], der[9];
    rqs_tables(p, cw, ch, der);
    rqs_eval(xval, cw, ch, der, zo, ldo);
}

// ---------------------------------------------------------------------------
// merged prep: blocks [0,1024) pack x (float4 = 2 pairs/thread);
//              blocks [1024, 1087) pack weights
// ---------------------------------------------------------------------------
__global__ void __launch_bounds__(256) nsf_prep(const float* __restrict__ x,
                                                const float* __restrict__ W1,
                                                const float* __restrict__ W2,
                                                const float* __restrict__ W3) {
    int tid = threadIdx.x;
    if (blockIdx.x < 1024) {
        int idx = blockIdx.x * 256 + tid;     // one float4 = pairs (2idx, 2idx+1)
        float4 v = ((const float4*)x)[idx];
        g_xpk[2 * idx]     = pack_h2(v.x, v.y);
        g_xpk[2 * idx + 1] = pack_h2(v.z, v.w);
        return;
    }
    int l = blockIdx.x - 1024;
    uint2* w12 = (uint2*)(g_w + (size_t)l * WSTRIDE);
    for (int f = tid; f < 1024; f += 256) {
        int s = f >> 8, n = (f >> 5) & 7, lane = f & 31;
        int g = lane >> 2, tg = lane & 3;
        int row = 8 * n + g, c0 = 16 * s + 2 * tg;
        const float* w = W1 + (size_t)l * 4096 + row * 64;
        w12[f] = make_uint2(pack_h2(w[c0], w[c0 + 1]), pack_h2(w[c0 + 8], w[c0 + 9]));
        w = W2 + (size_t)l * 4096 + row * 64;
        w12[1024 + f] = make_uint2(pack_h2(w[c0], w[c0 + 1]), pack_h2(w[c0 + 8], w[c0 + 9]));
    }
    uint4* b3r = (uint4*)(g_w + (size_t)l * WSTRIDE + 16384);
    for (int f = tid; f < 384; f += 256) {
        int sn = f >> 5, lane = f & 31;
        int s = sn / 3, n = sn % 3;
        int g = lane >> 2, tg = lane & 3;
        int row = 8 * n + g, c0 = 16 * s + 2 * tg;
        uint4 rec = make_uint4(0, 0, 0, 0);
        if (row < OD) {
            const float* w = W3 + (size_t)l * OD * 64 + row * 64;
            uint2 a = split2h(w[c0], w[c0 + 1]);
            uint2 b = split2h(w[c0 + 8], w[c0 + 9]);
            rec = make_uint4(a.x, b.x, a.y, b.y);
        }
        b3r[f] = rec;
    }
}

// ---------------------------------------------------------------------------
// main fused kernel: 128-row CTA, 4 warps x two m16 tiles each
// layers 1-2: fp16 A x fp16 W (hi only) -> 1 MMA per (n,s), LDS.64 weights
// layer  3  : fp16 A x fp16 W (hi+lo)  -> 2 MMAs per (n,s)
// ---------------------------------------------------------------------------
template <int NS>
__device__ __forceinline__ void run_main(unsigned char* smp, int l,
                                         const float* __restrict__ x,
                                         const float* __restrict__ b1,
                                         const float* __restrict__ b2,
                                         const float* __restrict__ b3,
                                         float* __restrict__ z) {
    float* psm = (float*)(smp + PSM_OFF);
    float* bsm = (float*)(smp + BIAS_OFF);
    const uint2* wb1 = (const uint2*)(smp + WB1_OFF);
    const uint2* wb2 = (const uint2*)(smp + WB2_OFF);
    const uint4* wb3 = (const uint4*)(smp + WB3_OFF);

    const int tid = threadIdx.x;
    const int warp = tid >> 5, lane = tid & 31;
    const int g = lane >> 2, tg = lane & 3;
    const int m0 = blockIdx.x * 128;
    const int mbase = warp * 32;
    const uint32_t sbase = smem_u32(smp);

    // ---- prefetch all three weight buffers via cp.async (3 commit groups) ----
    const uint4* wsrc = (const uint4*)(g_w + (size_t)l * WSTRIDE);
#pragma unroll
    for (int i = 0; i < NS; i++)        // W1 live chunks: NS*2048 B
        cp_async16(sbase + WB1_OFF + (i * 128 + tid) * 16, wsrc + i * 128 + tid);
    CP_COMMIT();
#pragma unroll
    for (int i = 0; i < 4; i++)         // W2: 8192 B
        cp_async16(sbase + WB2_OFF + (i * 128 + tid) * 16, wsrc + 512 + i * 128 + tid);
    CP_COMMIT();
#pragma unroll
    for (int i = 0; i < 3; i++)         // W3: 6144 B
        cp_async16(sbase + WB3_OFF + (i * 128 + tid) * 16, wsrc + 1024 + i * 128 + tid);
    CP_COMMIT();

    // ---- biases ----
    if (tid < 64) { bsm[tid] = b1[l * 64 + tid]; bsm[64 + tid] = b2[l * 64 + tid]; }
    if (tid >= 96) bsm[128 + tid - 96] = (tid - 96 < OD) ? b3[l * OD + tid - 96] : 0.f;
    float xv = x[(size_t)(m0 + tid) * DIMS + (l + 1)];

    // ---- layer-1 A fragments (fp16 single plane) from packed global x ----
    uint32_t A[2][4][4];
    uint32_t mA, mB;
    {
        int cA = 16 * (NS - 1) + 2 * tg, cB = cA + 8;
        mA = (cA + 1 <= l) ? 0xFFFFFFFFu : ((cA <= l) ? 0x0000FFFFu : 0u);
        mB = (cB + 1 <= l) ? 0xFFFFFFFFu : ((cB <= l) ? 0x0000FFFFu : 0u);
    }
#pragma unroll
    for (int i = 0; i < 2; i++) {
        int r0 = m0 + mbase + 16 * i + g;
#pragma unroll
        for (int s = 0; s < NS; s++) {
            int p0 = 8 * s + tg;
            uint32_t v0 = g_xpk[(size_t)r0 * 32 + p0];
            uint32_t v1 = g_xpk[(size_t)(r0 + 8) * 32 + p0];
            uint32_t v2 = g_xpk[(size_t)r0 * 32 + p0 + 4];
            uint32_t v3 = g_xpk[(size_t)(r0 + 8) * 32 + p0 + 4];
            if (s == NS - 1) { v0 &= mA; v1 &= mA; v2 &= mB; v3 &= mB; }
            A[i][s][0] = v0; A[i][s][1] = v1; A[i][s][2] = v2; A[i][s][3] = v3;
        }
    }
    CP_WAIT(2);           // W1 landed
    __syncthreads();

    float acc[2][8][4];

    // ================= layer 1 (K = 16*NS), bias in acc init =================
#pragma unroll
    for (int i = 0; i < 2; i++)
#pragma unroll
        for (int n = 0; n < 8; n++) {
            int c0 = 8 * n + 2 * tg;
            acc[i][n][0] = bsm[c0]; acc[i][n][1] = bsm[c0 + 1];
            acc[i][n][2] = bsm[c0]; acc[i][n][3] = bsm[c0 + 1];
        }
#pragma unroll
    for (int n = 0; n < 8; n++)
#pragma unroll
        for (int s = 0; s < NS; s++) {
            uint2 w = wb1[(s * 8 + n) * 32 + lane];
            uint32_t bh[2] = { w.x, w.y };
            mma16816(acc[0][n], A[0][s], bh);
            mma16816(acc[1][n], A[1][s], bh);
        }
    // epilogue 1: tanh + fp16 pack -> next A frags (registers only)
#pragma unroll
    for (int i = 0; i < 2; i++)
#pragma unroll
        for (int n = 0; n < 8; n++) {
            float h0 = tanha(acc[i][n][0]);
            float h1 = tanha(acc[i][n][1]);
            float h2 = tanha(acc[i][n][2]);
            float h3 = tanha(acc[i][n][3]);
            int j = n >> 1, b = n & 1;
            A[i][j][2 * b]     = pack_h2(h0, h1);
            A[i][j][2 * b + 1] = pack_h2(h2, h3);
        }
    CP_WAIT(1);           // W2 landed
    __syncthreads();      // all wb1 reads complete

    // ================= layer 2 =================
#pragma unroll
    for (int i = 0; i < 2; i++)
#pragma unroll
        for (int n = 0; n < 8; n++) {
            int c0 = 8 * n + 2 * tg;
            acc[i][n][0] = bsm[64 + c0]; acc[i][n][1] = bsm[64 + c0 + 1];
            acc[i][n][2] = bsm[64 + c0]; acc[i][n][3] = bsm[64 + c0 + 1];
        }
#pragma unroll
    for (int n = 0; n < 8; n++)
#pragma unroll
        for (int s = 0; s < 4; s++) {
            uint2 w = wb2[(s * 8 + n) * 32 + lane];
            uint32_t bh[2] = { w.x, w.y };
            mma16816(acc[0][n], A[0][s], bh);
            mma16816(acc[1][n], A[1][s], bh);
        }
    // epilogue 2
#pragma unroll
    for (int i = 0; i < 2; i++)
#pragma unroll
        for (int n = 0; n < 8; n++) {
            float h0 = tanha(acc[i][n][0]);
            float h1 = tanha(acc[i][n][1]);
            float h2 = tanha(acc[i][n][2]);
            float h3 = tanha(acc[i][n][3]);
            int j = n >> 1, b = n & 1;
            A[i][j][2 * b]     = pack_h2(h0, h1);
            A[i][j][2 * b + 1] = pack_h2(h2, h3);
        }
    CP_WAIT(0);           // W3 landed
    __syncthreads();

    // ================= layer 3 (3 n-tiles, hi+lo), bias in acc init =================
#pragma unroll
    for (int i = 0; i < 2; i++)
#pragma unroll
        for (int n = 0; n < 3; n++) {
            int c0 = 8 * n + 2 * tg;
            acc[i][n][0] = bsm[128 + c0]; acc[i][n][1] = bsm[128 + c0 + 1];
            acc[i][n][2] = bsm[128 + c0]; acc[i][n][3] = bsm[128 + c0 + 1];
        }
#pragma unroll
    for (int n = 0; n < 3; n++)
#pragma unroll
        for (int s = 0; s < 4; s++) {
            uint4 w = wb3[(s * 3 + n) * 32 + lane];
            uint32_t bh[2] = { w.x, w.y }, bl[2] = { w.z, w.w };
            mma16816(acc[0][n], A[0][s], bh);
            mma16816(acc[1][n], A[1][s], bh);
            mma16816(acc[0][n], A[0][s], bl);
            mma16816(acc[1][n], A[1][s], bl);
        }
    __syncthreads();      // orders all wb1/wb2 region reads before psm overwrite
    // write spline params (stride 25) into psm (aliases dead W1+W2 regions)
#pragma unroll
    for (int i = 0; i < 2; i++)
#pragma unroll
        for (int n = 0; n < 3; n++) {
            int c0 = 8 * n + 2 * tg;
            int r0 = mbase + 16 * i + g;
            if (c0 < OD)     psm[r0 * 25 + c0]           = acc[i][n][0];
            if (c0 + 1 < OD) psm[r0 * 25 + c0 + 1]       = acc[i][n][1];
            if (c0 < OD)     psm[(r0 + 8) * 25 + c0]     = acc[i][n][2];
            if (c0 + 1 < OD) psm[(r0 + 8) * 25 + c0 + 1] = acc[i][n][3];
        }
    __syncthreads();

    // ---- spline: one thread per batch row (128 rows) ----
    float zo, ldo;
    rqs23(xv, &psm[tid * 25], &zo, &ldo);
    z[(size_t)(m0 + tid) * DIMS + (l + 1)] = zo;
    g_ld[(size_t)(m0 + tid) * DIMS + (l + 1)] = ldo;
}

__global__ void __launch_bounds__(128, 4) nsf_main(
    const float* __restrict__ x,
    const float* __restrict__ b1, const float* __restrict__ b2,
    const float* __restrict__ b3, float* __restrict__ z) {
    extern __shared__ unsigned char smp[];
    int l = blockIdx.y;
    switch (l >> 4) {
        case 0:  run_main<1>(smp, l, x, b1, b2, b3, z); break;
        case 1:  run_main<2>(smp, l, x, b1, b2, b3, z); break;
        case 2:  run_main<3>(smp, l, x, b1, b2, b3, z); break;
        default: run_main<4>(smp, l, x, b1, b2, b3, z); break;
    }
}

// ---------------------------------------------------------------------------
// tail: dim-0 spline + logdet reduce, 4 threads per batch row
// ---------------------------------------------------------------------------
__global__ void __launch_bounds__(256) nsf_tail(const float* __restrict__ x,
                                                const float* __restrict__ ip,
                                                float* __restrict__ z,
                                                float* __restrict__ ldo) {
    __shared__ float cw[9], ch[9], der[9];
    if (threadIdx.x == 0) {
        float p[23];
#pragma unroll
        for (int i = 0; i < 23; i++) p[i] = ip[i];
        rqs_tables(p, cw, ch, der);
    }
    __syncthreads();
    int idx = blockIdx.x * 256 + threadIdx.x;
    int b = idx >> 2, q = idx & 3;

    const float4* r = (const float4*)(g_ld + (size_t)b * DIMS) + q * 4;
    float s = 0.f;
    if (q == 0) {
        float4 v = r[0];              // v.x is the unwritten dim-0 slot -> skip
        s += v.y + v.z + v.w;
#pragma unroll
        for (int i = 1; i < 4; i++) {
            float4 w = r[i];
            s += w.x + w.y + w.z + w.w;
        }
        float zo, ld0;
        rqs_eval(x[(size_t)b * DIMS], cw, ch, der, &zo, &ld0);
        z[(size_t)b * DIMS] = zo;
        s += ld0;
    } else {
#pragma unroll
        for (int i = 0; i < 4; i++) {
            float4 w = r[i];
            s += w.x + w.y + w.z + w.w;
        }
    }
    s += __shfl_xor_sync(0xFFFFFFFFu, s, 1);
    s += __shfl_xor_sync(0xFFFFFFFFu, s, 2);
    if (q == 0) ldo[b] = s;
}

// ---------------------------------------------------------------------------
extern "C" void kernel_launch(void* const* d_in, const int* in_sizes, int n_in,
                              void* d_out, int out_size) {
    const float* x  = (const float*)d_in[0];
    const float* ip = (const float*)d_in[1];
    const float* W1 = (const float*)d_in[2];
    const float* b1 = (const float*)d_in[3];
    const float* W2 = (const float*)d_in[4];
    const float* b2 = (const float*)d_in[5];
    const float* W3 = (const float*)d_in[6];
    const float* b3 = (const float*)d_in[7];

    float* z   = (float*)d_out;
    float* ldo = z + (size_t)BATCH * DIMS;

    cudaFuncSetAttribute(nsf_main, cudaFuncAttributeMaxDynamicSharedMemorySize, SMEM_BYTES);

    nsf_prep<<<1024 + LAYERS, 256>>>(x, W1, W2, W3);
    nsf_main<<<dim3(128, 63), 128, SMEM_BYTES>>>(x, b1, b2, b3, z);
    nsf_tail<<<BATCH * 4 / 256, 256>>>(x, ip, z, ldo);
}